// round 12
// baseline (speedup 1.0000x reference)
#include <cuda_runtime.h>
#include <cuda_fp16.h>
#include <cstdint>

#define S_LEN 4096
#define BATCH 2
#define EMB   768
#define NH    12
#define HDIM  64
#define WIN   256
#define GLB   32
#define QT2   64
#define NSEG  16
#define SEGLEN (S_LEN / NSEG)

typedef unsigned long long u64;

// ---------- packed f32x2 helpers ----------
__device__ __forceinline__ u64 pk2(float x, float y) {
    u64 r; asm("mov.b64 %0, {%1,%2};" : "=l"(r) : "f"(x), "f"(y)); return r;
}
__device__ __forceinline__ u64 dup2(float x) { return pk2(x, x); }
__device__ __forceinline__ float2 up2(u64 v) {
    float2 f; asm("mov.b64 {%0,%1}, %2;" : "=f"(f.x), "=f"(f.y) : "l"(v)); return f;
}
__device__ __forceinline__ u64 ffma2(u64 a, u64 b, u64 c) {
    u64 d; asm("fma.rn.f32x2 %0, %1, %2, %3;" : "=l"(d) : "l"(a), "l"(b), "l"(c)); return d;
}
__device__ __forceinline__ u64 fadd2(u64 a, u64 b) {
    u64 d; asm("add.rn.f32x2 %0, %1, %2;" : "=l"(d) : "l"(a), "l"(b)); return d;
}
__device__ __forceinline__ u64 fmul2(u64 a, u64 b) {
    u64 d; asm("mul.rn.f32x2 %0, %1, %2;" : "=l"(d) : "l"(a), "l"(b)); return d;
}

__device__ __forceinline__ uint32_t smem_to_u32(const void* p) {
    uint32_t a;
    asm("{ .reg .u64 t; cvta.to.shared.u64 t, %1; cvt.u32.u64 %0, t; }" : "=r"(a) : "l"(p));
    return a;
}
#define SW128(o) ((o) ^ (((o) >> 3) & 0x70))
#define SW64(o)  ((o) ^ (((o) >> 3) & 0x30))

#define CP16(dst, src) \
    asm volatile("cp.async.cg.shared.global [%0], [%1], 16;" \
                 :: "r"(dst), "l"(src) : "memory")
#define CPZ16(dst, src, pred) do { \
    int _sz = (pred) ? 16 : 0; \
    asm volatile("cp.async.cg.shared.global [%0], [%1], 16, %2;" \
                 :: "r"(dst), "l"(src), "r"(_sz) : "memory"); } while (0)
#define CPZ4(dst, src, pred) do { \
    int _sz = (pred) ? 4 : 0; \
    asm volatile("cp.async.ca.shared.global [%0], [%1], 4, %2;" \
                 :: "r"(dst), "l"(src), "r"(_sz) : "memory"); } while (0)
#define CP_COMMIT() asm volatile("cp.async.commit_group;" ::: "memory")
#define CP_WAIT1()  asm volatile("cp.async.wait_group 1;" ::: "memory")

__device__ __forceinline__ void ldsm_x4(uint32_t* r, uint32_t addr) {
    asm volatile("ldmatrix.sync.aligned.m8n8.x4.shared.b16 {%0,%1,%2,%3}, [%4];"
                 : "=r"(r[0]), "=r"(r[1]), "=r"(r[2]), "=r"(r[3]) : "r"(addr));
}
__device__ __forceinline__ void ldsm_x4t(uint32_t* r, uint32_t addr) {
    asm volatile("ldmatrix.sync.aligned.m8n8.x4.trans.shared.b16 {%0,%1,%2,%3}, [%4];"
                 : "=r"(r[0]), "=r"(r[1]), "=r"(r[2]), "=r"(r[3]) : "r"(addr));
}
// fp16 mma, fp32 accum
__device__ __forceinline__ void mma16816(float* c, const uint32_t* a,
                                         uint32_t b0, uint32_t b1) {
    asm volatile(
        "mma.sync.aligned.m16n8k16.row.col.f32.f16.f16.f32 "
        "{%0,%1,%2,%3}, {%4,%5,%6,%7}, {%8,%9}, {%0,%1,%2,%3};"
        : "+f"(c[0]), "+f"(c[1]), "+f"(c[2]), "+f"(c[3])
        : "r"(a[0]), "r"(a[1]), "r"(a[2]), "r"(a[3]), "r"(b0), "r"(b1));
}

// -------- scratch --------
__device__ float g_kg[BATCH * S_LEN * EMB];
__device__ float g_vg[BATCH * S_LEN * EMB];
__device__ float g_qg[BATCH * GLB * EMB];
__device__ __half g_xh[BATCH * S_LEN * EMB];
__device__ __half g_xl[BATCH * S_LEN * EMB];
__device__ __half g_wt[6 * EMB * EMB];
__device__ __half g_q1[BATCH * S_LEN * EMB];
__device__ __half g_q2[BATCH * S_LEN * EMB];
__device__ __half g_k1[BATCH * S_LEN * EMB];
__device__ __half g_v1[BATCH * S_LEN * EMB];
__device__ float g_po[NSEG * BATCH * NH * GLB * HDIM];
__device__ float g_pm[NSEG * BATCH * NH * GLB];
__device__ float g_pl[NSEG * BATCH * NH * GLB];

// ---------------- prep: x -> fp16 hi/lo ----------------
__global__ __launch_bounds__(256) void convx_kernel(
    const float* __restrict__ x, __half* __restrict__ xh,
    __half* __restrict__ xl)
{
    int i = (blockIdx.x * 256 + threadIdx.x) * 4;
    float4 a = *(const float4*)(x + i);
    __half h[4], l[4];
    float av[4] = {a.x, a.y, a.z, a.w};
#pragma unroll
    for (int j = 0; j < 4; j++) {
        h[j] = __float2half(av[j]);
        l[j] = __float2half(av[j] - __half2float(h[j]));
    }
    *(uint2*)(xh + i) = *(const uint2*)h;
    *(uint2*)(xl + i) = *(const uint2*)l;
}

// ---------------- prep: W -> W^T single fp16 (6 weights) ----------------
__global__ __launch_bounds__(256) void convw_kernel(
    const float* __restrict__ w0, const float* __restrict__ w1,
    const float* __restrict__ w2, const float* __restrict__ w3,
    const float* __restrict__ w4, const float* __restrict__ w5,
    __half* __restrict__ wt)
{
    __shared__ float tile[32][33];
    int z = blockIdx.z;
    const float* W = (z == 0) ? w0 : (z == 1) ? w1 : (z == 2) ? w2 :
                     (z == 3) ? w3 : (z == 4) ? w4 : w5;
    int kb = blockIdx.y * 32, nb = blockIdx.x * 32;
    int tx = threadIdx.x & 31, ty = threadIdx.x >> 5;
    for (int i = ty; i < 32; i += 8)
        tile[i][tx] = W[(size_t)(kb + i) * EMB + nb + tx];
    __syncthreads();
    for (int j = ty; j < 32; j += 8) {
        size_t o = (size_t)z * EMB * EMB + (size_t)(nb + j) * EMB + kb + tx;
        wt[o] = __float2half(tile[tx][j]);
    }
}

// ------- mma.sync GEMM: 128x128 CTA, 256 thr, warp 32x64, k-chunk 32 -------
// 3-stage cp.async pipeline, SW64 swizzle.
#define GST  24576
#define GSM3 (3 * GST)     // 72 KB -> 2 CTA/SM

__device__ __forceinline__ void gemm_core(
    int z, int m0, int n0,
    const __half* __restrict__ xh, const __half* __restrict__ xl,
    const __half* __restrict__ wt,
    const float* __restrict__ bq, const float* __restrict__ bk,
    const float* __restrict__ bv, const float* __restrict__ bkg,
    const float* __restrict__ bvg, const float* __restrict__ bqg,
    __half* q1, __half* q2, __half* k1, __half* v1,
    float* kg, float* vg, float* qg, char* dsm)
{
    int t = threadIdx.x, wid = t >> 5, lane = t & 31;
    int wm = wid & 3, wn = wid >> 2;

    const float* bias;
    switch (z) {
        case 0:  bias = bq;  break;
        case 1:  bias = bk;  break;
        case 2:  bias = bv;  break;
        case 3:  bias = bkg; break;
        case 4:  bias = bvg; break;
        default: bias = bqg; break;
    }
    float scale = (z == 0 || z == 5) ? 0.125f : 1.0f;
    const __half* Bw = wt + (size_t)z * EMB * EMB;

    uint32_t sb = smem_to_u32(dsm);

    float acc[2][8][4];
#pragma unroll
    for (int mi = 0; mi < 2; mi++)
#pragma unroll
        for (int ni = 0; ni < 8; ni++)
#pragma unroll
            for (int c = 0; c < 4; c++) acc[mi][ni][c] = 0.f;

    uint32_t a_off[2], b_off[4];
#pragma unroll
    for (int mi = 0; mi < 2; mi++) {
        int row = wm * 32 + mi * 16 + (lane & 15);
        a_off[mi] = (uint32_t)(row * 64) + ((lane >> 4) << 4);
    }
#pragma unroll
    for (int bi = 0; bi < 4; bi++) {
        int row = wn * 64 + bi * 16 + (lane & 15);
        b_off[bi] = (uint32_t)(row * 64) + ((lane >> 4) << 4);
    }

#define LOAD_STAGE(chunk, s) do {                                            \
        int k0 = (chunk) * 32;                                               \
        uint32_t base = sb + (s) * GST;                                      \
        _Pragma("unroll")                                                    \
        for (int i = 0; i < 2; i++) {                                        \
            int idx = t + i * 256;                                           \
            int r = idx >> 2, u = idx & 3;                                   \
            uint32_t sw = SW64((uint32_t)(r * 64 + u * 16));                 \
            size_t arow;                                                     \
            if (z == 5) { int q2r = r & 63;                                  \
                arow = (size_t)((q2r >> 5) * S_LEN + (q2r & 31)); }          \
            else arow = (size_t)(m0 + r);                                    \
            CP16(base + sw,        xh + arow * EMB + k0 + u * 8);            \
            CP16(base + 8192 + sw, xl + arow * EMB + k0 + u * 8);            \
            CP16(base + 16384 + sw, Bw + (size_t)(n0 + r) * EMB + k0 + u * 8); \
        }                                                                    \
    } while (0)

    LOAD_STAGE(0, 0);
    CP_COMMIT();
    LOAD_STAGE(1, 1);
    CP_COMMIT();

    for (int c = 0; c < 24; c++) {
        CP_WAIT1();        // stage c complete (only c+1's group may remain)
        __syncthreads();
        int s = c % 3;
        uint32_t base = sb + s * GST;
        uint32_t uAh = base, uAl = base + 8192;
        uint32_t uB  = base + 16384;
#pragma unroll
        for (int ks = 0; ks < 2; ks++) {
            uint32_t kb = (uint32_t)(ks * 32);
            uint32_t ah[2][4], al[2][4];
#pragma unroll
            for (int mi = 0; mi < 2; mi++) {
                uint32_t sw = SW64(a_off[mi] + kb);
                ldsm_x4(ah[mi], uAh + sw);
                ldsm_x4(al[mi], uAl + sw);
            }
#pragma unroll
            for (int bi = 0; bi < 4; bi++) {
                uint32_t bw[4];
                ldsm_x4(bw, uB + SW64(b_off[bi] + kb));
#pragma unroll
                for (int sel = 0; sel < 2; sel++) {
                    int ni = bi * 2 + sel;
#pragma unroll
                    for (int mi = 0; mi < 2; mi++) {
                        mma16816(acc[mi][ni], ah[mi], bw[sel], bw[sel + 2]);
                        mma16816(acc[mi][ni], al[mi], bw[sel], bw[sel + 2]);
                    }
                }
            }
        }
        __syncthreads();   // reads of stage s done before it is overwritten
        if (c + 2 < 24) { LOAD_STAGE(c + 2, (c + 2) % 3); }
        CP_COMMIT();
    }
#undef LOAD_STAGE

    int r = lane >> 2, cp = (lane & 3) * 2;
    if (z == 0) {
#pragma unroll
        for (int mi = 0; mi < 2; mi++) {
            int mbase = m0 + wm * 32 + mi * 16;
#pragma unroll
            for (int ni = 0; ni < 8; ni++) {
                int nbase = n0 + wn * 64 + ni * 8 + cp;
                float b0 = bias[nbase], b1 = bias[nbase + 1];
#pragma unroll
                for (int hr = 0; hr < 2; hr++) {
                    int row = mbase + r + hr * 8;
                    float v0 = (acc[mi][ni][hr * 2 + 0] + b0) * scale;
                    float v1 = (acc[mi][ni][hr * 2 + 1] + b1) * scale;
                    __half h0 = __float2half(v0);
                    __half h1 = __float2half(v1);
                    __half l0 = __float2half(v0 - __half2float(h0));
                    __half l1 = __float2half(v1 - __half2float(h1));
                    __half ph[2] = {h0, h1}, pl[2] = {l0, l1};
                    *(uint32_t*)(q1 + (size_t)row * EMB + nbase) = *(uint32_t*)ph;
                    *(uint32_t*)(q2 + (size_t)row * EMB + nbase) = *(uint32_t*)pl;
                }
            }
        }
    } else if (z == 1 || z == 2) {
        __half* Y = (z == 1) ? k1 : v1;
#pragma unroll
        for (int mi = 0; mi < 2; mi++) {
            int mbase = m0 + wm * 32 + mi * 16;
#pragma unroll
            for (int ni = 0; ni < 8; ni++) {
                int nbase = n0 + wn * 64 + ni * 8 + cp;
                float b0 = bias[nbase], b1 = bias[nbase + 1];
#pragma unroll
                for (int hr = 0; hr < 2; hr++) {
                    int row = mbase + r + hr * 8;
                    __half ph[2];
                    ph[0] = __float2half(acc[mi][ni][hr * 2 + 0] + b0);
                    ph[1] = __float2half(acc[mi][ni][hr * 2 + 1] + b1);
                    *(uint32_t*)(Y + (size_t)row * EMB + nbase) = *(uint32_t*)ph;
                }
            }
        }
    } else {
        float* Y = (z == 3) ? kg : (z == 4) ? vg : qg;
#pragma unroll
        for (int mi = 0; mi < 2; mi++) {
            int mbase = m0 + wm * 32 + mi * 16;
#pragma unroll
            for (int ni = 0; ni < 8; ni++) {
                int nbase = n0 + wn * 64 + ni * 8 + cp;
                float b0 = bias[nbase], b1 = bias[nbase + 1];
#pragma unroll
                for (int hr = 0; hr < 2; hr++) {
                    int row = mbase + r + hr * 8;
                    if (z == 5 && row >= BATCH * GLB) continue;
                    float2 o;
                    o.x = (acc[mi][ni][hr * 2 + 0] + b0) * scale;
                    o.y = (acc[mi][ni][hr * 2 + 1] + b1) * scale;
                    *(float2*)(Y + (size_t)row * EMB + nbase) = o;
                }
            }
        }
    }
}

__global__ __launch_bounds__(256, 2) void mma_gemm3a_kernel(
    const __half* __restrict__ xh, const __half* __restrict__ xl,
    const __half* __restrict__ wt,
    const float* __restrict__ bq, const float* __restrict__ bk,
    const float* __restrict__ bv, const float* __restrict__ bkg,
    const float* __restrict__ bvg, const float* __restrict__ bqg,
    __half* q1, __half* q2, __half* k1, __half* v1,
    float* kg, float* vg, float* qg)
{
    extern __shared__ char dsm[];
    gemm_core(blockIdx.z, blockIdx.y * 128, blockIdx.x * 128,
              xh, xl, wt, bq, bk, bv, bkg, bvg, bqg,
              q1, q2, k1, v1, kg, vg, qg, dsm);
}

__global__ __launch_bounds__(256, 2) void mma_gemm3b_kernel(
    const __half* __restrict__ xh, const __half* __restrict__ xl,
    const __half* __restrict__ wt,
    const float* __restrict__ bq, const float* __restrict__ bk,
    const float* __restrict__ bv, const float* __restrict__ bkg,
    const float* __restrict__ bvg, const float* __restrict__ bqg,
    __half* q1, __half* q2, __half* k1, __half* v1,
    float* kg, float* vg, float* qg)
{
    extern __shared__ char dsm[];
    int z = 3 + blockIdx.z;
    if (z == 5 && blockIdx.y > 0) return;
    gemm_core(z, blockIdx.y * 128, blockIdx.x * 128,
              xh, xl, wt, bq, bk, bv, bkg, bvg, bqg,
              q1, q2, k1, v1, kg, vg, qg, dsm);
}

// ---------------- Local attention, Q-tile 64, cp.async double-buffered -----
#define L_QH 0
#define L_QL 8192
#define L_K  16384
#define L_V  24576
#define L_SC 32768
#define L_PH 41984
#define L_PL 47104
#define L_RS 52224
#define L_LS 52480
#define L_MS 52736
#define L_TOTAL 53248

__global__ __launch_bounds__(256) void local_attn_mma(
    const __half* __restrict__ q1, const __half* __restrict__ q2,
    const __half* __restrict__ k1, const __half* __restrict__ v1,
    const int* __restrict__ mask, float* __restrict__ out)
{
    extern __shared__ char lsm[];
    uint32_t sbase = smem_to_u32(lsm);
    float* sc = (float*)(lsm + L_SC);
    __half* pbh = (__half*)(lsm + L_PH);
    __half* pbl = (__half*)(lsm + L_PL);
    float* rs = (float*)(lsm + L_RS);
    float* ls = (float*)(lsm + L_LS);
    int* msk = (int*)(lsm + L_MS);

    int b = blockIdx.z, h = blockIdx.y, i0 = blockIdx.x * QT2;
    int t = threadIdx.x, w = t >> 5, lane = t & 31;
    int qi = t >> 2, sub = t & 3;
    int iq = i0 + qi;

    uint32_t uQh = sbase + L_QH, uQl = sbase + L_QL;
    uint32_t uPh = sbase + L_PH, uPl = sbase + L_PL;

#pragma unroll
    for (int i = 0; i < 2; i++) {
        int idx = t + i * 256;
        int r = idx >> 3, u = idx & 7;
        size_t g = ((size_t)(b * S_LEN + i0 + r)) * EMB + h * HDIM + u * 8;
        uint32_t sw = SW128((uint32_t)(r * 128 + u * 16));
        *(uint4*)(lsm + L_QH + sw) = *(const uint4*)(q1 + g);
        *(uint4*)(lsm + L_QL + sw) = *(const uint4*)(q2 + g);
    }

    int lo = i0 - WIN; if (lo < 0) lo = 0;
    int hi = i0 + QT2 - 1 + WIN; if (hi > S_LEN - 1) hi = S_LEN - 1;
    int wstart = lo & ~31;
    int nwin = (hi - wstart) / 32 + 1;

#define LOAD_KV(kstart_, s_) do {                                            \
        int r_ = t >> 3, u_ = t & 7;                                         \
        int p_ = (kstart_) + r_;                                             \
        int ok_ = p_ < S_LEN;                                                \
        int pc_ = ok_ ? p_ : (S_LEN - 1);                                    \
        size_t g_ = ((size_t)(b * S_LEN + pc_)) * EMB + h * HDIM + u_ * 8;   \
        uint32_t sw_ = SW128((uint32_t)(r_ * 128 + u_ * 16));                \
        CPZ16(sbase + L_K + (s_) * 4096 + sw_, k1 + g_, ok_);                \
        CPZ16(sbase + L_V + (s_) * 4096 + sw_, v1 + g_, ok_);                \
        if (t < 32) {                                                        \
            int p2_ = (kstart_) + t;                                         \
            int ok2_ = p2_ < S_LEN;                                          \
            const int* ms_ = mask + b * S_LEN + (ok2_ ? p2_ : (S_LEN - 1));  \
            CPZ4(sbase + L_MS + (s_) * 128 + t * 4, ms_, ok2_);              \
        }                                                                    \
    } while (0)

    LOAD_KV(0, 0);
    CP_COMMIT();

    int wm = w & 3;
    int wn = w >> 2;
    uint32_t aoff = (uint32_t)((wm * 16 + (lane & 15)) * 128 + ((lane >> 4) << 4));
    uint32_t boff = (uint32_t)((wn * 16 + (lane & 15)) * 128 + ((lane >> 4) << 4));
    uint32_t poff = (uint32_t)((wm * 16 + (lane & 15)) * 80 + ((lane >> 4) << 4));
    int vtile = lane >> 3, vrow = lane & 7;
    uint32_t vbase0 = (uint32_t)(((vtile & 1) * 8 + vrow) * 128 +
                                 wn * 64 + ((vtile >> 1) << 4));

    __syncthreads();
    uint32_t qfh[4][4], qfl[4][4];
#pragma unroll
    for (int ks = 0; ks < 4; ks++) {
        uint32_t kb = (uint32_t)(ks * 32);
        ldsm_x4(qfh[ks], uQh + SW128(aoff + kb));
        ldsm_x4(qfl[ks], uQl + SW128(aoff + kb));
    }

    float oacc[4][4];
#pragma unroll
    for (int ni = 0; ni < 4; ni++)
#pragma unroll
        for (int c = 0; c < 4; c++) oacc[ni][c] = 0.f;
    float m_run = -1e30f, l_run = 0.f;

    for (int ci = -1; ci < nwin; ci++) {
        bool gl = (ci < 0);
        int kstart = gl ? 0 : wstart + ci * 32;
        int s = (ci + 1) & 1;

        __syncthreads();
        if (ci + 1 < nwin) LOAD_KV(wstart + (ci + 1) * 32, s ^ 1);
        CP_COMMIT();
        CP_WAIT1();
        __syncthreads();

        uint32_t uK = sbase + L_K + s * 4096;
        uint32_t uV = sbase + L_V + s * 4096;
        const int* mskS = msk + s * 32;

        {
            float f0[4] = {0.f, 0.f, 0.f, 0.f};
            float f1[4] = {0.f, 0.f, 0.f, 0.f};
#pragma unroll
            for (int ks = 0; ks < 4; ks++) {
                uint32_t bw[4];
                ldsm_x4(bw, uK + SW128(boff + (uint32_t)(ks * 32)));
                mma16816(f0, qfh[ks], bw[0], bw[2]);
                mma16816(f0, qfl[ks], bw[0], bw[2]);
                mma16816(f1, qfh[ks], bw[1], bw[3]);
                mma16816(f1, qfl[ks], bw[1], bw[3]);
            }
            int r = wm * 16 + (lane >> 2), c = wn * 16 + (lane & 3) * 2;
            *(float2*)&sc[r * 36 + c]           = make_float2(f0[0], f0[1]);
            *(float2*)&sc[(r + 8) * 36 + c]     = make_float2(f0[2], f0[3]);
            *(float2*)&sc[r * 36 + c + 8]       = make_float2(f1[0], f1[1]);
            *(float2*)&sc[(r + 8) * 36 + c + 8] = make_float2(f1[2], f1[3]);
        }
        __syncthreads();

        {
            float4 s4a = *(float4*)&sc[qi * 36 + sub * 8];
            float4 s4b = *(float4*)&sc[qi * 36 + sub * 8 + 4];
            float sv[8] = {s4a.x, s4a.y, s4a.z, s4a.w, s4b.x, s4b.y, s4b.z, s4b.w};
            if (!gl) {
#pragma unroll
                for (int u2 = 0; u2 < 8; u2++) {
                    int j = sub * 8 + u2, p = kstart + j;
                    bool valid = (p < S_LEN) && (p >= iq - WIN) && (p <= iq + WIN);
                    if (!valid) sv[u2] = -1e30f;
                    else if (mskS[j]) sv[u2] -= 10000.f;
                }
            }
            float cm = sv[0];
#pragma unroll
            for (int u2 = 1; u2 < 8; u2++) cm = fmaxf(cm, sv[u2]);
            cm = fmaxf(cm, __shfl_xor_sync(0xffffffffu, cm, 1));
            cm = fmaxf(cm, __shfl_xor_sync(0xffffffffu, cm, 2));
            float m_new = fmaxf(m_run, cm);
            float rsc = __expf(m_run - m_new);
            float psum = 0.f;
            __half eh[8], el[8];
#pragma unroll
            for (int u2 = 0; u2 < 8; u2++) {
                float e = __expf(sv[u2] - m_new);
                psum += e;
                eh[u2] = __float2half(e);
                el[u2] = __float2half(e - __half2float(eh[u2]));
            }
            psum += __shfl_xor_sync(0xffffffffu, psum, 1);
            psum += __shfl_xor_sync(0xffffffffu, psum, 2);
            l_run = l_run * rsc + psum;
            m_run = m_new;
            *(uint4*)(pbh + qi * 40 + sub * 8) = *(const uint4*)eh;
            *(uint4*)(pbl + qi * 40 + sub * 8) = *(const uint4*)el;
            if (sub == 0) rs[qi] = rsc;
        }
        __syncthreads();

        {
            float r0 = rs[wm * 16 + (lane >> 2)];
            float r1 = rs[wm * 16 + 8 + (lane >> 2)];
#pragma unroll
            for (int ni = 0; ni < 4; ni++) {
                oacc[ni][0] *= r0; oacc[ni][1] *= r0;
                oacc[ni][2] *= r1; oacc[ni][3] *= r1;
            }
#pragma unroll
            for (int ks = 0; ks < 2; ks++) {
                uint32_t ap0[4], ap1[4];
                ldsm_x4(ap0, uPh + poff + ks * 32);
                ldsm_x4(ap1, uPl + poff + ks * 32);
#pragma unroll
                for (int hs = 0; hs < 2; hs++) {
                    uint32_t bv0[4];
                    uint32_t va = SW128(vbase0 + (uint32_t)(hs * 32) +
                                        (uint32_t)(ks * 2048));
                    ldsm_x4t(bv0, uV + va);
                    mma16816(oacc[hs * 2 + 0], ap0, bv0[0], bv0[1]);
                    mma16816(oacc[hs * 2 + 0], ap1, bv0[0], bv0[1]);
                    mma16816(oacc[hs * 2 + 1], ap0, bv0[2], bv0[3]);
                    mma16816(oacc[hs * 2 + 1], ap1, bv0[2], bv0[3]);
                }
            }
        }
    }
#undef LOAD_KV

    if (sub == 0) ls[qi] = l_run;
    __syncthreads();
    {
        float i0v = 1.f / ls[wm * 16 + (lane >> 2)];
        float i1v = 1.f / ls[wm * 16 + 8 + (lane >> 2)];
        int r = wm * 16 + (lane >> 2);
#pragma unroll
        for (int ni = 0; ni < 4; ni++) {
            int c = wn * 32 + ni * 8 + (lane & 3) * 2;
            size_t o0 = ((size_t)(b * S_LEN + i0 + r)) * EMB + h * HDIM + c;
            size_t o1 = ((size_t)(b * S_LEN + i0 + r + 8)) * EMB + h * HDIM + c;
            float2 v0; v0.x = oacc[ni][0] * i0v; v0.y = oacc[ni][1] * i0v;
            float2 v1; v1.x = oacc[ni][2] * i1v; v1.y = oacc[ni][3] * i1v;
            *(float2*)(out + o0) = v0;
            *(float2*)(out + o1) = v1;
        }
    }
}

// ---------------- Global rows: split-K partial flash ----------------
__global__ __launch_bounds__(256, 2) void global_part_kernel(
    const float* __restrict__ qg, const float* __restrict__ kg,
    const float* __restrict__ vg,
    float* __restrict__ po, float* __restrict__ pm, float* __restrict__ pl)
{
    __shared__ float ks[32][68];
    __shared__ float vs[32][68];
    __shared__ float sc[32][36];

    int seg = blockIdx.x, h = blockIdx.y, b = blockIdx.z;
    int t = threadIdx.x;
    int qi = t >> 3, sub = t & 7;

    u64 q2[32];
    {
        const ulonglong2* qrow = (const ulonglong2*)
            (qg + ((size_t)(b * GLB + qi)) * EMB + h * HDIM);
#pragma unroll
        for (int e = 0; e < 16; e++) {
            ulonglong2 t2 = qrow[e];
            q2[e * 2] = t2.x; q2[e * 2 + 1] = t2.y;
        }
    }
    u64 acc2[4] = {0ULL, 0ULL, 0ULL, 0ULL};
    float m_run = -1e30f, l_run = 0.f;

    for (int c = 0; c < SEGLEN / 32; c++) {
        int kstart = seg * SEGLEN + c * 32;
        __syncthreads();
        for (int u = t; u < 32 * 16; u += 256) {
            int r = u >> 4, cc = (u & 15) << 2;
            size_t off = ((size_t)(b * S_LEN + kstart + r)) * EMB + h * HDIM + cc;
            *(float4*)&ks[r][cc] = *(const float4*)(kg + off);
            *(float4*)&vs[r][cc] = *(const float4*)(vg + off);
        }
        __syncthreads();

        float sv[4];
#pragma unroll
        for (int u2 = 0; u2 < 4; u2++) {
            int j = sub * 4 + u2;
            const ulonglong2* kr = (const ulonglong2*)&ks[j][0];
            u64 s0 = 0ULL, s1 = 0ULL, s2 = 0ULL, s3 = 0ULL;
#pragma unroll
            for (int e = 0; e < 16; e += 2) {
                ulonglong2 ka = kr[e];
                ulonglong2 kb = kr[e + 1];
                s0 = ffma2(q2[e * 2],     ka.x, s0);
                s1 = ffma2(q2[e * 2 + 1], ka.y, s1);
                s2 = ffma2(q2[e * 2 + 2], kb.x, s2);
                s3 = ffma2(q2[e * 2 + 3], kb.y, s3);
            }
            float2 r2 = up2(fadd2(fadd2(s0, s1), fadd2(s2, s3)));
            sv[u2] = r2.x + r2.y;
        }
        float cm = fmaxf(fmaxf(sv[0], sv[1]), fmaxf(sv[2], sv[3]));
        cm = fmaxf(cm, __shfl_xor_sync(0xffffffffu, cm, 1));
        cm = fmaxf(cm, __shfl_xor_sync(0xffffffffu, cm, 2));
        cm = fmaxf(cm, __shfl_xor_sync(0xffffffffu, cm, 4));
        float m_new = fmaxf(m_run, cm);
        float rsc = __expf(m_run - m_new);
        float psum = 0.f;
#pragma unroll
        for (int u2 = 0; u2 < 4; u2++) {
            float e = __expf(sv[u2] - m_new);
            sc[qi][sub * 4 + u2] = e;
            psum += e;
        }
        psum += __shfl_xor_sync(0xffffffffu, psum, 1);
        psum += __shfl_xor_sync(0xffffffffu, psum, 2);
        psum += __shfl_xor_sync(0xffffffffu, psum, 4);
        l_run = l_run * rsc + psum;
        m_run = m_new;
        __syncwarp();

        u64 rb = dup2(rsc);
#pragma unroll
        for (int d = 0; d < 4; d++) acc2[d] = fmul2(acc2[d], rb);
#pragma unroll 4
        for (int j = 0; j < 32; j++) {
            u64 eb = dup2(sc[qi][j]);
            ulonglong2 v0 = *(const ulonglong2*)&vs[j][sub * 4];
            ulonglong2 v1 = *(const ulonglong2*)&vs[j][sub * 4 + 32];
            acc2[0] = ffma2(eb, v0.x, acc2[0]);
            acc2[1] = ffma2(eb, v0.y, acc2[1]);
            acc2[2] = ffma2(eb, v1.x, acc2[2]);
            acc2[3] = ffma2(eb, v1.y, acc2[3]);
        }
    }

    size_t pidx = (((size_t)seg * BATCH + b) * NH + h) * GLB + qi;
    float2 a0 = up2(acc2[0]), a1 = up2(acc2[1]);
    float2 a2 = up2(acc2[2]), a3 = up2(acc2[3]);
    float* prow = po + pidx * HDIM;
    *(float4*)(prow + sub * 4)      = make_float4(a0.x, a0.y, a1.x, a1.y);
    *(float4*)(prow + 32 + sub * 4) = make_float4(a2.x, a2.y, a3.x, a3.y);
    if (sub == 0) { pm[pidx] = m_run; pl[pidx] = l_run; }
}

__global__ __launch_bounds__(64) void global_merge_kernel(
    const float* __restrict__ po, const float* __restrict__ pm,
    const float* __restrict__ pl, float* __restrict__ out)
{
    int g = blockIdx.x, h = blockIdx.y, b = blockIdx.z;
    int d = threadIdx.x;

    float mv[NSEG];
    float mx = -1e30f;
#pragma unroll
    for (int s = 0; s < NSEG; s++) {
        mv[s] = pm[(((size_t)s * BATCH + b) * NH + h) * GLB + g];
        mx = fmaxf(mx, mv[s]);
    }
    float num = 0.f, den = 0.f;
#pragma unroll
    for (int s = 0; s < NSEG; s++) {
        size_t pidx = (((size_t)s * BATCH + b) * NH + h) * GLB + g;
        float w = __expf(mv[s] - mx);
        num += w * po[pidx * HDIM + d];
        den += w * pl[pidx];
    }
    out[((size_t)(b * S_LEN + g)) * EMB + h * HDIM + d] = num / den;
}

// ---------------- launch ----------------
extern "C" void kernel_launch(void* const* d_in, const int* in_sizes, int n_in,
                              void* d_out, int out_size)
{
    (void)n_in; (void)out_size;
    int base = (in_sizes[2] == EMB * EMB) ? 2 : 3;

    const float* x    = (const float*)d_in[0];
    const int*   mask = (const int*)d_in[1];
    const float* wq   = (const float*)d_in[base + 0];
    const float* bq   = (const float*)d_in[base + 1];
    const float* wk   = (const float*)d_in[base + 2];
    const float* bk   = (const float*)d_in[base + 3];
    const float* wv   = (const float*)d_in[base + 4];
    const float* bv   = (const float*)d_in[base + 5];
    const float* wqg  = (const float*)d_in[base + 6];
    const float* bqg  = (const float*)d_in[base + 7];
    const float* wkg  = (const float*)d_in[base + 8];
    const float* bkg  = (const float*)d_in[base + 9];
    const float* wvg  = (const float*)d_in[base + 10];
    const float* bvg  = (const float*)d_in[base + 11];
    float* out = (float*)d_out;

    float *kg, *vg, *qg, *po, *pm, *pl;
    __half *xh, *xl, *wt, *q1, *q2, *k1, *v1;
    cudaGetSymbolAddress((void**)&kg, g_kg);
    cudaGetSymbolAddress((void**)&vg, g_vg);
    cudaGetSymbolAddress((void**)&qg, g_qg);
    cudaGetSymbolAddress((void**)&xh, g_xh);
    cudaGetSymbolAddress((void**)&xl, g_xl);
    cudaGetSymbolAddress((void**)&wt, g_wt);
    cudaGetSymbolAddress((void**)&q1, g_q1);
    cudaGetSymbolAddress((void**)&q2, g_q2);
    cudaGetSymbolAddress((void**)&k1, g_k1);
    cudaGetSymbolAddress((void**)&v1, g_v1);
    cudaGetSymbolAddress((void**)&po, g_po);
    cudaGetSymbolAddress((void**)&pm, g_pm);
    cudaGetSymbolAddress((void**)&pl, g_pl);

    cudaFuncSetAttribute(mma_gemm3a_kernel,
                         cudaFuncAttributeMaxDynamicSharedMemorySize, GSM3);
    cudaFuncSetAttribute(mma_gemm3b_kernel,
                         cudaFuncAttributeMaxDynamicSharedMemorySize, GSM3);
    cudaFuncSetAttribute(local_attn_mma,
                         cudaFuncAttributeMaxDynamicSharedMemorySize, L_TOTAL);

    convx_kernel<<<(BATCH * S_LEN * EMB) / (256 * 4), 256>>>(x, xh, xl);
    convw_kernel<<<dim3(EMB / 32, EMB / 32, 6), 256>>>(
        wq, wk, wv, wkg, wvg, wqg, wt);
    mma_gemm3a_kernel<<<dim3(EMB / 128, BATCH * S_LEN / 128, 3), 256, GSM3>>>(
        xh, xl, wt, bq, bk, bv, bkg, bvg, bqg,
        q1, q2, k1, v1, kg, vg, qg);
    mma_gemm3b_kernel<<<dim3(EMB / 128, BATCH * S_LEN / 128, 3), 256, GSM3>>>(
        xh, xl, wt, bq, bk, bv, bkg, bvg, bqg,
        q1, q2, k1, v1, kg, vg, qg);
    local_attn_mma<<<dim3(S_LEN / QT2, NH, BATCH), 256, L_TOTAL>>>(
        q1, q2, k1, v1, mask, out);
    global_part_kernel<<<dim3(NSEG, NH, BATCH), 256>>>(qg, kg, vg, po, pm, pl);
    global_merge_kernel<<<dim3(GLB, NH, BATCH), 64>>>(po, pm, pl, out);
}

// round 13
// speedup vs baseline: 1.0924x; 1.0924x over previous
#include <cuda_runtime.h>
#include <cuda_fp16.h>
#include <cstdint>

#define S_LEN 4096
#define BATCH 2
#define EMB   768
#define NH    12
#define HDIM  64
#define WIN   256
#define GLB   32
#define QT2   64
#define NSEG  16
#define SEGLEN (S_LEN / NSEG)

typedef unsigned long long u64;

// ---------- packed f32x2 helpers ----------
__device__ __forceinline__ u64 pk2(float x, float y) {
    u64 r; asm("mov.b64 %0, {%1,%2};" : "=l"(r) : "f"(x), "f"(y)); return r;
}
__device__ __forceinline__ u64 dup2(float x) { return pk2(x, x); }
__device__ __forceinline__ float2 up2(u64 v) {
    float2 f; asm("mov.b64 {%0,%1}, %2;" : "=f"(f.x), "=f"(f.y) : "l"(v)); return f;
}
__device__ __forceinline__ u64 ffma2(u64 a, u64 b, u64 c) {
    u64 d; asm("fma.rn.f32x2 %0, %1, %2, %3;" : "=l"(d) : "l"(a), "l"(b), "l"(c)); return d;
}
__device__ __forceinline__ u64 fadd2(u64 a, u64 b) {
    u64 d; asm("add.rn.f32x2 %0, %1, %2;" : "=l"(d) : "l"(a), "l"(b)); return d;
}
__device__ __forceinline__ u64 fmul2(u64 a, u64 b) {
    u64 d; asm("mul.rn.f32x2 %0, %1, %2;" : "=l"(d) : "l"(a), "l"(b)); return d;
}

__device__ __forceinline__ uint32_t smem_to_u32(const void* p) {
    uint32_t a;
    asm("{ .reg .u64 t; cvta.to.shared.u64 t, %1; cvt.u32.u64 %0, t; }" : "=r"(a) : "l"(p));
    return a;
}
#define SW128(o) ((o) ^ (((o) >> 3) & 0x70))

#define CP16(dst, src) \
    asm volatile("cp.async.cg.shared.global [%0], [%1], 16;" \
                 :: "r"(dst), "l"(src) : "memory")
#define CPZ16(dst, src, pred) do { \
    int _sz = (pred) ? 16 : 0; \
    asm volatile("cp.async.cg.shared.global [%0], [%1], 16, %2;" \
                 :: "r"(dst), "l"(src), "r"(_sz) : "memory"); } while (0)
#define CPZ4(dst, src, pred) do { \
    int _sz = (pred) ? 4 : 0; \
    asm volatile("cp.async.ca.shared.global [%0], [%1], 4, %2;" \
                 :: "r"(dst), "l"(src), "r"(_sz) : "memory"); } while (0)
#define CP_COMMIT() asm volatile("cp.async.commit_group;" ::: "memory")
#define CP_WAIT1()  asm volatile("cp.async.wait_group 1;" ::: "memory")

__device__ __forceinline__ void ldsm_x4(uint32_t* r, uint32_t addr) {
    asm volatile("ldmatrix.sync.aligned.m8n8.x4.shared.b16 {%0,%1,%2,%3}, [%4];"
                 : "=r"(r[0]), "=r"(r[1]), "=r"(r[2]), "=r"(r[3]) : "r"(addr));
}
__device__ __forceinline__ void ldsm_x4t(uint32_t* r, uint32_t addr) {
    asm volatile("ldmatrix.sync.aligned.m8n8.x4.trans.shared.b16 {%0,%1,%2,%3}, [%4];"
                 : "=r"(r[0]), "=r"(r[1]), "=r"(r[2]), "=r"(r[3]) : "r"(addr));
}
// fp16 mma, fp32 accum
__device__ __forceinline__ void mma16816(float* c, const uint32_t* a,
                                         uint32_t b0, uint32_t b1) {
    asm volatile(
        "mma.sync.aligned.m16n8k16.row.col.f32.f16.f16.f32 "
        "{%0,%1,%2,%3}, {%4,%5,%6,%7}, {%8,%9}, {%0,%1,%2,%3};"
        : "+f"(c[0]), "+f"(c[1]), "+f"(c[2]), "+f"(c[3])
        : "r"(a[0]), "r"(a[1]), "r"(a[2]), "r"(a[3]), "r"(b0), "r"(b1));
}

// -------- scratch --------
__device__ float g_kg[BATCH * S_LEN * EMB];
__device__ float g_vg[BATCH * S_LEN * EMB];
__device__ float g_qg[BATCH * GLB * EMB];
__device__ __half g_xh[BATCH * S_LEN * EMB];
__device__ __half g_xl[BATCH * S_LEN * EMB];
__device__ __half g_wt[6 * EMB * EMB];
__device__ __half g_q1[BATCH * S_LEN * EMB];
__device__ __half g_q2[BATCH * S_LEN * EMB];
__device__ __half g_k1[BATCH * S_LEN * EMB];
__device__ __half g_v1[BATCH * S_LEN * EMB];
__device__ float g_po[NSEG * BATCH * NH * GLB * HDIM];
__device__ float g_pm[NSEG * BATCH * NH * GLB];
__device__ float g_pl[NSEG * BATCH * NH * GLB];

// ---------------- prep: x -> fp16 hi/lo ----------------
__global__ __launch_bounds__(256) void convx_kernel(
    const float* __restrict__ x, __half* __restrict__ xh,
    __half* __restrict__ xl)
{
    int i = (blockIdx.x * 256 + threadIdx.x) * 4;
    float4 a = *(const float4*)(x + i);
    __half h[4], l[4];
    float av[4] = {a.x, a.y, a.z, a.w};
#pragma unroll
    for (int j = 0; j < 4; j++) {
        h[j] = __float2half(av[j]);
        l[j] = __float2half(av[j] - __half2float(h[j]));
    }
    *(uint2*)(xh + i) = *(const uint2*)h;
    *(uint2*)(xl + i) = *(const uint2*)l;
}

// ---------------- prep: W -> W^T single fp16 (6 weights) ----------------
__global__ __launch_bounds__(256) void convw_kernel(
    const float* __restrict__ w0, const float* __restrict__ w1,
    const float* __restrict__ w2, const float* __restrict__ w3,
    const float* __restrict__ w4, const float* __restrict__ w5,
    __half* __restrict__ wt)
{
    __shared__ float tile[32][33];
    int z = blockIdx.z;
    const float* W = (z == 0) ? w0 : (z == 1) ? w1 : (z == 2) ? w2 :
                     (z == 3) ? w3 : (z == 4) ? w4 : w5;
    int kb = blockIdx.y * 32, nb = blockIdx.x * 32;
    int tx = threadIdx.x & 31, ty = threadIdx.x >> 5;
    for (int i = ty; i < 32; i += 8)
        tile[i][tx] = W[(size_t)(kb + i) * EMB + nb + tx];
    __syncthreads();
    for (int j = ty; j < 32; j += 8) {
        size_t o = (size_t)z * EMB * EMB + (size_t)(nb + j) * EMB + kb + tx;
        wt[o] = __float2half(tile[tx][j]);
    }
}

// ------- mma.sync GEMM: 128x128 CTA, 256 thr, warp 32x64, k-chunk 64 -------
// 2-stage cp.async, SW128 swizzle, 12 chunks -> half the barrier quanta.
#define GST  49152                 // AH 16K, AL 16K, B 16K per stage
#define GSM2 (2 * GST)             // 96 KB -> 2 CTA/SM

__global__ __launch_bounds__(256, 2) void mma_gemm6_kernel(
    const __half* __restrict__ xh, const __half* __restrict__ xl,
    const __half* __restrict__ wt,
    const float* __restrict__ bq, const float* __restrict__ bk,
    const float* __restrict__ bv, const float* __restrict__ bkg,
    const float* __restrict__ bvg, const float* __restrict__ bqg,
    __half* q1, __half* q2, __half* k1, __half* v1,
    float* kg, float* vg, float* qg)
{
    extern __shared__ char dsm[];
    int z = blockIdx.z;
    if (z == 5 && blockIdx.y > 0) return;
    int t = threadIdx.x, wid = t >> 5, lane = t & 31;
    int m0 = blockIdx.y * 128, n0 = blockIdx.x * 128;
    int wm = wid & 3, wn = wid >> 2;   // warp tile 32(m) x 64(n)

    const float* bias;
    switch (z) {
        case 0:  bias = bq;  break;
        case 1:  bias = bk;  break;
        case 2:  bias = bv;  break;
        case 3:  bias = bkg; break;
        case 4:  bias = bvg; break;
        default: bias = bqg; break;
    }
    float scale = (z == 0 || z == 5) ? 0.125f : 1.0f;
    const __half* Bw = wt + (size_t)z * EMB * EMB;

    uint32_t sb = smem_to_u32(dsm);

    float acc[2][8][4];
#pragma unroll
    for (int mi = 0; mi < 2; mi++)
#pragma unroll
        for (int ni = 0; ni < 8; ni++)
#pragma unroll
            for (int c = 0; c < 4; c++) acc[mi][ni][c] = 0.f;

    uint32_t a_off[2], b_off[4];
#pragma unroll
    for (int mi = 0; mi < 2; mi++) {
        int row = wm * 32 + mi * 16 + (lane & 15);
        a_off[mi] = (uint32_t)(row * 128) + ((lane >> 4) << 4);
    }
#pragma unroll
    for (int bi = 0; bi < 4; bi++) {
        int row = wn * 64 + bi * 16 + (lane & 15);
        b_off[bi] = (uint32_t)(row * 128) + ((lane >> 4) << 4);
    }

#define LOAD_STAGE(chunk, s) do {                                            \
        int k0 = (chunk) * 64;                                               \
        uint32_t base = sb + (s) * GST;                                      \
        _Pragma("unroll")                                                    \
        for (int i = 0; i < 4; i++) {                                        \
            int idx = t + i * 256;                                           \
            int r = idx >> 3, u = idx & 7;                                   \
            uint32_t sw = SW128((uint32_t)(r * 128 + u * 16));               \
            size_t arow;                                                     \
            if (z == 5) { int q2r = r & 63;                                  \
                arow = (size_t)((q2r >> 5) * S_LEN + (q2r & 31)); }          \
            else arow = (size_t)(m0 + r);                                    \
            CP16(base + sw,         xh + arow * EMB + k0 + u * 8);           \
            CP16(base + 16384 + sw, xl + arow * EMB + k0 + u * 8);           \
            CP16(base + 32768 + sw, Bw + (size_t)(n0 + r) * EMB + k0 + u * 8); \
        }                                                                    \
    } while (0)

    LOAD_STAGE(0, 0);
    CP_COMMIT();

    for (int c = 0; c < 12; c++) {
        if (c < 11) LOAD_STAGE(c + 1, (c + 1) & 1);
        CP_COMMIT();
        CP_WAIT1();
        __syncthreads();
        uint32_t base = sb + (c & 1) * GST;
        uint32_t uAh = base, uAl = base + 16384;
        uint32_t uB  = base + 32768;
#pragma unroll
        for (int ks = 0; ks < 4; ks++) {
            uint32_t kb = (uint32_t)(ks * 32);
            uint32_t ah[2][4], al[2][4];
#pragma unroll
            for (int mi = 0; mi < 2; mi++) {
                uint32_t sw = SW128(a_off[mi] + kb);
                ldsm_x4(ah[mi], uAh + sw);
                ldsm_x4(al[mi], uAl + sw);
            }
#pragma unroll
            for (int bi = 0; bi < 4; bi++) {
                uint32_t bw[4];
                ldsm_x4(bw, uB + SW128(b_off[bi] + kb));
#pragma unroll
                for (int sel = 0; sel < 2; sel++) {
                    int ni = bi * 2 + sel;
#pragma unroll
                    for (int mi = 0; mi < 2; mi++) {
                        mma16816(acc[mi][ni], ah[mi], bw[sel], bw[sel + 2]);
                        mma16816(acc[mi][ni], al[mi], bw[sel], bw[sel + 2]);
                    }
                }
            }
        }
        __syncthreads();
    }
#undef LOAD_STAGE

    int r = lane >> 2, cp = (lane & 3) * 2;
    if (z == 0) {
#pragma unroll
        for (int mi = 0; mi < 2; mi++) {
            int mbase = m0 + wm * 32 + mi * 16;
#pragma unroll
            for (int ni = 0; ni < 8; ni++) {
                int nbase = n0 + wn * 64 + ni * 8 + cp;
                float b0 = bias[nbase], b1 = bias[nbase + 1];
#pragma unroll
                for (int hr = 0; hr < 2; hr++) {
                    int row = mbase + r + hr * 8;
                    float v0 = (acc[mi][ni][hr * 2 + 0] + b0) * scale;
                    float v1 = (acc[mi][ni][hr * 2 + 1] + b1) * scale;
                    __half h0 = __float2half(v0);
                    __half h1 = __float2half(v1);
                    __half l0 = __float2half(v0 - __half2float(h0));
                    __half l1 = __float2half(v1 - __half2float(h1));
                    __half ph[2] = {h0, h1}, pl[2] = {l0, l1};
                    *(uint32_t*)(q1 + (size_t)row * EMB + nbase) = *(uint32_t*)ph;
                    *(uint32_t*)(q2 + (size_t)row * EMB + nbase) = *(uint32_t*)pl;
                }
            }
        }
    } else if (z == 1 || z == 2) {
        __half* Y = (z == 1) ? k1 : v1;
#pragma unroll
        for (int mi = 0; mi < 2; mi++) {
            int mbase = m0 + wm * 32 + mi * 16;
#pragma unroll
            for (int ni = 0; ni < 8; ni++) {
                int nbase = n0 + wn * 64 + ni * 8 + cp;
                float b0 = bias[nbase], b1 = bias[nbase + 1];
#pragma unroll
                for (int hr = 0; hr < 2; hr++) {
                    int row = mbase + r + hr * 8;
                    __half ph[2];
                    ph[0] = __float2half(acc[mi][ni][hr * 2 + 0] + b0);
                    ph[1] = __float2half(acc[mi][ni][hr * 2 + 1] + b1);
                    *(uint32_t*)(Y + (size_t)row * EMB + nbase) = *(uint32_t*)ph;
                }
            }
        }
    } else {
        float* Y = (z == 3) ? kg : (z == 4) ? vg : qg;
#pragma unroll
        for (int mi = 0; mi < 2; mi++) {
            int mbase = m0 + wm * 32 + mi * 16;
#pragma unroll
            for (int ni = 0; ni < 8; ni++) {
                int nbase = n0 + wn * 64 + ni * 8 + cp;
                float b0 = bias[nbase], b1 = bias[nbase + 1];
#pragma unroll
                for (int hr = 0; hr < 2; hr++) {
                    int row = mbase + r + hr * 8;
                    if (z == 5 && row >= BATCH * GLB) continue;
                    float2 o;
                    o.x = (acc[mi][ni][hr * 2 + 0] + b0) * scale;
                    o.y = (acc[mi][ni][hr * 2 + 1] + b1) * scale;
                    *(float2*)(Y + (size_t)row * EMB + nbase) = o;
                }
            }
        }
    }
}

// ---------------- Local attention, Q-tile 64, cp.async double-buffered -----
#define L_QH 0
#define L_QL 8192
#define L_K  16384
#define L_V  24576
#define L_SC 32768
#define L_PH 41984
#define L_PL 47104
#define L_RS 52224
#define L_LS 52480
#define L_MS 52736
#define L_TOTAL 53248

__global__ __launch_bounds__(256) void local_attn_mma(
    const __half* __restrict__ q1, const __half* __restrict__ q2,
    const __half* __restrict__ k1, const __half* __restrict__ v1,
    const int* __restrict__ mask, float* __restrict__ out)
{
    extern __shared__ char lsm[];
    uint32_t sbase = smem_to_u32(lsm);
    float* sc = (float*)(lsm + L_SC);
    __half* pbh = (__half*)(lsm + L_PH);
    __half* pbl = (__half*)(lsm + L_PL);
    float* rs = (float*)(lsm + L_RS);
    float* ls = (float*)(lsm + L_LS);
    int* msk = (int*)(lsm + L_MS);

    int b = blockIdx.z, h = blockIdx.y, i0 = blockIdx.x * QT2;
    int t = threadIdx.x, w = t >> 5, lane = t & 31;
    int qi = t >> 2, sub = t & 3;
    int iq = i0 + qi;

    uint32_t uQh = sbase + L_QH, uQl = sbase + L_QL;
    uint32_t uPh = sbase + L_PH, uPl = sbase + L_PL;

#pragma unroll
    for (int i = 0; i < 2; i++) {
        int idx = t + i * 256;
        int r = idx >> 3, u = idx & 7;
        size_t g = ((size_t)(b * S_LEN + i0 + r)) * EMB + h * HDIM + u * 8;
        uint32_t sw = SW128((uint32_t)(r * 128 + u * 16));
        *(uint4*)(lsm + L_QH + sw) = *(const uint4*)(q1 + g);
        *(uint4*)(lsm + L_QL + sw) = *(const uint4*)(q2 + g);
    }

    int lo = i0 - WIN; if (lo < 0) lo = 0;
    int hi = i0 + QT2 - 1 + WIN; if (hi > S_LEN - 1) hi = S_LEN - 1;
    int wstart = lo & ~31;
    int nwin = (hi - wstart) / 32 + 1;

#define LOAD_KV(kstart_, s_) do {                                            \
        int r_ = t >> 3, u_ = t & 7;                                         \
        int p_ = (kstart_) + r_;                                             \
        int ok_ = p_ < S_LEN;                                                \
        int pc_ = ok_ ? p_ : (S_LEN - 1);                                    \
        size_t g_ = ((size_t)(b * S_LEN + pc_)) * EMB + h * HDIM + u_ * 8;   \
        uint32_t sw_ = SW128((uint32_t)(r_ * 128 + u_ * 16));                \
        CPZ16(sbase + L_K + (s_) * 4096 + sw_, k1 + g_, ok_);                \
        CPZ16(sbase + L_V + (s_) * 4096 + sw_, v1 + g_, ok_);                \
        if (t < 32) {                                                        \
            int p2_ = (kstart_) + t;                                         \
            int ok2_ = p2_ < S_LEN;                                          \
            const int* ms_ = mask + b * S_LEN + (ok2_ ? p2_ : (S_LEN - 1));  \
            CPZ4(sbase + L_MS + (s_) * 128 + t * 4, ms_, ok2_);              \
        }                                                                    \
    } while (0)

    LOAD_KV(0, 0);
    CP_COMMIT();

    int wm = w & 3;
    int wn = w >> 2;
    uint32_t aoff = (uint32_t)((wm * 16 + (lane & 15)) * 128 + ((lane >> 4) << 4));
    uint32_t boff = (uint32_t)((wn * 16 + (lane & 15)) * 128 + ((lane >> 4) << 4));
    uint32_t poff = (uint32_t)((wm * 16 + (lane & 15)) * 80 + ((lane >> 4) << 4));
    int vtile = lane >> 3, vrow = lane & 7;
    uint32_t vbase0 = (uint32_t)(((vtile & 1) * 8 + vrow) * 128 +
                                 wn * 64 + ((vtile >> 1) << 4));

    __syncthreads();
    uint32_t qfh[4][4], qfl[4][4];
#pragma unroll
    for (int ks = 0; ks < 4; ks++) {
        uint32_t kb = (uint32_t)(ks * 32);
        ldsm_x4(qfh[ks], uQh + SW128(aoff + kb));
        ldsm_x4(qfl[ks], uQl + SW128(aoff + kb));
    }

    float oacc[4][4];
#pragma unroll
    for (int ni = 0; ni < 4; ni++)
#pragma unroll
        for (int c = 0; c < 4; c++) oacc[ni][c] = 0.f;
    float m_run = -1e30f, l_run = 0.f;

    for (int ci = -1; ci < nwin; ci++) {
        bool gl = (ci < 0);
        int kstart = gl ? 0 : wstart + ci * 32;
        int s = (ci + 1) & 1;

        __syncthreads();
        if (ci + 1 < nwin) LOAD_KV(wstart + (ci + 1) * 32, s ^ 1);
        CP_COMMIT();
        CP_WAIT1();
        __syncthreads();

        uint32_t uK = sbase + L_K + s * 4096;
        uint32_t uV = sbase + L_V + s * 4096;
        const int* mskS = msk + s * 32;

        {
            float f0[4] = {0.f, 0.f, 0.f, 0.f};
            float f1[4] = {0.f, 0.f, 0.f, 0.f};
#pragma unroll
            for (int ks = 0; ks < 4; ks++) {
                uint32_t bw[4];
                ldsm_x4(bw, uK + SW128(boff + (uint32_t)(ks * 32)));
                mma16816(f0, qfh[ks], bw[0], bw[2]);
                mma16816(f0, qfl[ks], bw[0], bw[2]);
                mma16816(f1, qfh[ks], bw[1], bw[3]);
                mma16816(f1, qfl[ks], bw[1], bw[3]);
            }
            int r = wm * 16 + (lane >> 2), c = wn * 16 + (lane & 3) * 2;
            *(float2*)&sc[r * 36 + c]           = make_float2(f0[0], f0[1]);
            *(float2*)&sc[(r + 8) * 36 + c]     = make_float2(f0[2], f0[3]);
            *(float2*)&sc[r * 36 + c + 8]       = make_float2(f1[0], f1[1]);
            *(float2*)&sc[(r + 8) * 36 + c + 8] = make_float2(f1[2], f1[3]);
        }
        __syncthreads();

        {
            float4 s4a = *(float4*)&sc[qi * 36 + sub * 8];
            float4 s4b = *(float4*)&sc[qi * 36 + sub * 8 + 4];
            float sv[8] = {s4a.x, s4a.y, s4a.z, s4a.w, s4b.x, s4b.y, s4b.z, s4b.w};
            if (!gl) {
#pragma unroll
                for (int u2 = 0; u2 < 8; u2++) {
                    int j = sub * 8 + u2, p = kstart + j;
                    bool valid = (p < S_LEN) && (p >= iq - WIN) && (p <= iq + WIN);
                    if (!valid) sv[u2] = -1e30f;
                    else if (mskS[j]) sv[u2] -= 10000.f;
                }
            }
            float cm = sv[0];
#pragma unroll
            for (int u2 = 1; u2 < 8; u2++) cm = fmaxf(cm, sv[u2]);
            cm = fmaxf(cm, __shfl_xor_sync(0xffffffffu, cm, 1));
            cm = fmaxf(cm, __shfl_xor_sync(0xffffffffu, cm, 2));
            float m_new = fmaxf(m_run, cm);
            float rsc = __expf(m_run - m_new);
            float psum = 0.f;
            __half eh[8], el[8];
#pragma unroll
            for (int u2 = 0; u2 < 8; u2++) {
                float e = __expf(sv[u2] - m_new);
                psum += e;
                eh[u2] = __float2half(e);
                el[u2] = __float2half(e - __half2float(eh[u2]));
            }
            psum += __shfl_xor_sync(0xffffffffu, psum, 1);
            psum += __shfl_xor_sync(0xffffffffu, psum, 2);
            l_run = l_run * rsc + psum;
            m_run = m_new;
            *(uint4*)(pbh + qi * 40 + sub * 8) = *(const uint4*)eh;
            *(uint4*)(pbl + qi * 40 + sub * 8) = *(const uint4*)el;
            if (sub == 0) rs[qi] = rsc;
        }
        __syncthreads();

        {
            float r0 = rs[wm * 16 + (lane >> 2)];
            float r1 = rs[wm * 16 + 8 + (lane >> 2)];
#pragma unroll
            for (int ni = 0; ni < 4; ni++) {
                oacc[ni][0] *= r0; oacc[ni][1] *= r0;
                oacc[ni][2] *= r1; oacc[ni][3] *= r1;
            }
#pragma unroll
            for (int ks = 0; ks < 2; ks++) {
                uint32_t ap0[4], ap1[4];
                ldsm_x4(ap0, uPh + poff + ks * 32);
                ldsm_x4(ap1, uPl + poff + ks * 32);
#pragma unroll
                for (int hs = 0; hs < 2; hs++) {
                    uint32_t bv0[4];
                    uint32_t va = SW128(vbase0 + (uint32_t)(hs * 32) +
                                        (uint32_t)(ks * 2048));
                    ldsm_x4t(bv0, uV + va);
                    mma16816(oacc[hs * 2 + 0], ap0, bv0[0], bv0[1]);
                    mma16816(oacc[hs * 2 + 0], ap1, bv0[0], bv0[1]);
                    mma16816(oacc[hs * 2 + 1], ap0, bv0[2], bv0[3]);
                    mma16816(oacc[hs * 2 + 1], ap1, bv0[2], bv0[3]);
                }
            }
        }
    }
#undef LOAD_KV

    if (sub == 0) ls[qi] = l_run;
    __syncthreads();
    {
        float i0v = 1.f / ls[wm * 16 + (lane >> 2)];
        float i1v = 1.f / ls[wm * 16 + 8 + (lane >> 2)];
        int r = wm * 16 + (lane >> 2);
#pragma unroll
        for (int ni = 0; ni < 4; ni++) {
            int c = wn * 32 + ni * 8 + (lane & 3) * 2;
            size_t o0 = ((size_t)(b * S_LEN + i0 + r)) * EMB + h * HDIM + c;
            size_t o1 = ((size_t)(b * S_LEN + i0 + r + 8)) * EMB + h * HDIM + c;
            float2 v0; v0.x = oacc[ni][0] * i0v; v0.y = oacc[ni][1] * i0v;
            float2 v1; v1.x = oacc[ni][2] * i1v; v1.y = oacc[ni][3] * i1v;
            *(float2*)(out + o0) = v0;
            *(float2*)(out + o1) = v1;
        }
    }
}

// ---------------- Global rows: split-K partial flash ----------------
__global__ __launch_bounds__(256, 2) void global_part_kernel(
    const float* __restrict__ qg, const float* __restrict__ kg,
    const float* __restrict__ vg,
    float* __restrict__ po, float* __restrict__ pm, float* __restrict__ pl)
{
    __shared__ float ks[32][68];
    __shared__ float vs[32][68];
    __shared__ float sc[32][36];

    int seg = blockIdx.x, h = blockIdx.y, b = blockIdx.z;
    int t = threadIdx.x;
    int qi = t >> 3, sub = t & 7;

    u64 q2[32];
    {
        const ulonglong2* qrow = (const ulonglong2*)
            (qg + ((size_t)(b * GLB + qi)) * EMB + h * HDIM);
#pragma unroll
        for (int e = 0; e < 16; e++) {
            ulonglong2 t2 = qrow[e];
            q2[e * 2] = t2.x; q2[e * 2 + 1] = t2.y;
        }
    }
    u64 acc2[4] = {0ULL, 0ULL, 0ULL, 0ULL};
    float m_run = -1e30f, l_run = 0.f;

    for (int c = 0; c < SEGLEN / 32; c++) {
        int kstart = seg * SEGLEN + c * 32;
        __syncthreads();
        for (int u = t; u < 32 * 16; u += 256) {
            int r = u >> 4, cc = (u & 15) << 2;
            size_t off = ((size_t)(b * S_LEN + kstart + r)) * EMB + h * HDIM + cc;
            *(float4*)&ks[r][cc] = *(const float4*)(kg + off);
            *(float4*)&vs[r][cc] = *(const float4*)(vg + off);
        }
        __syncthreads();

        float sv[4];
#pragma unroll
        for (int u2 = 0; u2 < 4; u2++) {
            int j = sub * 4 + u2;
            const ulonglong2* kr = (const ulonglong2*)&ks[j][0];
            u64 s0 = 0ULL, s1 = 0ULL, s2 = 0ULL, s3 = 0ULL;
#pragma unroll
            for (int e = 0; e < 16; e += 2) {
                ulonglong2 ka = kr[e];
                ulonglong2 kb = kr[e + 1];
                s0 = ffma2(q2[e * 2],     ka.x, s0);
                s1 = ffma2(q2[e * 2 + 1], ka.y, s1);
                s2 = ffma2(q2[e * 2 + 2], kb.x, s2);
                s3 = ffma2(q2[e * 2 + 3], kb.y, s3);
            }
            float2 r2 = up2(fadd2(fadd2(s0, s1), fadd2(s2, s3)));
            sv[u2] = r2.x + r2.y;
        }
        float cm = fmaxf(fmaxf(sv[0], sv[1]), fmaxf(sv[2], sv[3]));
        cm = fmaxf(cm, __shfl_xor_sync(0xffffffffu, cm, 1));
        cm = fmaxf(cm, __shfl_xor_sync(0xffffffffu, cm, 2));
        cm = fmaxf(cm, __shfl_xor_sync(0xffffffffu, cm, 4));
        float m_new = fmaxf(m_run, cm);
        float rsc = __expf(m_run - m_new);
        float psum = 0.f;
#pragma unroll
        for (int u2 = 0; u2 < 4; u2++) {
            float e = __expf(sv[u2] - m_new);
            sc[qi][sub * 4 + u2] = e;
            psum += e;
        }
        psum += __shfl_xor_sync(0xffffffffu, psum, 1);
        psum += __shfl_xor_sync(0xffffffffu, psum, 2);
        psum += __shfl_xor_sync(0xffffffffu, psum, 4);
        l_run = l_run * rsc + psum;
        m_run = m_new;
        __syncwarp();

        u64 rb = dup2(rsc);
#pragma unroll
        for (int d = 0; d < 4; d++) acc2[d] = fmul2(acc2[d], rb);
#pragma unroll 4
        for (int j = 0; j < 32; j++) {
            u64 eb = dup2(sc[qi][j]);
            ulonglong2 v0 = *(const ulonglong2*)&vs[j][sub * 4];
            ulonglong2 v1 = *(const ulonglong2*)&vs[j][sub * 4 + 32];
            acc2[0] = ffma2(eb, v0.x, acc2[0]);
            acc2[1] = ffma2(eb, v0.y, acc2[1]);
            acc2[2] = ffma2(eb, v1.x, acc2[2]);
            acc2[3] = ffma2(eb, v1.y, acc2[3]);
        }
    }

    size_t pidx = (((size_t)seg * BATCH + b) * NH + h) * GLB + qi;
    float2 a0 = up2(acc2[0]), a1 = up2(acc2[1]);
    float2 a2 = up2(acc2[2]), a3 = up2(acc2[3]);
    float* prow = po + pidx * HDIM;
    *(float4*)(prow + sub * 4)      = make_float4(a0.x, a0.y, a1.x, a1.y);
    *(float4*)(prow + 32 + sub * 4) = make_float4(a2.x, a2.y, a3.x, a3.y);
    if (sub == 0) { pm[pidx] = m_run; pl[pidx] = l_run; }
}

__global__ __launch_bounds__(64) void global_merge_kernel(
    const float* __restrict__ po, const float* __restrict__ pm,
    const float* __restrict__ pl, float* __restrict__ out)
{
    int g = blockIdx.x, h = blockIdx.y, b = blockIdx.z;
    int d = threadIdx.x;

    float mv[NSEG];
    float mx = -1e30f;
#pragma unroll
    for (int s = 0; s < NSEG; s++) {
        mv[s] = pm[(((size_t)s * BATCH + b) * NH + h) * GLB + g];
        mx = fmaxf(mx, mv[s]);
    }
    float num = 0.f, den = 0.f;
#pragma unroll
    for (int s = 0; s < NSEG; s++) {
        size_t pidx = (((size_t)s * BATCH + b) * NH + h) * GLB + g;
        float w = __expf(mv[s] - mx);
        num += w * po[pidx * HDIM + d];
        den += w * pl[pidx];
    }
    out[((size_t)(b * S_LEN + g)) * EMB + h * HDIM + d] = num / den;
}

// ---------------- launch ----------------
extern "C" void kernel_launch(void* const* d_in, const int* in_sizes, int n_in,
                              void* d_out, int out_size)
{
    (void)n_in; (void)out_size;
    int base = (in_sizes[2] == EMB * EMB) ? 2 : 3;

    const float* x    = (const float*)d_in[0];
    const int*   mask = (const int*)d_in[1];
    const float* wq   = (const float*)d_in[base + 0];
    const float* bq   = (const float*)d_in[base + 1];
    const float* wk   = (const float*)d_in[base + 2];
    const float* bk   = (const float*)d_in[base + 3];
    const float* wv   = (const float*)d_in[base + 4];
    const float* bv   = (const float*)d_in[base + 5];
    const float* wqg  = (const float*)d_in[base + 6];
    const float* bqg  = (const float*)d_in[base + 7];
    const float* wkg  = (const float*)d_in[base + 8];
    const float* bkg  = (const float*)d_in[base + 9];
    const float* wvg  = (const float*)d_in[base + 10];
    const float* bvg  = (const float*)d_in[base + 11];
    float* out = (float*)d_out;

    float *kg, *vg, *qg, *po, *pm, *pl;
    __half *xh, *xl, *wt, *q1, *q2, *k1, *v1;
    cudaGetSymbolAddress((void**)&kg, g_kg);
    cudaGetSymbolAddress((void**)&vg, g_vg);
    cudaGetSymbolAddress((void**)&qg, g_qg);
    cudaGetSymbolAddress((void**)&xh, g_xh);
    cudaGetSymbolAddress((void**)&xl, g_xl);
    cudaGetSymbolAddress((void**)&wt, g_wt);
    cudaGetSymbolAddress((void**)&q1, g_q1);
    cudaGetSymbolAddress((void**)&q2, g_q2);
    cudaGetSymbolAddress((void**)&k1, g_k1);
    cudaGetSymbolAddress((void**)&v1, g_v1);
    cudaGetSymbolAddress((void**)&po, g_po);
    cudaGetSymbolAddress((void**)&pm, g_pm);
    cudaGetSymbolAddress((void**)&pl, g_pl);

    cudaFuncSetAttribute(mma_gemm6_kernel,
                         cudaFuncAttributeMaxDynamicSharedMemorySize, GSM2);
    cudaFuncSetAttribute(local_attn_mma,
                         cudaFuncAttributeMaxDynamicSharedMemorySize, L_TOTAL);

    convx_kernel<<<(BATCH * S_LEN * EMB) / (256 * 4), 256>>>(x, xh, xl);
    convw_kernel<<<dim3(EMB / 32, EMB / 32, 6), 256>>>(
        wq, wk, wv, wkg, wvg, wqg, wt);
    mma_gemm6_kernel<<<dim3(EMB / 128, BATCH * S_LEN / 128, 6), 256, GSM2>>>(
        xh, xl, wt, bq, bk, bv, bkg, bvg, bqg,
        q1, q2, k1, v1, kg, vg, qg);
    local_attn_mma<<<dim3(S_LEN / QT2, NH, BATCH), 256, L_TOTAL>>>(
        q1, q2, k1, v1, mask, out);
    global_part_kernel<<<dim3(NSEG, NH, BATCH), 256>>>(qg, kg, vg, po, pm, pl);
    global_merge_kernel<<<dim3(GLB, NH, BATCH), 64>>>(po, pm, pl, out);
}

// round 14
// speedup vs baseline: 1.1189x; 1.0243x over previous
#include <cuda_runtime.h>
#include <cuda_fp16.h>
#include <cstdint>

#define S_LEN 4096
#define BATCH 2
#define EMB   768
#define NH    12
#define HDIM  64
#define WIN   256
#define GLB   32
#define QTL   128
#define NSEG  16
#define SEGLEN (S_LEN / NSEG)

typedef unsigned long long u64;

// ---------- packed f32x2 helpers ----------
__device__ __forceinline__ u64 pk2(float x, float y) {
    u64 r; asm("mov.b64 %0, {%1,%2};" : "=l"(r) : "f"(x), "f"(y)); return r;
}
__device__ __forceinline__ u64 dup2(float x) { return pk2(x, x); }
__device__ __forceinline__ float2 up2(u64 v) {
    float2 f; asm("mov.b64 {%0,%1}, %2;" : "=f"(f.x), "=f"(f.y) : "l"(v)); return f;
}
__device__ __forceinline__ u64 ffma2(u64 a, u64 b, u64 c) {
    u64 d; asm("fma.rn.f32x2 %0, %1, %2, %3;" : "=l"(d) : "l"(a), "l"(b), "l"(c)); return d;
}
__device__ __forceinline__ u64 fadd2(u64 a, u64 b) {
    u64 d; asm("add.rn.f32x2 %0, %1, %2;" : "=l"(d) : "l"(a), "l"(b)); return d;
}
__device__ __forceinline__ u64 fmul2(u64 a, u64 b) {
    u64 d; asm("mul.rn.f32x2 %0, %1, %2;" : "=l"(d) : "l"(a), "l"(b)); return d;
}

__device__ __forceinline__ uint32_t smem_to_u32(const void* p) {
    uint32_t a;
    asm("{ .reg .u64 t; cvta.to.shared.u64 t, %1; cvt.u32.u64 %0, t; }" : "=r"(a) : "l"(p));
    return a;
}
#define SW128(o) ((o) ^ (((o) >> 3) & 0x70))

#define CP16(dst, src) \
    asm volatile("cp.async.cg.shared.global [%0], [%1], 16;" \
                 :: "r"(dst), "l"(src) : "memory")
#define CPZ16(dst, src, pred) do { \
    int _sz = (pred) ? 16 : 0; \
    asm volatile("cp.async.cg.shared.global [%0], [%1], 16, %2;" \
                 :: "r"(dst), "l"(src), "r"(_sz) : "memory"); } while (0)
#define CPZ4(dst, src, pred) do { \
    int _sz = (pred) ? 4 : 0; \
    asm volatile("cp.async.ca.shared.global [%0], [%1], 4, %2;" \
                 :: "r"(dst), "l"(src), "r"(_sz) : "memory"); } while (0)
#define CP_COMMIT() asm volatile("cp.async.commit_group;" ::: "memory")
#define CP_WAIT1()  asm volatile("cp.async.wait_group 1;" ::: "memory")

__device__ __forceinline__ void ldsm_x4(uint32_t* r, uint32_t addr) {
    asm volatile("ldmatrix.sync.aligned.m8n8.x4.shared.b16 {%0,%1,%2,%3}, [%4];"
                 : "=r"(r[0]), "=r"(r[1]), "=r"(r[2]), "=r"(r[3]) : "r"(addr));
}
__device__ __forceinline__ void ldsm_x4t(uint32_t* r, uint32_t addr) {
    asm volatile("ldmatrix.sync.aligned.m8n8.x4.trans.shared.b16 {%0,%1,%2,%3}, [%4];"
                 : "=r"(r[0]), "=r"(r[1]), "=r"(r[2]), "=r"(r[3]) : "r"(addr));
}
// fp16 mma, fp32 accum
__device__ __forceinline__ void mma16816(float* c, const uint32_t* a,
                                         uint32_t b0, uint32_t b1) {
    asm volatile(
        "mma.sync.aligned.m16n8k16.row.col.f32.f16.f16.f32 "
        "{%0,%1,%2,%3}, {%4,%5,%6,%7}, {%8,%9}, {%0,%1,%2,%3};"
        : "+f"(c[0]), "+f"(c[1]), "+f"(c[2]), "+f"(c[3])
        : "r"(a[0]), "r"(a[1]), "r"(a[2]), "r"(a[3]), "r"(b0), "r"(b1));
}
__device__ __forceinline__ uint32_t packh2(float a, float b) {
    __half2 h; h.x = __float2half(a); h.y = __float2half(b);
    return *(uint32_t*)&h;
}

// -------- scratch --------
__device__ float g_kg[BATCH * S_LEN * EMB];
__device__ float g_vg[BATCH * S_LEN * EMB];
__device__ float g_qg[BATCH * GLB * EMB];
__device__ __half g_xh[BATCH * S_LEN * EMB];
__device__ __half g_xl[BATCH * S_LEN * EMB];
__device__ __half g_wt[6 * EMB * EMB];
__device__ __half g_q1[BATCH * S_LEN * EMB];
__device__ __half g_q2[BATCH * S_LEN * EMB];
__device__ __half g_k1[BATCH * S_LEN * EMB];
__device__ __half g_v1[BATCH * S_LEN * EMB];
__device__ float g_po[NSEG * BATCH * NH * GLB * HDIM];
__device__ float g_pm[NSEG * BATCH * NH * GLB];
__device__ float g_pl[NSEG * BATCH * NH * GLB];

// ---------------- prep: x -> fp16 hi/lo ----------------
__global__ __launch_bounds__(256) void convx_kernel(
    const float* __restrict__ x, __half* __restrict__ xh,
    __half* __restrict__ xl)
{
    int i = (blockIdx.x * 256 + threadIdx.x) * 4;
    float4 a = *(const float4*)(x + i);
    __half h[4], l[4];
    float av[4] = {a.x, a.y, a.z, a.w};
#pragma unroll
    for (int j = 0; j < 4; j++) {
        h[j] = __float2half(av[j]);
        l[j] = __float2half(av[j] - __half2float(h[j]));
    }
    *(uint2*)(xh + i) = *(const uint2*)h;
    *(uint2*)(xl + i) = *(const uint2*)l;
}

// ---------------- prep: W -> W^T single fp16 (6 weights) ----------------
__global__ __launch_bounds__(256) void convw_kernel(
    const float* __restrict__ w0, const float* __restrict__ w1,
    const float* __restrict__ w2, const float* __restrict__ w3,
    const float* __restrict__ w4, const float* __restrict__ w5,
    __half* __restrict__ wt)
{
    __shared__ float tile[32][33];
    int z = blockIdx.z;
    const float* W = (z == 0) ? w0 : (z == 1) ? w1 : (z == 2) ? w2 :
                     (z == 3) ? w3 : (z == 4) ? w4 : w5;
    int kb = blockIdx.y * 32, nb = blockIdx.x * 32;
    int tx = threadIdx.x & 31, ty = threadIdx.x >> 5;
    for (int i = ty; i < 32; i += 8)
        tile[i][tx] = W[(size_t)(kb + i) * EMB + nb + tx];
    __syncthreads();
    for (int j = ty; j < 32; j += 8) {
        size_t o = (size_t)z * EMB * EMB + (size_t)(nb + j) * EMB + kb + tx;
        wt[o] = __float2half(tile[tx][j]);
    }
}

// ------- mma.sync GEMM: 128x128 CTA, 256 thr, warp 32x64, k-chunk 64 -------
#define GST  49152
#define GSM2 (2 * GST)

__global__ __launch_bounds__(256, 2) void mma_gemm6_kernel(
    const __half* __restrict__ xh, const __half* __restrict__ xl,
    const __half* __restrict__ wt,
    const float* __restrict__ bq, const float* __restrict__ bk,
    const float* __restrict__ bv, const float* __restrict__ bkg,
    const float* __restrict__ bvg, const float* __restrict__ bqg,
    __half* q1, __half* q2, __half* k1, __half* v1,
    float* kg, float* vg, float* qg)
{
    extern __shared__ char dsm[];
    int z = blockIdx.z;
    if (z == 5 && blockIdx.y > 0) return;
    int t = threadIdx.x, wid = t >> 5, lane = t & 31;
    int m0 = blockIdx.y * 128, n0 = blockIdx.x * 128;
    int wm = wid & 3, wn = wid >> 2;

    const float* bias;
    switch (z) {
        case 0:  bias = bq;  break;
        case 1:  bias = bk;  break;
        case 2:  bias = bv;  break;
        case 3:  bias = bkg; break;
        case 4:  bias = bvg; break;
        default: bias = bqg; break;
    }
    float scale = (z == 0 || z == 5) ? 0.125f : 1.0f;
    const __half* Bw = wt + (size_t)z * EMB * EMB;

    uint32_t sb = smem_to_u32(dsm);

    float acc[2][8][4];
#pragma unroll
    for (int mi = 0; mi < 2; mi++)
#pragma unroll
        for (int ni = 0; ni < 8; ni++)
#pragma unroll
            for (int c = 0; c < 4; c++) acc[mi][ni][c] = 0.f;

    uint32_t a_off[2], b_off[4];
#pragma unroll
    for (int mi = 0; mi < 2; mi++) {
        int row = wm * 32 + mi * 16 + (lane & 15);
        a_off[mi] = (uint32_t)(row * 128) + ((lane >> 4) << 4);
    }
#pragma unroll
    for (int bi = 0; bi < 4; bi++) {
        int row = wn * 64 + bi * 16 + (lane & 15);
        b_off[bi] = (uint32_t)(row * 128) + ((lane >> 4) << 4);
    }

#define LOAD_STAGE(chunk, s) do {                                            \
        int k0 = (chunk) * 64;                                               \
        uint32_t base = sb + (s) * GST;                                      \
        _Pragma("unroll")                                                    \
        for (int i = 0; i < 4; i++) {                                        \
            int idx = t + i * 256;                                           \
            int r = idx >> 3, u = idx & 7;                                   \
            uint32_t sw = SW128((uint32_t)(r * 128 + u * 16));               \
            size_t arow;                                                     \
            if (z == 5) { int q2r = r & 63;                                  \
                arow = (size_t)((q2r >> 5) * S_LEN + (q2r & 31)); }          \
            else arow = (size_t)(m0 + r);                                    \
            CP16(base + sw,         xh + arow * EMB + k0 + u * 8);           \
            CP16(base + 16384 + sw, xl + arow * EMB + k0 + u * 8);           \
            CP16(base + 32768 + sw, Bw + (size_t)(n0 + r) * EMB + k0 + u * 8); \
        }                                                                    \
    } while (0)

    LOAD_STAGE(0, 0);
    CP_COMMIT();

    for (int c = 0; c < 12; c++) {
        if (c < 11) LOAD_STAGE(c + 1, (c + 1) & 1);
        CP_COMMIT();
        CP_WAIT1();
        __syncthreads();
        uint32_t base = sb + (c & 1) * GST;
        uint32_t uAh = base, uAl = base + 16384;
        uint32_t uB  = base + 32768;
#pragma unroll
        for (int ks = 0; ks < 4; ks++) {
            uint32_t kb = (uint32_t)(ks * 32);
            uint32_t ah[2][4], al[2][4];
#pragma unroll
            for (int mi = 0; mi < 2; mi++) {
                uint32_t sw = SW128(a_off[mi] + kb);
                ldsm_x4(ah[mi], uAh + sw);
                ldsm_x4(al[mi], uAl + sw);
            }
#pragma unroll
            for (int bi = 0; bi < 4; bi++) {
                uint32_t bw[4];
                ldsm_x4(bw, uB + SW128(b_off[bi] + kb));
#pragma unroll
                for (int sel = 0; sel < 2; sel++) {
                    int ni = bi * 2 + sel;
#pragma unroll
                    for (int mi = 0; mi < 2; mi++) {
                        mma16816(acc[mi][ni], ah[mi], bw[sel], bw[sel + 2]);
                        mma16816(acc[mi][ni], al[mi], bw[sel], bw[sel + 2]);
                    }
                }
            }
        }
        __syncthreads();
    }
#undef LOAD_STAGE

    int r = lane >> 2, cp = (lane & 3) * 2;
    if (z == 0) {
#pragma unroll
        for (int mi = 0; mi < 2; mi++) {
            int mbase = m0 + wm * 32 + mi * 16;
#pragma unroll
            for (int ni = 0; ni < 8; ni++) {
                int nbase = n0 + wn * 64 + ni * 8 + cp;
                float b0 = bias[nbase], b1 = bias[nbase + 1];
#pragma unroll
                for (int hr = 0; hr < 2; hr++) {
                    int row = mbase + r + hr * 8;
                    float v0 = (acc[mi][ni][hr * 2 + 0] + b0) * scale;
                    float v1 = (acc[mi][ni][hr * 2 + 1] + b1) * scale;
                    __half h0 = __float2half(v0);
                    __half h1 = __float2half(v1);
                    __half l0 = __float2half(v0 - __half2float(h0));
                    __half l1 = __float2half(v1 - __half2float(h1));
                    __half ph[2] = {h0, h1}, pl[2] = {l0, l1};
                    *(uint32_t*)(q1 + (size_t)row * EMB + nbase) = *(uint32_t*)ph;
                    *(uint32_t*)(q2 + (size_t)row * EMB + nbase) = *(uint32_t*)pl;
                }
            }
        }
    } else if (z == 1 || z == 2) {
        __half* Y = (z == 1) ? k1 : v1;
#pragma unroll
        for (int mi = 0; mi < 2; mi++) {
            int mbase = m0 + wm * 32 + mi * 16;
#pragma unroll
            for (int ni = 0; ni < 8; ni++) {
                int nbase = n0 + wn * 64 + ni * 8 + cp;
                float b0 = bias[nbase], b1 = bias[nbase + 1];
#pragma unroll
                for (int hr = 0; hr < 2; hr++) {
                    int row = mbase + r + hr * 8;
                    __half ph[2];
                    ph[0] = __float2half(acc[mi][ni][hr * 2 + 0] + b0);
                    ph[1] = __float2half(acc[mi][ni][hr * 2 + 1] + b1);
                    *(uint32_t*)(Y + (size_t)row * EMB + nbase) = *(uint32_t*)ph;
                }
            }
        }
    } else {
        float* Y = (z == 3) ? kg : (z == 4) ? vg : qg;
#pragma unroll
        for (int mi = 0; mi < 2; mi++) {
            int mbase = m0 + wm * 32 + mi * 16;
#pragma unroll
            for (int ni = 0; ni < 8; ni++) {
                int nbase = n0 + wn * 64 + ni * 8 + cp;
                float b0 = bias[nbase], b1 = bias[nbase + 1];
#pragma unroll
                for (int hr = 0; hr < 2; hr++) {
                    int row = mbase + r + hr * 8;
                    if (z == 5 && row >= BATCH * GLB) continue;
                    float2 o;
                    o.x = (acc[mi][ni][hr * 2 + 0] + b0) * scale;
                    o.y = (acc[mi][ni][hr * 2 + 1] + b1) * scale;
                    *(float2*)(Y + (size_t)row * EMB + nbase) = o;
                }
            }
        }
    }
}

// ------- Local attention: flash-v2, Q-tile 128, register softmax ----------
// Warp owns m16 x all 32 chunk keys; softmax via quad shuffles; P stays in
// registers (C-frag -> A-frag identity); 2 barriers/chunk.
#define LL_QH 0
#define LL_QL 16384
#define LL_K  32768           // + s*4096
#define LL_V  40960           // + s*4096
#define LL_MS 49152           // int[2][32]
#define LL_TOTAL 49408

__global__ __launch_bounds__(256, 2) void local_attn_mma(
    const __half* __restrict__ q1, const __half* __restrict__ q2,
    const __half* __restrict__ k1, const __half* __restrict__ v1,
    const int* __restrict__ mask, float* __restrict__ out)
{
    extern __shared__ char lsm[];
    uint32_t sbase = smem_to_u32(lsm);
    int* msk = (int*)(lsm + LL_MS);

    int b = blockIdx.z, h = blockIdx.y, i0 = blockIdx.x * QTL;
    int t = threadIdx.x, wm = t >> 5, lane = t & 31;
    int r = lane >> 2, cq = lane & 3;

    // load Q tile (128 rows x 64 halves, hi/lo)
#pragma unroll
    for (int i = 0; i < 4; i++) {
        int idx = t + i * 256;
        int row = idx >> 3, u = idx & 7;
        size_t g = ((size_t)(b * S_LEN + i0 + row)) * EMB + h * HDIM + u * 8;
        uint32_t sw = SW128((uint32_t)(row * 128 + u * 16));
        *(uint4*)(lsm + LL_QH + sw) = *(const uint4*)(q1 + g);
        *(uint4*)(lsm + LL_QL + sw) = *(const uint4*)(q2 + g);
    }

    int lo = i0 - WIN; if (lo < 0) lo = 0;
    int hi = i0 + QTL - 1 + WIN; if (hi > S_LEN - 1) hi = S_LEN - 1;
    int wstart = lo & ~31;
    int nwin = (hi - wstart) / 32 + 1;

#define LOAD_KV(kstart_, s_) do {                                            \
        int r_ = t >> 3, u_ = t & 7;                                         \
        int p_ = (kstart_) + r_;                                             \
        int ok_ = p_ < S_LEN;                                                \
        int pc_ = ok_ ? p_ : (S_LEN - 1);                                    \
        size_t g_ = ((size_t)(b * S_LEN + pc_)) * EMB + h * HDIM + u_ * 8;   \
        uint32_t sw_ = SW128((uint32_t)(r_ * 128 + u_ * 16));                \
        CPZ16(sbase + LL_K + (s_) * 4096 + sw_, k1 + g_, ok_);               \
        CPZ16(sbase + LL_V + (s_) * 4096 + sw_, v1 + g_, ok_);               \
        if (t < 32) {                                                        \
            int p2_ = (kstart_) + t;                                         \
            int ok2_ = p2_ < S_LEN;                                          \
            const int* ms_ = mask + b * S_LEN + (ok2_ ? p2_ : (S_LEN - 1));  \
            CPZ4(sbase + LL_MS + (s_) * 128 + t * 4, ms_, ok2_);             \
        }                                                                    \
    } while (0)

    LOAD_KV(0, 0);
    CP_COMMIT();

    uint32_t aoff = (uint32_t)((wm * 16 + (lane & 15)) * 128 + ((lane >> 4) << 4));
    uint32_t koff0 = (uint32_t)(((lane & 15)) * 128 + ((lane >> 4) << 4));
    uint32_t koff1 = (uint32_t)((16 + (lane & 15)) * 128 + ((lane >> 4) << 4));
    int vtile = lane >> 3, vrow = lane & 7;
    uint32_t vb = (uint32_t)(((vtile & 1) * 8 + vrow) * 128 + ((vtile >> 1) << 4));

    __syncthreads();   // Q tile visible
    uint32_t qfh[4][4], qfl[4][4];
#pragma unroll
    for (int ks = 0; ks < 4; ks++) {
        uint32_t kb = (uint32_t)(ks * 32);
        ldsm_x4(qfh[ks], sbase + LL_QH + SW128(aoff + kb));
        ldsm_x4(qfl[ks], sbase + LL_QL + SW128(aoff + kb));
    }

    float oacc[8][4];
#pragma unroll
    for (int dg = 0; dg < 8; dg++)
#pragma unroll
        for (int c = 0; c < 4; c++) oacc[dg][c] = 0.f;
    float m0 = -1e30f, m1 = -1e30f, l0 = 0.f, l1 = 0.f;

    int iq0 = i0 + wm * 16 + r;

    for (int ci = -1; ci < nwin; ci++) {
        bool gl = (ci < 0);
        int kstart = gl ? 0 : wstart + ci * 32;
        int s = (ci + 1) & 1;

        __syncthreads();   // all warps done with stage s^1 (prev chunk)
        if (ci + 1 < nwin) LOAD_KV(wstart + (ci + 1) * 32, s ^ 1);
        CP_COMMIT();
        CP_WAIT1();
        __syncthreads();

        uint32_t uK = sbase + LL_K + s * 4096;
        uint32_t uV = sbase + LL_V + s * 4096;
        const int* mskS = msk + s * 32;

        // QK: m16 x n32, K=64, 2-term. f[nt] = keys nt*8..nt*8+7
        float f[4][4];
#pragma unroll
        for (int nt = 0; nt < 4; nt++)
#pragma unroll
            for (int c = 0; c < 4; c++) f[nt][c] = 0.f;
#pragma unroll
        for (int ks = 0; ks < 4; ks++) {
            uint32_t kb = (uint32_t)(ks * 32);
            uint32_t bw0[4], bw1[4];
            ldsm_x4(bw0, uK + SW128(koff0 + kb));
            ldsm_x4(bw1, uK + SW128(koff1 + kb));
            mma16816(f[0], qfh[ks], bw0[0], bw0[2]);
            mma16816(f[0], qfl[ks], bw0[0], bw0[2]);
            mma16816(f[1], qfh[ks], bw0[1], bw0[3]);
            mma16816(f[1], qfl[ks], bw0[1], bw0[3]);
            mma16816(f[2], qfh[ks], bw1[0], bw1[2]);
            mma16816(f[2], qfl[ks], bw1[0], bw1[2]);
            mma16816(f[3], qfh[ks], bw1[1], bw1[3]);
            mma16816(f[3], qfl[ks], bw1[1], bw1[3]);
        }

        // mask / validity (band chunks only)
        if (!gl) {
#pragma unroll
            for (int nt = 0; nt < 4; nt++)
#pragma unroll
                for (int cc = 0; cc < 2; cc++) {
                    int j = nt * 8 + cq * 2 + cc;
                    int p = kstart + j;
                    float pen = mskS[j] ? -10000.f : 0.f;
                    bool okp = (p < S_LEN);
                    bool v0 = okp && (p >= iq0 - WIN) && (p <= iq0 + WIN);
                    bool v1v = okp && (p >= iq0 + 8 - WIN) && (p <= iq0 + 8 + WIN);
                    f[nt][cc]     = v0  ? f[nt][cc] + pen     : -1e30f;
                    f[nt][2 + cc] = v1v ? f[nt][2 + cc] + pen : -1e30f;
                }
        }

        // row-wise online softmax (quad shuffles)
        float mx0 = fmaxf(fmaxf(f[0][0], f[0][1]), fmaxf(f[1][0], f[1][1]));
        mx0 = fmaxf(mx0, fmaxf(fmaxf(f[2][0], f[2][1]), fmaxf(f[3][0], f[3][1])));
        float mx1 = fmaxf(fmaxf(f[0][2], f[0][3]), fmaxf(f[1][2], f[1][3]));
        mx1 = fmaxf(mx1, fmaxf(fmaxf(f[2][2], f[2][3]), fmaxf(f[3][2], f[3][3])));
        mx0 = fmaxf(mx0, __shfl_xor_sync(0xffffffffu, mx0, 1));
        mx0 = fmaxf(mx0, __shfl_xor_sync(0xffffffffu, mx0, 2));
        mx1 = fmaxf(mx1, __shfl_xor_sync(0xffffffffu, mx1, 1));
        mx1 = fmaxf(mx1, __shfl_xor_sync(0xffffffffu, mx1, 2));
        float mn0 = fmaxf(m0, mx0), mn1 = fmaxf(m1, mx1);
        float rsc0 = __expf(m0 - mn0), rsc1 = __expf(m1 - mn1);
        float s0 = 0.f, s1 = 0.f;
#pragma unroll
        for (int nt = 0; nt < 4; nt++) {
#pragma unroll
            for (int cc = 0; cc < 2; cc++) {
                float e0 = __expf(f[nt][cc] - mn0);
                float e1 = __expf(f[nt][2 + cc] - mn1);
                f[nt][cc] = e0; f[nt][2 + cc] = e1;
                s0 += e0; s1 += e1;
            }
        }
        s0 += __shfl_xor_sync(0xffffffffu, s0, 1);
        s0 += __shfl_xor_sync(0xffffffffu, s0, 2);
        s1 += __shfl_xor_sync(0xffffffffu, s1, 1);
        s1 += __shfl_xor_sync(0xffffffffu, s1, 2);
        l0 = l0 * rsc0 + s0; m0 = mn0;
        l1 = l1 * rsc1 + s1; m1 = mn1;

        // pack P (2-term) into A-fragments: ks 0 -> tiles 0,1; ks 1 -> 2,3
        uint32_t aPh[2][4], aPl[2][4];
#pragma unroll
        for (int ks = 0; ks < 2; ks++) {
            int t0 = 2 * ks, t1 = 2 * ks + 1;
            float e00 = f[t0][0], e01 = f[t0][1], e02 = f[t0][2], e03 = f[t0][3];
            float e10 = f[t1][0], e11 = f[t1][1], e12 = f[t1][2], e13 = f[t1][3];
            aPh[ks][0] = packh2(e00, e01);
            aPh[ks][1] = packh2(e02, e03);
            aPh[ks][2] = packh2(e10, e11);
            aPh[ks][3] = packh2(e12, e13);
            __half2 h0 = *(__half2*)&aPh[ks][0];
            __half2 h1 = *(__half2*)&aPh[ks][1];
            __half2 h2 = *(__half2*)&aPh[ks][2];
            __half2 h3 = *(__half2*)&aPh[ks][3];
            aPl[ks][0] = packh2(e00 - __half2float(h0.x), e01 - __half2float(h0.y));
            aPl[ks][1] = packh2(e02 - __half2float(h1.x), e03 - __half2float(h1.y));
            aPl[ks][2] = packh2(e10 - __half2float(h2.x), e11 - __half2float(h2.y));
            aPl[ks][3] = packh2(e12 - __half2float(h3.x), e13 - __half2float(h3.y));
        }

        // rescale accumulators
#pragma unroll
        for (int dg = 0; dg < 8; dg++) {
            oacc[dg][0] *= rsc0; oacc[dg][1] *= rsc0;
            oacc[dg][2] *= rsc1; oacc[dg][3] *= rsc1;
        }

        // PV: m16 x d64, k=32 (2 ksteps), 2-term
#pragma unroll
        for (int ks = 0; ks < 2; ks++) {
#pragma unroll
            for (int dgp = 0; dgp < 4; dgp++) {
                uint32_t bv[4];
                ldsm_x4t(bv, uV + SW128(vb + (uint32_t)(dgp * 32) +
                                        (uint32_t)(ks * 2048)));
                mma16816(oacc[dgp * 2],     aPh[ks], bv[0], bv[1]);
                mma16816(oacc[dgp * 2],     aPl[ks], bv[0], bv[1]);
                mma16816(oacc[dgp * 2 + 1], aPh[ks], bv[2], bv[3]);
                mma16816(oacc[dgp * 2 + 1], aPl[ks], bv[2], bv[3]);
            }
        }
    }
#undef LOAD_KV

    // epilogue: normalize + store (no smem needed)
    float inv0 = 1.f / l0, inv1 = 1.f / l1;
    int row0 = i0 + wm * 16 + r;
#pragma unroll
    for (int dg = 0; dg < 8; dg++) {
        int c = dg * 8 + cq * 2;
        size_t o0 = ((size_t)(b * S_LEN + row0)) * EMB + h * HDIM + c;
        size_t o1 = ((size_t)(b * S_LEN + row0 + 8)) * EMB + h * HDIM + c;
        float2 v0; v0.x = oacc[dg][0] * inv0; v0.y = oacc[dg][1] * inv0;
        float2 v1; v1.x = oacc[dg][2] * inv1; v1.y = oacc[dg][3] * inv1;
        *(float2*)(out + o0) = v0;
        *(float2*)(out + o1) = v1;
    }
}

// ---------------- Global rows: split-K partial flash ----------------
__global__ __launch_bounds__(256, 2) void global_part_kernel(
    const float* __restrict__ qg, const float* __restrict__ kg,
    const float* __restrict__ vg,
    float* __restrict__ po, float* __restrict__ pm, float* __restrict__ pl)
{
    __shared__ float ks[32][68];
    __shared__ float vs[32][68];
    __shared__ float sc[32][36];

    int seg = blockIdx.x, h = blockIdx.y, b = blockIdx.z;
    int t = threadIdx.x;
    int qi = t >> 3, sub = t & 7;

    u64 q2[32];
    {
        const ulonglong2* qrow = (const ulonglong2*)
            (qg + ((size_t)(b * GLB + qi)) * EMB + h * HDIM);
#pragma unroll
        for (int e = 0; e < 16; e++) {
            ulonglong2 t2 = qrow[e];
            q2[e * 2] = t2.x; q2[e * 2 + 1] = t2.y;
        }
    }
    u64 acc2[4] = {0ULL, 0ULL, 0ULL, 0ULL};
    float m_run = -1e30f, l_run = 0.f;

    for (int c = 0; c < SEGLEN / 32; c++) {
        int kstart = seg * SEGLEN + c * 32;
        __syncthreads();
        for (int u = t; u < 32 * 16; u += 256) {
            int r = u >> 4, cc = (u & 15) << 2;
            size_t off = ((size_t)(b * S_LEN + kstart + r)) * EMB + h * HDIM + cc;
            *(float4*)&ks[r][cc] = *(const float4*)(kg + off);
            *(float4*)&vs[r][cc] = *(const float4*)(vg + off);
        }
        __syncthreads();

        float sv[4];
#pragma unroll
        for (int u2 = 0; u2 < 4; u2++) {
            int j = sub * 4 + u2;
            const ulonglong2* kr = (const ulonglong2*)&ks[j][0];
            u64 s0 = 0ULL, s1 = 0ULL, s2 = 0ULL, s3 = 0ULL;
#pragma unroll
            for (int e = 0; e < 16; e += 2) {
                ulonglong2 ka = kr[e];
                ulonglong2 kb = kr[e + 1];
                s0 = ffma2(q2[e * 2],     ka.x, s0);
                s1 = ffma2(q2[e * 2 + 1], ka.y, s1);
                s2 = ffma2(q2[e * 2 + 2], kb.x, s2);
                s3 = ffma2(q2[e * 2 + 3], kb.y, s3);
            }
            float2 r2 = up2(fadd2(fadd2(s0, s1), fadd2(s2, s3)));
            sv[u2] = r2.x + r2.y;
        }
        float cm = fmaxf(fmaxf(sv[0], sv[1]), fmaxf(sv[2], sv[3]));
        cm = fmaxf(cm, __shfl_xor_sync(0xffffffffu, cm, 1));
        cm = fmaxf(cm, __shfl_xor_sync(0xffffffffu, cm, 2));
        cm = fmaxf(cm, __shfl_xor_sync(0xffffffffu, cm, 4));
        float m_new = fmaxf(m_run, cm);
        float rsc = __expf(m_run - m_new);
        float psum = 0.f;
#pragma unroll
        for (int u2 = 0; u2 < 4; u2++) {
            float e = __expf(sv[u2] - m_new);
            sc[qi][sub * 4 + u2] = e;
            psum += e;
        }
        psum += __shfl_xor_sync(0xffffffffu, psum, 1);
        psum += __shfl_xor_sync(0xffffffffu, psum, 2);
        psum += __shfl_xor_sync(0xffffffffu, psum, 4);
        l_run = l_run * rsc + psum;
        m_run = m_new;
        __syncwarp();

        u64 rb = dup2(rsc);
#pragma unroll
        for (int d = 0; d < 4; d++) acc2[d] = fmul2(acc2[d], rb);
#pragma unroll 4
        for (int j = 0; j < 32; j++) {
            u64 eb = dup2(sc[qi][j]);
            ulonglong2 v0 = *(const ulonglong2*)&vs[j][sub * 4];
            ulonglong2 v1 = *(const ulonglong2*)&vs[j][sub * 4 + 32];
            acc2[0] = ffma2(eb, v0.x, acc2[0]);
            acc2[1] = ffma2(eb, v0.y, acc2[1]);
            acc2[2] = ffma2(eb, v1.x, acc2[2]);
            acc2[3] = ffma2(eb, v1.y, acc2[3]);
        }
    }

    size_t pidx = (((size_t)seg * BATCH + b) * NH + h) * GLB + qi;
    float2 a0 = up2(acc2[0]), a1 = up2(acc2[1]);
    float2 a2 = up2(acc2[2]), a3 = up2(acc2[3]);
    float* prow = po + pidx * HDIM;
    *(float4*)(prow + sub * 4)      = make_float4(a0.x, a0.y, a1.x, a1.y);
    *(float4*)(prow + 32 + sub * 4) = make_float4(a2.x, a2.y, a3.x, a3.y);
    if (sub == 0) { pm[pidx] = m_run; pl[pidx] = l_run; }
}

__global__ __launch_bounds__(64) void global_merge_kernel(
    const float* __restrict__ po, const float* __restrict__ pm,
    const float* __restrict__ pl, float* __restrict__ out)
{
    int g = blockIdx.x, h = blockIdx.y, b = blockIdx.z;
    int d = threadIdx.x;

    float mv[NSEG];
    float mx = -1e30f;
#pragma unroll
    for (int s = 0; s < NSEG; s++) {
        mv[s] = pm[(((size_t)s * BATCH + b) * NH + h) * GLB + g];
        mx = fmaxf(mx, mv[s]);
    }
    float num = 0.f, den = 0.f;
#pragma unroll
    for (int s = 0; s < NSEG; s++) {
        size_t pidx = (((size_t)s * BATCH + b) * NH + h) * GLB + g;
        float w = __expf(mv[s] - mx);
        num += w * po[pidx * HDIM + d];
        den += w * pl[pidx];
    }
    out[((size_t)(b * S_LEN + g)) * EMB + h * HDIM + d] = num / den;
}

// ---------------- launch ----------------
extern "C" void kernel_launch(void* const* d_in, const int* in_sizes, int n_in,
                              void* d_out, int out_size)
{
    (void)n_in; (void)out_size;
    int base = (in_sizes[2] == EMB * EMB) ? 2 : 3;

    const float* x    = (const float*)d_in[0];
    const int*   mask = (const int*)d_in[1];
    const float* wq   = (const float*)d_in[base + 0];
    const float* bq   = (const float*)d_in[base + 1];
    const float* wk   = (const float*)d_in[base + 2];
    const float* bk   = (const float*)d_in[base + 3];
    const float* wv   = (const float*)d_in[base + 4];
    const float* bv   = (const float*)d_in[base + 5];
    const float* wqg  = (const float*)d_in[base + 6];
    const float* bqg  = (const float*)d_in[base + 7];
    const float* wkg  = (const float*)d_in[base + 8];
    const float* bkg  = (const float*)d_in[base + 9];
    const float* wvg  = (const float*)d_in[base + 10];
    const float* bvg  = (const float*)d_in[base + 11];
    float* out = (float*)d_out;

    float *kg, *vg, *qg, *po, *pm, *pl;
    __half *xh, *xl, *wt, *q1, *q2, *k1, *v1;
    cudaGetSymbolAddress((void**)&kg, g_kg);
    cudaGetSymbolAddress((void**)&vg, g_vg);
    cudaGetSymbolAddress((void**)&qg, g_qg);
    cudaGetSymbolAddress((void**)&xh, g_xh);
    cudaGetSymbolAddress((void**)&xl, g_xl);
    cudaGetSymbolAddress((void**)&wt, g_wt);
    cudaGetSymbolAddress((void**)&q1, g_q1);
    cudaGetSymbolAddress((void**)&q2, g_q2);
    cudaGetSymbolAddress((void**)&k1, g_k1);
    cudaGetSymbolAddress((void**)&v1, g_v1);
    cudaGetSymbolAddress((void**)&po, g_po);
    cudaGetSymbolAddress((void**)&pm, g_pm);
    cudaGetSymbolAddress((void**)&pl, g_pl);

    cudaFuncSetAttribute(mma_gemm6_kernel,
                         cudaFuncAttributeMaxDynamicSharedMemorySize, GSM2);
    cudaFuncSetAttribute(local_attn_mma,
                         cudaFuncAttributeMaxDynamicSharedMemorySize, LL_TOTAL);

    convx_kernel<<<(BATCH * S_LEN * EMB) / (256 * 4), 256>>>(x, xh, xl);
    convw_kernel<<<dim3(EMB / 32, EMB / 32, 6), 256>>>(
        wq, wk, wv, wkg, wvg, wqg, wt);
    mma_gemm6_kernel<<<dim3(EMB / 128, BATCH * S_LEN / 128, 6), 256, GSM2>>>(
        xh, xl, wt, bq, bk, bv, bkg, bvg, bqg,
        q1, q2, k1, v1, kg, vg, qg);
    local_attn_mma<<<dim3(S_LEN / QTL, NH, BATCH), 256, LL_TOTAL>>>(
        q1, q2, k1, v1, mask, out);
    global_part_kernel<<<dim3(NSEG, NH, BATCH), 256>>>(qg, kg, vg, po, pm, pl);
    global_merge_kernel<<<dim3(GLB, NH, BATCH), 64>>>(po, pm, pl, out);
}

// round 15
// speedup vs baseline: 1.1840x; 1.0581x over previous
#include <cuda_runtime.h>
#include <cuda_fp16.h>
#include <cstdint>

#define S_LEN 4096
#define BATCH 2
#define EMB   768
#define NH    12
#define HDIM  64
#define WIN   256
#define GLB   32
#define QTL   128
#define NSEG  16
#define SEGLEN (S_LEN / NSEG)

typedef unsigned long long u64;

// ---------- packed f32x2 helpers ----------
__device__ __forceinline__ u64 pk2(float x, float y) {
    u64 r; asm("mov.b64 %0, {%1,%2};" : "=l"(r) : "f"(x), "f"(y)); return r;
}
__device__ __forceinline__ u64 dup2(float x) { return pk2(x, x); }
__device__ __forceinline__ float2 up2(u64 v) {
    float2 f; asm("mov.b64 {%0,%1}, %2;" : "=f"(f.x), "=f"(f.y) : "l"(v)); return f;
}
__device__ __forceinline__ u64 ffma2(u64 a, u64 b, u64 c) {
    u64 d; asm("fma.rn.f32x2 %0, %1, %2, %3;" : "=l"(d) : "l"(a), "l"(b), "l"(c)); return d;
}
__device__ __forceinline__ u64 fadd2(u64 a, u64 b) {
    u64 d; asm("add.rn.f32x2 %0, %1, %2;" : "=l"(d) : "l"(a), "l"(b)); return d;
}
__device__ __forceinline__ u64 fmul2(u64 a, u64 b) {
    u64 d; asm("mul.rn.f32x2 %0, %1, %2;" : "=l"(d) : "l"(a), "l"(b)); return d;
}

__device__ __forceinline__ uint32_t smem_to_u32(const void* p) {
    uint32_t a;
    asm("{ .reg .u64 t; cvta.to.shared.u64 t, %1; cvt.u32.u64 %0, t; }" : "=r"(a) : "l"(p));
    return a;
}
#define SW128(o) ((o) ^ (((o) >> 3) & 0x70))

#define CP16(dst, src) \
    asm volatile("cp.async.cg.shared.global [%0], [%1], 16;" \
                 :: "r"(dst), "l"(src) : "memory")
#define CPZ16(dst, src, pred) do { \
    int _sz = (pred) ? 16 : 0; \
    asm volatile("cp.async.cg.shared.global [%0], [%1], 16, %2;" \
                 :: "r"(dst), "l"(src), "r"(_sz) : "memory"); } while (0)
#define CPZ4(dst, src, pred) do { \
    int _sz = (pred) ? 4 : 0; \
    asm volatile("cp.async.ca.shared.global [%0], [%1], 4, %2;" \
                 :: "r"(dst), "l"(src), "r"(_sz) : "memory"); } while (0)
#define CP_COMMIT() asm volatile("cp.async.commit_group;" ::: "memory")
#define CP_WAIT1()  asm volatile("cp.async.wait_group 1;" ::: "memory")

__device__ __forceinline__ void ldsm_x4(uint32_t* r, uint32_t addr) {
    asm volatile("ldmatrix.sync.aligned.m8n8.x4.shared.b16 {%0,%1,%2,%3}, [%4];"
                 : "=r"(r[0]), "=r"(r[1]), "=r"(r[2]), "=r"(r[3]) : "r"(addr));
}
__device__ __forceinline__ void ldsm_x4t(uint32_t* r, uint32_t addr) {
    asm volatile("ldmatrix.sync.aligned.m8n8.x4.trans.shared.b16 {%0,%1,%2,%3}, [%4];"
                 : "=r"(r[0]), "=r"(r[1]), "=r"(r[2]), "=r"(r[3]) : "r"(addr));
}
// fp16 mma, fp32 accum
__device__ __forceinline__ void mma16816(float* c, const uint32_t* a,
                                         uint32_t b0, uint32_t b1) {
    asm volatile(
        "mma.sync.aligned.m16n8k16.row.col.f32.f16.f16.f32 "
        "{%0,%1,%2,%3}, {%4,%5,%6,%7}, {%8,%9}, {%0,%1,%2,%3};"
        : "+f"(c[0]), "+f"(c[1]), "+f"(c[2]), "+f"(c[3])
        : "r"(a[0]), "r"(a[1]), "r"(a[2]), "r"(a[3]), "r"(b0), "r"(b1));
}
__device__ __forceinline__ uint32_t packh2(float a, float b) {
    __half2 h; h.x = __float2half(a); h.y = __float2half(b);
    return *(uint32_t*)&h;
}

// -------- scratch --------
__device__ float g_kg[BATCH * S_LEN * EMB];
__device__ float g_vg[BATCH * S_LEN * EMB];
__device__ float g_qg[BATCH * GLB * EMB];
__device__ __half g_xh[BATCH * S_LEN * EMB];
__device__ __half g_xl[BATCH * S_LEN * EMB];
__device__ __half g_wt[6 * EMB * EMB];
__device__ __half g_q1[BATCH * S_LEN * EMB];
__device__ __half g_q2[BATCH * S_LEN * EMB];
__device__ __half g_k1[BATCH * S_LEN * EMB];
__device__ __half g_v1[BATCH * S_LEN * EMB];
__device__ float g_po[NSEG * BATCH * NH * GLB * HDIM];
__device__ float g_pm[NSEG * BATCH * NH * GLB];
__device__ float g_pl[NSEG * BATCH * NH * GLB];

// ---------------- prep: x -> fp16 hi/lo ----------------
__global__ __launch_bounds__(256) void convx_kernel(
    const float* __restrict__ x, __half* __restrict__ xh,
    __half* __restrict__ xl)
{
    int i = (blockIdx.x * 256 + threadIdx.x) * 4;
    float4 a = *(const float4*)(x + i);
    __half h[4], l[4];
    float av[4] = {a.x, a.y, a.z, a.w};
#pragma unroll
    for (int j = 0; j < 4; j++) {
        h[j] = __float2half(av[j]);
        l[j] = __float2half(av[j] - __half2float(h[j]));
    }
    *(uint2*)(xh + i) = *(const uint2*)h;
    *(uint2*)(xl + i) = *(const uint2*)l;
}

// ---------------- prep: W -> W^T single fp16 (6 weights) ----------------
__global__ __launch_bounds__(256) void convw_kernel(
    const float* __restrict__ w0, const float* __restrict__ w1,
    const float* __restrict__ w2, const float* __restrict__ w3,
    const float* __restrict__ w4, const float* __restrict__ w5,
    __half* __restrict__ wt)
{
    __shared__ float tile[32][33];
    int z = blockIdx.z;
    const float* W = (z == 0) ? w0 : (z == 1) ? w1 : (z == 2) ? w2 :
                     (z == 3) ? w3 : (z == 4) ? w4 : w5;
    int kb = blockIdx.y * 32, nb = blockIdx.x * 32;
    int tx = threadIdx.x & 31, ty = threadIdx.x >> 5;
    for (int i = ty; i < 32; i += 8)
        tile[i][tx] = W[(size_t)(kb + i) * EMB + nb + tx];
    __syncthreads();
    for (int j = ty; j < 32; j += 8) {
        size_t o = (size_t)z * EMB * EMB + (size_t)(nb + j) * EMB + kb + tx;
        wt[o] = __float2half(tile[tx][j]);
    }
}

// ------- mma.sync GEMM: 128x128 CTA, 256 thr, warp 32x64, k-chunk 64 -------
// z=0 (q) and z=5 (qg): 2-term (xh+xl). z=1..4 (k,v,kg,vg): 1-term (xh only).
#define GST  49152
#define GSM2 (2 * GST)

__global__ __launch_bounds__(256, 2) void mma_gemm6_kernel(
    const __half* __restrict__ xh, const __half* __restrict__ xl,
    const __half* __restrict__ wt,
    const float* __restrict__ bq, const float* __restrict__ bk,
    const float* __restrict__ bv, const float* __restrict__ bkg,
    const float* __restrict__ bvg, const float* __restrict__ bqg,
    __half* q1, __half* q2, __half* k1, __half* v1,
    float* kg, float* vg, float* qg)
{
    extern __shared__ char dsm[];
    int z = blockIdx.z;
    if (z == 5 && blockIdx.y > 0) return;
    int t = threadIdx.x, wid = t >> 5, lane = t & 31;
    int m0 = blockIdx.y * 128, n0 = blockIdx.x * 128;
    int wm = wid & 3, wn = wid >> 2;
    bool twot = (z == 0 || z == 5);

    const float* bias;
    switch (z) {
        case 0:  bias = bq;  break;
        case 1:  bias = bk;  break;
        case 2:  bias = bv;  break;
        case 3:  bias = bkg; break;
        case 4:  bias = bvg; break;
        default: bias = bqg; break;
    }
    float scale = (z == 0 || z == 5) ? 0.125f : 1.0f;
    const __half* Bw = wt + (size_t)z * EMB * EMB;

    uint32_t sb = smem_to_u32(dsm);

    float acc[2][8][4];
#pragma unroll
    for (int mi = 0; mi < 2; mi++)
#pragma unroll
        for (int ni = 0; ni < 8; ni++)
#pragma unroll
            for (int c = 0; c < 4; c++) acc[mi][ni][c] = 0.f;

    uint32_t a_off[2], b_off[4];
#pragma unroll
    for (int mi = 0; mi < 2; mi++) {
        int row = wm * 32 + mi * 16 + (lane & 15);
        a_off[mi] = (uint32_t)(row * 128) + ((lane >> 4) << 4);
    }
#pragma unroll
    for (int bi = 0; bi < 4; bi++) {
        int row = wn * 64 + bi * 16 + (lane & 15);
        b_off[bi] = (uint32_t)(row * 128) + ((lane >> 4) << 4);
    }

#define LOAD_STAGE(chunk, s) do {                                            \
        int k0 = (chunk) * 64;                                               \
        uint32_t base = sb + (s) * GST;                                      \
        _Pragma("unroll")                                                    \
        for (int i = 0; i < 4; i++) {                                        \
            int idx = t + i * 256;                                           \
            int r = idx >> 3, u = idx & 7;                                   \
            uint32_t sw = SW128((uint32_t)(r * 128 + u * 16));               \
            size_t arow;                                                     \
            if (z == 5) { int q2r = r & 63;                                  \
                arow = (size_t)((q2r >> 5) * S_LEN + (q2r & 31)); }          \
            else arow = (size_t)(m0 + r);                                    \
            CP16(base + sw,         xh + arow * EMB + k0 + u * 8);           \
            if (twot)                                                        \
                CP16(base + 16384 + sw, xl + arow * EMB + k0 + u * 8);       \
            CP16(base + 32768 + sw, Bw + (size_t)(n0 + r) * EMB + k0 + u * 8); \
        }                                                                    \
    } while (0)

    LOAD_STAGE(0, 0);
    CP_COMMIT();

    for (int c = 0; c < 12; c++) {
        if (c < 11) LOAD_STAGE(c + 1, (c + 1) & 1);
        CP_COMMIT();
        CP_WAIT1();
        __syncthreads();
        uint32_t base = sb + (c & 1) * GST;
        uint32_t uAh = base, uAl = base + 16384;
        uint32_t uB  = base + 32768;
#pragma unroll
        for (int ks = 0; ks < 4; ks++) {
            uint32_t kb = (uint32_t)(ks * 32);
            uint32_t ah[2][4], al[2][4];
#pragma unroll
            for (int mi = 0; mi < 2; mi++) {
                uint32_t sw = SW128(a_off[mi] + kb);
                ldsm_x4(ah[mi], uAh + sw);
                if (twot) ldsm_x4(al[mi], uAl + sw);
            }
#pragma unroll
            for (int bi = 0; bi < 4; bi++) {
                uint32_t bw[4];
                ldsm_x4(bw, uB + SW128(b_off[bi] + kb));
#pragma unroll
                for (int sel = 0; sel < 2; sel++) {
                    int ni = bi * 2 + sel;
#pragma unroll
                    for (int mi = 0; mi < 2; mi++) {
                        mma16816(acc[mi][ni], ah[mi], bw[sel], bw[sel + 2]);
                        if (twot)
                            mma16816(acc[mi][ni], al[mi], bw[sel], bw[sel + 2]);
                    }
                }
            }
        }
        __syncthreads();
    }
#undef LOAD_STAGE

    int r = lane >> 2, cp = (lane & 3) * 2;
    if (z == 0) {
#pragma unroll
        for (int mi = 0; mi < 2; mi++) {
            int mbase = m0 + wm * 32 + mi * 16;
#pragma unroll
            for (int ni = 0; ni < 8; ni++) {
                int nbase = n0 + wn * 64 + ni * 8 + cp;
                float b0 = bias[nbase], b1 = bias[nbase + 1];
#pragma unroll
                for (int hr = 0; hr < 2; hr++) {
                    int row = mbase + r + hr * 8;
                    float v0 = (acc[mi][ni][hr * 2 + 0] + b0) * scale;
                    float v1 = (acc[mi][ni][hr * 2 + 1] + b1) * scale;
                    __half h0 = __float2half(v0);
                    __half h1 = __float2half(v1);
                    __half l0 = __float2half(v0 - __half2float(h0));
                    __half l1 = __float2half(v1 - __half2float(h1));
                    __half ph[2] = {h0, h1}, pl[2] = {l0, l1};
                    *(uint32_t*)(q1 + (size_t)row * EMB + nbase) = *(uint32_t*)ph;
                    *(uint32_t*)(q2 + (size_t)row * EMB + nbase) = *(uint32_t*)pl;
                }
            }
        }
    } else if (z == 1 || z == 2) {
        __half* Y = (z == 1) ? k1 : v1;
#pragma unroll
        for (int mi = 0; mi < 2; mi++) {
            int mbase = m0 + wm * 32 + mi * 16;
#pragma unroll
            for (int ni = 0; ni < 8; ni++) {
                int nbase = n0 + wn * 64 + ni * 8 + cp;
                float b0 = bias[nbase], b1 = bias[nbase + 1];
#pragma unroll
                for (int hr = 0; hr < 2; hr++) {
                    int row = mbase + r + hr * 8;
                    __half ph[2];
                    ph[0] = __float2half(acc[mi][ni][hr * 2 + 0] + b0);
                    ph[1] = __float2half(acc[mi][ni][hr * 2 + 1] + b1);
                    *(uint32_t*)(Y + (size_t)row * EMB + nbase) = *(uint32_t*)ph;
                }
            }
        }
    } else {
        float* Y = (z == 3) ? kg : (z == 4) ? vg : qg;
#pragma unroll
        for (int mi = 0; mi < 2; mi++) {
            int mbase = m0 + wm * 32 + mi * 16;
#pragma unroll
            for (int ni = 0; ni < 8; ni++) {
                int nbase = n0 + wn * 64 + ni * 8 + cp;
                float b0 = bias[nbase], b1 = bias[nbase + 1];
#pragma unroll
                for (int hr = 0; hr < 2; hr++) {
                    int row = mbase + r + hr * 8;
                    if (z == 5 && row >= BATCH * GLB) continue;
                    float2 o;
                    o.x = (acc[mi][ni][hr * 2 + 0] + b0) * scale;
                    o.y = (acc[mi][ni][hr * 2 + 1] + b1) * scale;
                    *(float2*)(Y + (size_t)row * EMB + nbase) = o;
                }
            }
        }
    }
}

// ------- Local attention: flash-v2, Q-tile 128, 64-key stages ------------
#define LL_QH 0
#define LL_QL 16384
#define LL_K  32768           // + s*8192 (64 rows)
#define LL_V  49152           // + s*8192
#define LL_MS 65536           // int[2][64]
#define LL_TOTAL 66048

__global__ __launch_bounds__(256, 2) void local_attn_mma(
    const __half* __restrict__ q1, const __half* __restrict__ q2,
    const __half* __restrict__ k1, const __half* __restrict__ v1,
    const int* __restrict__ mask, float* __restrict__ out)
{
    extern __shared__ char lsm[];
    uint32_t sbase = smem_to_u32(lsm);
    int* msk = (int*)(lsm + LL_MS);

    int b = blockIdx.z, h = blockIdx.y, i0 = blockIdx.x * QTL;
    int t = threadIdx.x, wm = t >> 5, lane = t & 31;
    int r = lane >> 2, cq = lane & 3;

#pragma unroll
    for (int i = 0; i < 4; i++) {
        int idx = t + i * 256;
        int row = idx >> 3, u = idx & 7;
        size_t g = ((size_t)(b * S_LEN + i0 + row)) * EMB + h * HDIM + u * 8;
        uint32_t sw = SW128((uint32_t)(row * 128 + u * 16));
        *(uint4*)(lsm + LL_QH + sw) = *(const uint4*)(q1 + g);
        *(uint4*)(lsm + LL_QL + sw) = *(const uint4*)(q2 + g);
    }

    int lo = i0 - WIN; if (lo < 0) lo = 0;
    int hi = i0 + QTL - 1 + WIN; if (hi > S_LEN - 1) hi = S_LEN - 1;
    int wstart = lo & ~63;
    int nst = (hi - wstart) / 64 + 1;    // 64-key band stages

#define LOAD_KV64(kstart_, s_) do {                                          \
        _Pragma("unroll")                                                    \
        for (int i_ = 0; i_ < 2; i_++) {                                     \
            int idx_ = t + i_ * 256;                                         \
            int r_ = idx_ >> 3, u_ = idx_ & 7;                               \
            int p_ = (kstart_) + r_;                                         \
            int ok_ = p_ < S_LEN;                                            \
            int pc_ = ok_ ? p_ : (S_LEN - 1);                                \
            size_t g_ = ((size_t)(b * S_LEN + pc_)) * EMB + h * HDIM + u_ * 8; \
            uint32_t sw_ = SW128((uint32_t)(r_ * 128 + u_ * 16));            \
            CPZ16(sbase + LL_K + (s_) * 8192 + sw_, k1 + g_, ok_);           \
            CPZ16(sbase + LL_V + (s_) * 8192 + sw_, v1 + g_, ok_);           \
        }                                                                    \
        if (t < 64) {                                                        \
            int p2_ = (kstart_) + t;                                         \
            int ok2_ = p2_ < S_LEN;                                          \
            const int* ms_ = mask + b * S_LEN + (ok2_ ? p2_ : (S_LEN - 1));  \
            CPZ4(sbase + LL_MS + (s_) * 256 + t * 4, ms_, ok2_);             \
        }                                                                    \
    } while (0)

    LOAD_KV64(0, 0);     // stage for global keys (only first 32 used)
    CP_COMMIT();

    uint32_t aoff = (uint32_t)((wm * 16 + (lane & 15)) * 128 + ((lane >> 4) << 4));
    uint32_t koff0 = (uint32_t)(((lane & 15)) * 128 + ((lane >> 4) << 4));
    uint32_t koff1 = (uint32_t)((16 + (lane & 15)) * 128 + ((lane >> 4) << 4));
    int vtile = lane >> 3, vrow = lane & 7;
    uint32_t vb = (uint32_t)(((vtile & 1) * 8 + vrow) * 128 + ((vtile >> 1) << 4));

    __syncthreads();
    uint32_t qfh[4][4], qfl[4][4];
#pragma unroll
    for (int ks = 0; ks < 4; ks++) {
        uint32_t kb = (uint32_t)(ks * 32);
        ldsm_x4(qfh[ks], sbase + LL_QH + SW128(aoff + kb));
        ldsm_x4(qfl[ks], sbase + LL_QL + SW128(aoff + kb));
    }

    float oacc[8][4];
#pragma unroll
    for (int dg = 0; dg < 8; dg++)
#pragma unroll
        for (int c = 0; c < 4; c++) oacc[dg][c] = 0.f;
    float m0 = -1e30f, m1 = -1e30f, l0 = 0.f, l1 = 0.f;

    int iq0 = i0 + wm * 16 + r;
    int iq_lo = i0 + wm * 16, iq_hi = iq_lo + 15;

    for (int st = -1; st < nst; st++) {
        bool gl = (st < 0);
        int s = (st + 1) & 1;

        __syncthreads();
        if (st + 1 < nst) LOAD_KV64(wstart + (st + 1) * 64, s ^ 1);
        CP_COMMIT();
        CP_WAIT1();
        __syncthreads();

        int nsub = gl ? 1 : 2;
        int kbase = gl ? 0 : wstart + st * 64;

        for (int sub = 0; sub < nsub; sub++) {
            int kstart = kbase + sub * 32;
            uint32_t uK = sbase + LL_K + s * 8192 + (uint32_t)(sub * 4096);
            uint32_t uV = sbase + LL_V + s * 8192 + (uint32_t)(sub * 4096);
            const int* mskS = msk + s * 64 + sub * 32;

            // QK: m16 x n32, K=64, 2-term
            float f[4][4];
#pragma unroll
            for (int nt = 0; nt < 4; nt++)
#pragma unroll
                for (int c = 0; c < 4; c++) f[nt][c] = 0.f;
#pragma unroll
            for (int ks = 0; ks < 4; ks++) {
                uint32_t kb = (uint32_t)(ks * 32);
                uint32_t bw0[4], bw1[4];
                ldsm_x4(bw0, uK + SW128(koff0 + kb));
                ldsm_x4(bw1, uK + SW128(koff1 + kb));
                mma16816(f[0], qfh[ks], bw0[0], bw0[2]);
                mma16816(f[0], qfl[ks], bw0[0], bw0[2]);
                mma16816(f[1], qfh[ks], bw0[1], bw0[3]);
                mma16816(f[1], qfl[ks], bw0[1], bw0[3]);
                mma16816(f[2], qfh[ks], bw1[0], bw1[2]);
                mma16816(f[2], qfl[ks], bw1[0], bw1[2]);
                mma16816(f[3], qfh[ks], bw1[1], bw1[3]);
                mma16816(f[3], qfl[ks], bw1[1], bw1[3]);
            }

            if (!gl) {
                bool all_valid = (kstart >= iq_hi - WIN) &&
                                 (kstart + 31 <= iq_lo + WIN) &&
                                 (kstart + 31 < S_LEN);
                if (all_valid) {
                    // interior: only mask penalty
#pragma unroll
                    for (int nt = 0; nt < 4; nt++)
#pragma unroll
                        for (int cc = 0; cc < 2; cc++) {
                            int j = nt * 8 + cq * 2 + cc;
                            float pen = mskS[j] ? -10000.f : 0.f;
                            f[nt][cc]     += pen;
                            f[nt][2 + cc] += pen;
                        }
                } else {
#pragma unroll
                    for (int nt = 0; nt < 4; nt++)
#pragma unroll
                        for (int cc = 0; cc < 2; cc++) {
                            int j = nt * 8 + cq * 2 + cc;
                            int p = kstart + j;
                            float pen = mskS[j] ? -10000.f : 0.f;
                            bool okp = (p < S_LEN);
                            bool v0 = okp && (p >= iq0 - WIN) && (p <= iq0 + WIN);
                            bool v1v = okp && (p >= iq0 + 8 - WIN) && (p <= iq0 + 8 + WIN);
                            f[nt][cc]     = v0  ? f[nt][cc] + pen     : -1e30f;
                            f[nt][2 + cc] = v1v ? f[nt][2 + cc] + pen : -1e30f;
                        }
                }
            }

            // row-wise online softmax
            float mx0 = fmaxf(fmaxf(f[0][0], f[0][1]), fmaxf(f[1][0], f[1][1]));
            mx0 = fmaxf(mx0, fmaxf(fmaxf(f[2][0], f[2][1]), fmaxf(f[3][0], f[3][1])));
            float mx1 = fmaxf(fmaxf(f[0][2], f[0][3]), fmaxf(f[1][2], f[1][3]));
            mx1 = fmaxf(mx1, fmaxf(fmaxf(f[2][2], f[2][3]), fmaxf(f[3][2], f[3][3])));
            mx0 = fmaxf(mx0, __shfl_xor_sync(0xffffffffu, mx0, 1));
            mx0 = fmaxf(mx0, __shfl_xor_sync(0xffffffffu, mx0, 2));
            mx1 = fmaxf(mx1, __shfl_xor_sync(0xffffffffu, mx1, 1));
            mx1 = fmaxf(mx1, __shfl_xor_sync(0xffffffffu, mx1, 2));
            float mn0 = fmaxf(m0, mx0), mn1 = fmaxf(m1, mx1);
            float rsc0 = __expf(m0 - mn0), rsc1 = __expf(m1 - mn1);
            float s0 = 0.f, s1 = 0.f;
#pragma unroll
            for (int nt = 0; nt < 4; nt++) {
#pragma unroll
                for (int cc = 0; cc < 2; cc++) {
                    float e0 = __expf(f[nt][cc] - mn0);
                    float e1 = __expf(f[nt][2 + cc] - mn1);
                    f[nt][cc] = e0; f[nt][2 + cc] = e1;
                    s0 += e0; s1 += e1;
                }
            }
            s0 += __shfl_xor_sync(0xffffffffu, s0, 1);
            s0 += __shfl_xor_sync(0xffffffffu, s0, 2);
            s1 += __shfl_xor_sync(0xffffffffu, s1, 1);
            s1 += __shfl_xor_sync(0xffffffffu, s1, 2);
            l0 = l0 * rsc0 + s0; m0 = mn0;
            l1 = l1 * rsc1 + s1; m1 = mn1;

            // pack P (2-term) into A-fragments
            uint32_t aPh[2][4], aPl[2][4];
#pragma unroll
            for (int ks = 0; ks < 2; ks++) {
                int t0 = 2 * ks, t1 = 2 * ks + 1;
                float e00 = f[t0][0], e01 = f[t0][1], e02 = f[t0][2], e03 = f[t0][3];
                float e10 = f[t1][0], e11 = f[t1][1], e12 = f[t1][2], e13 = f[t1][3];
                aPh[ks][0] = packh2(e00, e01);
                aPh[ks][1] = packh2(e02, e03);
                aPh[ks][2] = packh2(e10, e11);
                aPh[ks][3] = packh2(e12, e13);
                __half2 h0 = *(__half2*)&aPh[ks][0];
                __half2 h1 = *(__half2*)&aPh[ks][1];
                __half2 h2 = *(__half2*)&aPh[ks][2];
                __half2 h3 = *(__half2*)&aPh[ks][3];
                aPl[ks][0] = packh2(e00 - __half2float(h0.x), e01 - __half2float(h0.y));
                aPl[ks][1] = packh2(e02 - __half2float(h1.x), e03 - __half2float(h1.y));
                aPl[ks][2] = packh2(e10 - __half2float(h2.x), e11 - __half2float(h2.y));
                aPl[ks][3] = packh2(e12 - __half2float(h3.x), e13 - __half2float(h3.y));
            }

#pragma unroll
            for (int dg = 0; dg < 8; dg++) {
                oacc[dg][0] *= rsc0; oacc[dg][1] *= rsc0;
                oacc[dg][2] *= rsc1; oacc[dg][3] *= rsc1;
            }

#pragma unroll
            for (int ks = 0; ks < 2; ks++) {
#pragma unroll
                for (int dgp = 0; dgp < 4; dgp++) {
                    uint32_t bv[4];
                    ldsm_x4t(bv, uV + SW128(vb + (uint32_t)(dgp * 32) +
                                            (uint32_t)(ks * 2048)));
                    mma16816(oacc[dgp * 2],     aPh[ks], bv[0], bv[1]);
                    mma16816(oacc[dgp * 2],     aPl[ks], bv[0], bv[1]);
                    mma16816(oacc[dgp * 2 + 1], aPh[ks], bv[2], bv[3]);
                    mma16816(oacc[dgp * 2 + 1], aPl[ks], bv[2], bv[3]);
                }
            }
        }
    }
#undef LOAD_KV64

    float inv0 = 1.f / l0, inv1 = 1.f / l1;
    int row0 = i0 + wm * 16 + r;
#pragma unroll
    for (int dg = 0; dg < 8; dg++) {
        int c = dg * 8 + cq * 2;
        size_t o0 = ((size_t)(b * S_LEN + row0)) * EMB + h * HDIM + c;
        size_t o1 = ((size_t)(b * S_LEN + row0 + 8)) * EMB + h * HDIM + c;
        float2 v0; v0.x = oacc[dg][0] * inv0; v0.y = oacc[dg][1] * inv0;
        float2 v1; v1.x = oacc[dg][2] * inv1; v1.y = oacc[dg][3] * inv1;
        *(float2*)(out + o0) = v0;
        *(float2*)(out + o1) = v1;
    }
}

// ---------------- Global rows: split-K partial flash ----------------
__global__ __launch_bounds__(256, 2) void global_part_kernel(
    const float* __restrict__ qg, const float* __restrict__ kg,
    const float* __restrict__ vg,
    float* __restrict__ po, float* __restrict__ pm, float* __restrict__ pl)
{
    __shared__ float ks[32][68];
    __shared__ float vs[32][68];
    __shared__ float sc[32][36];

    int seg = blockIdx.x, h = blockIdx.y, b = blockIdx.z;
    int t = threadIdx.x;
    int qi = t >> 3, sub = t & 7;

    u64 q2[32];
    {
        const ulonglong2* qrow = (const ulonglong2*)
            (qg + ((size_t)(b * GLB + qi)) * EMB + h * HDIM);
#pragma unroll
        for (int e = 0; e < 16; e++) {
            ulonglong2 t2 = qrow[e];
            q2[e * 2] = t2.x; q2[e * 2 + 1] = t2.y;
        }
    }
    u64 acc2[4] = {0ULL, 0ULL, 0ULL, 0ULL};
    float m_run = -1e30f, l_run = 0.f;

    for (int c = 0; c < SEGLEN / 32; c++) {
        int kstart = seg * SEGLEN + c * 32;
        __syncthreads();
        for (int u = t; u < 32 * 16; u += 256) {
            int r = u >> 4, cc = (u & 15) << 2;
            size_t off = ((size_t)(b * S_LEN + kstart + r)) * EMB + h * HDIM + cc;
            *(float4*)&ks[r][cc] = *(const float4*)(kg + off);
            *(float4*)&vs[r][cc] = *(const float4*)(vg + off);
        }
        __syncthreads();

        float sv[4];
#pragma unroll
        for (int u2 = 0; u2 < 4; u2++) {
            int j = sub * 4 + u2;
            const ulonglong2* kr = (const ulonglong2*)&ks[j][0];
            u64 s0 = 0ULL, s1 = 0ULL, s2 = 0ULL, s3 = 0ULL;
#pragma unroll
            for (int e = 0; e < 16; e += 2) {
                ulonglong2 ka = kr[e];
                ulonglong2 kb = kr[e + 1];
                s0 = ffma2(q2[e * 2],     ka.x, s0);
                s1 = ffma2(q2[e * 2 + 1], ka.y, s1);
                s2 = ffma2(q2[e * 2 + 2], kb.x, s2);
                s3 = ffma2(q2[e * 2 + 3], kb.y, s3);
            }
            float2 r2 = up2(fadd2(fadd2(s0, s1), fadd2(s2, s3)));
            sv[u2] = r2.x + r2.y;
        }
        float cm = fmaxf(fmaxf(sv[0], sv[1]), fmaxf(sv[2], sv[3]));
        cm = fmaxf(cm, __shfl_xor_sync(0xffffffffu, cm, 1));
        cm = fmaxf(cm, __shfl_xor_sync(0xffffffffu, cm, 2));
        cm = fmaxf(cm, __shfl_xor_sync(0xffffffffu, cm, 4));
        float m_new = fmaxf(m_run, cm);
        float rsc = __expf(m_run - m_new);
        float psum = 0.f;
#pragma unroll
        for (int u2 = 0; u2 < 4; u2++) {
            float e = __expf(sv[u2] - m_new);
            sc[qi][sub * 4 + u2] = e;
            psum += e;
        }
        psum += __shfl_xor_sync(0xffffffffu, psum, 1);
        psum += __shfl_xor_sync(0xffffffffu, psum, 2);
        psum += __shfl_xor_sync(0xffffffffu, psum, 4);
        l_run = l_run * rsc + psum;
        m_run = m_new;
        __syncwarp();

        u64 rb = dup2(rsc);
#pragma unroll
        for (int d = 0; d < 4; d++) acc2[d] = fmul2(acc2[d], rb);
#pragma unroll 4
        for (int j = 0; j < 32; j++) {
            u64 eb = dup2(sc[qi][j]);
            ulonglong2 v0 = *(const ulonglong2*)&vs[j][sub * 4];
            ulonglong2 v1 = *(const ulonglong2*)&vs[j][sub * 4 + 32];
            acc2[0] = ffma2(eb, v0.x, acc2[0]);
            acc2[1] = ffma2(eb, v0.y, acc2[1]);
            acc2[2] = ffma2(eb, v1.x, acc2[2]);
            acc2[3] = ffma2(eb, v1.y, acc2[3]);
        }
    }

    size_t pidx = (((size_t)seg * BATCH + b) * NH + h) * GLB + qi;
    float2 a0 = up2(acc2[0]), a1 = up2(acc2[1]);
    float2 a2 = up2(acc2[2]), a3 = up2(acc2[3]);
    float* prow = po + pidx * HDIM;
    *(float4*)(prow + sub * 4)      = make_float4(a0.x, a0.y, a1.x, a1.y);
    *(float4*)(prow + 32 + sub * 4) = make_float4(a2.x, a2.y, a3.x, a3.y);
    if (sub == 0) { pm[pidx] = m_run; pl[pidx] = l_run; }
}

__global__ __launch_bounds__(64) void global_merge_kernel(
    const float* __restrict__ po, const float* __restrict__ pm,
    const float* __restrict__ pl, float* __restrict__ out)
{
    int g = blockIdx.x, h = blockIdx.y, b = blockIdx.z;
    int d = threadIdx.x;

    float mv[NSEG];
    float mx = -1e30f;
#pragma unroll
    for (int s = 0; s < NSEG; s++) {
        mv[s] = pm[(((size_t)s * BATCH + b) * NH + h) * GLB + g];
        mx = fmaxf(mx, mv[s]);
    }
    float num = 0.f, den = 0.f;
#pragma unroll
    for (int s = 0; s < NSEG; s++) {
        size_t pidx = (((size_t)s * BATCH + b) * NH + h) * GLB + g;
        float w = __expf(mv[s] - mx);
        num += w * po[pidx * HDIM + d];
        den += w * pl[pidx];
    }
    out[((size_t)(b * S_LEN + g)) * EMB + h * HDIM + d] = num / den;
}

// ---------------- launch ----------------
extern "C" void kernel_launch(void* const* d_in, const int* in_sizes, int n_in,
                              void* d_out, int out_size)
{
    (void)n_in; (void)out_size;
    int base = (in_sizes[2] == EMB * EMB) ? 2 : 3;

    const float* x    = (const float*)d_in[0];
    const int*   mask = (const int*)d_in[1];
    const float* wq   = (const float*)d_in[base + 0];
    const float* bq   = (const float*)d_in[base + 1];
    const float* wk   = (const float*)d_in[base + 2];
    const float* bk   = (const float*)d_in[base + 3];
    const float* wv   = (const float*)d_in[base + 4];
    const float* bv   = (const float*)d_in[base + 5];
    const float* wqg  = (const float*)d_in[base + 6];
    const float* bqg  = (const float*)d_in[base + 7];
    const float* wkg  = (const float*)d_in[base + 8];
    const float* bkg  = (const float*)d_in[base + 9];
    const float* wvg  = (const float*)d_in[base + 10];
    const float* bvg  = (const float*)d_in[base + 11];
    float* out = (float*)d_out;

    float *kg, *vg, *qg, *po, *pm, *pl;
    __half *xh, *xl, *wt, *q1, *q2, *k1, *v1;
    cudaGetSymbolAddress((void**)&kg, g_kg);
    cudaGetSymbolAddress((void**)&vg, g_vg);
    cudaGetSymbolAddress((void**)&qg, g_qg);
    cudaGetSymbolAddress((void**)&xh, g_xh);
    cudaGetSymbolAddress((void**)&xl, g_xl);
    cudaGetSymbolAddress((void**)&wt, g_wt);
    cudaGetSymbolAddress((void**)&q1, g_q1);
    cudaGetSymbolAddress((void**)&q2, g_q2);
    cudaGetSymbolAddress((void**)&k1, g_k1);
    cudaGetSymbolAddress((void**)&v1, g_v1);
    cudaGetSymbolAddress((void**)&po, g_po);
    cudaGetSymbolAddress((void**)&pm, g_pm);
    cudaGetSymbolAddress((void**)&pl, g_pl);

    cudaFuncSetAttribute(mma_gemm6_kernel,
                         cudaFuncAttributeMaxDynamicSharedMemorySize, GSM2);
    cudaFuncSetAttribute(local_attn_mma,
                         cudaFuncAttributeMaxDynamicSharedMemorySize, LL_TOTAL);

    convx_kernel<<<(BATCH * S_LEN * EMB) / (256 * 4), 256>>>(x, xh, xl);
    convw_kernel<<<dim3(EMB / 32, EMB / 32, 6), 256>>>(
        wq, wk, wv, wkg, wvg, wqg, wt);
    mma_gemm6_kernel<<<dim3(EMB / 128, BATCH * S_LEN / 128, 6), 256, GSM2>>>(
        xh, xl, wt, bq, bk, bv, bkg, bvg, bqg,
        q1, q2, k1, v1, kg, vg, qg);
    local_attn_mma<<<dim3(S_LEN / QTL, NH, BATCH), 256, LL_TOTAL>>>(
        q1, q2, k1, v1, mask, out);
    global_part_kernel<<<dim3(NSEG, NH, BATCH), 256>>>(qg, kg, vg, po, pm, pl);
    global_merge_kernel<<<dim3(GLB, NH, BATCH), 64>>>(po, pm, pl, out);
}

// round 16
// speedup vs baseline: 1.2228x; 1.0328x over previous
#include <cuda_runtime.h>
#include <cuda_fp16.h>
#include <cstdint>

#define S_LEN 4096
#define BATCH 2
#define EMB   768
#define NH    12
#define HDIM  64
#define WIN   256
#define GLB   32
#define QTL   128
#define NSEG  16
#define SEGLEN (S_LEN / NSEG)

typedef unsigned long long u64;

// ---------- packed f32x2 helpers ----------
__device__ __forceinline__ u64 pk2(float x, float y) {
    u64 r; asm("mov.b64 %0, {%1,%2};" : "=l"(r) : "f"(x), "f"(y)); return r;
}
__device__ __forceinline__ u64 dup2(float x) { return pk2(x, x); }
__device__ __forceinline__ float2 up2(u64 v) {
    float2 f; asm("mov.b64 {%0,%1}, %2;" : "=f"(f.x), "=f"(f.y) : "l"(v)); return f;
}
__device__ __forceinline__ u64 ffma2(u64 a, u64 b, u64 c) {
    u64 d; asm("fma.rn.f32x2 %0, %1, %2, %3;" : "=l"(d) : "l"(a), "l"(b), "l"(c)); return d;
}
__device__ __forceinline__ u64 fadd2(u64 a, u64 b) {
    u64 d; asm("add.rn.f32x2 %0, %1, %2;" : "=l"(d) : "l"(a), "l"(b)); return d;
}
__device__ __forceinline__ u64 fmul2(u64 a, u64 b) {
    u64 d; asm("mul.rn.f32x2 %0, %1, %2;" : "=l"(d) : "l"(a), "l"(b)); return d;
}

__device__ __forceinline__ uint32_t smem_to_u32(const void* p) {
    uint32_t a;
    asm("{ .reg .u64 t; cvta.to.shared.u64 t, %1; cvt.u32.u64 %0, t; }" : "=r"(a) : "l"(p));
    return a;
}
#define SW128(o) ((o) ^ (((o) >> 3) & 0x70))

#define CP16(dst, src) \
    asm volatile("cp.async.cg.shared.global [%0], [%1], 16;" \
                 :: "r"(dst), "l"(src) : "memory")
#define CPZ16(dst, src, pred) do { \
    int _sz = (pred) ? 16 : 0; \
    asm volatile("cp.async.cg.shared.global [%0], [%1], 16, %2;" \
                 :: "r"(dst), "l"(src), "r"(_sz) : "memory"); } while (0)
#define CPZ4(dst, src, pred) do { \
    int _sz = (pred) ? 4 : 0; \
    asm volatile("cp.async.ca.shared.global [%0], [%1], 4, %2;" \
                 :: "r"(dst), "l"(src), "r"(_sz) : "memory"); } while (0)
#define CP_COMMIT() asm volatile("cp.async.commit_group;" ::: "memory")
#define CP_WAIT1()  asm volatile("cp.async.wait_group 1;" ::: "memory")

__device__ __forceinline__ void ldsm_x4(uint32_t* r, uint32_t addr) {
    asm volatile("ldmatrix.sync.aligned.m8n8.x4.shared.b16 {%0,%1,%2,%3}, [%4];"
                 : "=r"(r[0]), "=r"(r[1]), "=r"(r[2]), "=r"(r[3]) : "r"(addr));
}
__device__ __forceinline__ void ldsm_x4t(uint32_t* r, uint32_t addr) {
    asm volatile("ldmatrix.sync.aligned.m8n8.x4.trans.shared.b16 {%0,%1,%2,%3}, [%4];"
                 : "=r"(r[0]), "=r"(r[1]), "=r"(r[2]), "=r"(r[3]) : "r"(addr));
}
// fp16 mma, fp32 accum
__device__ __forceinline__ void mma16816(float* c, const uint32_t* a,
                                         uint32_t b0, uint32_t b1) {
    asm volatile(
        "mma.sync.aligned.m16n8k16.row.col.f32.f16.f16.f32 "
        "{%0,%1,%2,%3}, {%4,%5,%6,%7}, {%8,%9}, {%0,%1,%2,%3};"
        : "+f"(c[0]), "+f"(c[1]), "+f"(c[2]), "+f"(c[3])
        : "r"(a[0]), "r"(a[1]), "r"(a[2]), "r"(a[3]), "r"(b0), "r"(b1));
}
__device__ __forceinline__ uint32_t packh2(float a, float b) {
    __half2 h; h.x = __float2half(a); h.y = __float2half(b);
    return *(uint32_t*)&h;
}

// -------- scratch --------
__device__ float g_kg[BATCH * S_LEN * EMB];
__device__ float g_vg[BATCH * S_LEN * EMB];
__device__ float g_qg[BATCH * GLB * EMB];
__device__ __half g_xh[BATCH * S_LEN * EMB];
__device__ __half g_xl[BATCH * S_LEN * EMB];
__device__ __half g_wt[6 * EMB * EMB];
__device__ __half g_q1[BATCH * S_LEN * EMB];
__device__ __half g_q2[BATCH * S_LEN * EMB];
__device__ __half g_k1[BATCH * S_LEN * EMB];
__device__ __half g_v1[BATCH * S_LEN * EMB];
__device__ float g_po[NSEG * BATCH * NH * GLB * HDIM];
__device__ float g_pm[NSEG * BATCH * NH * GLB];
__device__ float g_pl[NSEG * BATCH * NH * GLB];

// ---------------- prep: x -> fp16 hi/lo ----------------
__global__ __launch_bounds__(256) void convx_kernel(
    const float* __restrict__ x, __half* __restrict__ xh,
    __half* __restrict__ xl)
{
    int i = (blockIdx.x * 256 + threadIdx.x) * 4;
    float4 a = *(const float4*)(x + i);
    __half h[4], l[4];
    float av[4] = {a.x, a.y, a.z, a.w};
#pragma unroll
    for (int j = 0; j < 4; j++) {
        h[j] = __float2half(av[j]);
        l[j] = __float2half(av[j] - __half2float(h[j]));
    }
    *(uint2*)(xh + i) = *(const uint2*)h;
    *(uint2*)(xl + i) = *(const uint2*)l;
}

// ---------------- prep: W -> W^T single fp16 (6 weights) ----------------
__global__ __launch_bounds__(256) void convw_kernel(
    const float* __restrict__ w0, const float* __restrict__ w1,
    const float* __restrict__ w2, const float* __restrict__ w3,
    const float* __restrict__ w4, const float* __restrict__ w5,
    __half* __restrict__ wt)
{
    __shared__ float tile[32][33];
    int z = blockIdx.z;
    const float* W = (z == 0) ? w0 : (z == 1) ? w1 : (z == 2) ? w2 :
                     (z == 3) ? w3 : (z == 4) ? w4 : w5;
    int kb = blockIdx.y * 32, nb = blockIdx.x * 32;
    int tx = threadIdx.x & 31, ty = threadIdx.x >> 5;
    for (int i = ty; i < 32; i += 8)
        tile[i][tx] = W[(size_t)(kb + i) * EMB + nb + tx];
    __syncthreads();
    for (int j = ty; j < 32; j += 8) {
        size_t o = (size_t)z * EMB * EMB + (size_t)(nb + j) * EMB + kb + tx;
        wt[o] = __float2half(tile[tx][j]);
    }
}

// ------- mma.sync GEMM: 128x128 CTA, 256 thr, warp 32x64, k-chunk 64 -------
// z=0 (q) and z=5 (qg): 2-term (xh+xl). z=1..4 (k,v,kg,vg): 1-term (xh only).
#define GST  49152
#define GSM2 (2 * GST)

__global__ __launch_bounds__(256, 2) void mma_gemm6_kernel(
    const __half* __restrict__ xh, const __half* __restrict__ xl,
    const __half* __restrict__ wt,
    const float* __restrict__ bq, const float* __restrict__ bk,
    const float* __restrict__ bv, const float* __restrict__ bkg,
    const float* __restrict__ bvg, const float* __restrict__ bqg,
    __half* q1, __half* q2, __half* k1, __half* v1,
    float* kg, float* vg, float* qg)
{
    extern __shared__ char dsm[];
    int z = blockIdx.z;
    if (z == 5 && blockIdx.y > 0) return;
    int t = threadIdx.x, wid = t >> 5, lane = t & 31;
    int m0 = blockIdx.y * 128, n0 = blockIdx.x * 128;
    int wm = wid & 3, wn = wid >> 2;
    bool twot = (z == 0 || z == 5);

    const float* bias;
    switch (z) {
        case 0:  bias = bq;  break;
        case 1:  bias = bk;  break;
        case 2:  bias = bv;  break;
        case 3:  bias = bkg; break;
        case 4:  bias = bvg; break;
        default: bias = bqg; break;
    }
    float scale = (z == 0 || z == 5) ? 0.125f : 1.0f;
    const __half* Bw = wt + (size_t)z * EMB * EMB;

    uint32_t sb = smem_to_u32(dsm);

    float acc[2][8][4];
#pragma unroll
    for (int mi = 0; mi < 2; mi++)
#pragma unroll
        for (int ni = 0; ni < 8; ni++)
#pragma unroll
            for (int c = 0; c < 4; c++) acc[mi][ni][c] = 0.f;

    uint32_t a_off[2], b_off[4];
#pragma unroll
    for (int mi = 0; mi < 2; mi++) {
        int row = wm * 32 + mi * 16 + (lane & 15);
        a_off[mi] = (uint32_t)(row * 128) + ((lane >> 4) << 4);
    }
#pragma unroll
    for (int bi = 0; bi < 4; bi++) {
        int row = wn * 64 + bi * 16 + (lane & 15);
        b_off[bi] = (uint32_t)(row * 128) + ((lane >> 4) << 4);
    }

#define LOAD_STAGE(chunk, s) do {                                            \
        int k0 = (chunk) * 64;                                               \
        uint32_t base = sb + (s) * GST;                                      \
        _Pragma("unroll")                                                    \
        for (int i = 0; i < 4; i++) {                                        \
            int idx = t + i * 256;                                           \
            int r = idx >> 3, u = idx & 7;                                   \
            uint32_t sw = SW128((uint32_t)(r * 128 + u * 16));               \
            size_t arow;                                                     \
            if (z == 5) { int q2r = r & 63;                                  \
                arow = (size_t)((q2r >> 5) * S_LEN + (q2r & 31)); }          \
            else arow = (size_t)(m0 + r);                                    \
            CP16(base + sw,         xh + arow * EMB + k0 + u * 8);           \
            if (twot)                                                        \
                CP16(base + 16384 + sw, xl + arow * EMB + k0 + u * 8);       \
            CP16(base + 32768 + sw, Bw + (size_t)(n0 + r) * EMB + k0 + u * 8); \
        }                                                                    \
    } while (0)

    LOAD_STAGE(0, 0);
    CP_COMMIT();

    for (int c = 0; c < 12; c++) {
        if (c < 11) LOAD_STAGE(c + 1, (c + 1) & 1);
        CP_COMMIT();
        CP_WAIT1();
        __syncthreads();
        uint32_t base = sb + (c & 1) * GST;
        uint32_t uAh = base, uAl = base + 16384;
        uint32_t uB  = base + 32768;
#pragma unroll
        for (int ks = 0; ks < 4; ks++) {
            uint32_t kb = (uint32_t)(ks * 32);
            uint32_t ah[2][4], al[2][4];
#pragma unroll
            for (int mi = 0; mi < 2; mi++) {
                uint32_t sw = SW128(a_off[mi] + kb);
                ldsm_x4(ah[mi], uAh + sw);
                if (twot) ldsm_x4(al[mi], uAl + sw);
            }
#pragma unroll
            for (int bi = 0; bi < 4; bi++) {
                uint32_t bw[4];
                ldsm_x4(bw, uB + SW128(b_off[bi] + kb));
#pragma unroll
                for (int sel = 0; sel < 2; sel++) {
                    int ni = bi * 2 + sel;
#pragma unroll
                    for (int mi = 0; mi < 2; mi++) {
                        mma16816(acc[mi][ni], ah[mi], bw[sel], bw[sel + 2]);
                        if (twot)
                            mma16816(acc[mi][ni], al[mi], bw[sel], bw[sel + 2]);
                    }
                }
            }
        }
        __syncthreads();
    }
#undef LOAD_STAGE

    int r = lane >> 2, cp = (lane & 3) * 2;
    if (z == 0) {
#pragma unroll
        for (int mi = 0; mi < 2; mi++) {
            int mbase = m0 + wm * 32 + mi * 16;
#pragma unroll
            for (int ni = 0; ni < 8; ni++) {
                int nbase = n0 + wn * 64 + ni * 8 + cp;
                float b0 = bias[nbase], b1 = bias[nbase + 1];
#pragma unroll
                for (int hr = 0; hr < 2; hr++) {
                    int row = mbase + r + hr * 8;
                    float v0 = (acc[mi][ni][hr * 2 + 0] + b0) * scale;
                    float v1 = (acc[mi][ni][hr * 2 + 1] + b1) * scale;
                    __half h0 = __float2half(v0);
                    __half h1 = __float2half(v1);
                    __half l0 = __float2half(v0 - __half2float(h0));
                    __half l1 = __float2half(v1 - __half2float(h1));
                    __half ph[2] = {h0, h1}, pl[2] = {l0, l1};
                    *(uint32_t*)(q1 + (size_t)row * EMB + nbase) = *(uint32_t*)ph;
                    *(uint32_t*)(q2 + (size_t)row * EMB + nbase) = *(uint32_t*)pl;
                }
            }
        }
    } else if (z == 1 || z == 2) {
        __half* Y = (z == 1) ? k1 : v1;
#pragma unroll
        for (int mi = 0; mi < 2; mi++) {
            int mbase = m0 + wm * 32 + mi * 16;
#pragma unroll
            for (int ni = 0; ni < 8; ni++) {
                int nbase = n0 + wn * 64 + ni * 8 + cp;
                float b0 = bias[nbase], b1 = bias[nbase + 1];
#pragma unroll
                for (int hr = 0; hr < 2; hr++) {
                    int row = mbase + r + hr * 8;
                    __half ph[2];
                    ph[0] = __float2half(acc[mi][ni][hr * 2 + 0] + b0);
                    ph[1] = __float2half(acc[mi][ni][hr * 2 + 1] + b1);
                    *(uint32_t*)(Y + (size_t)row * EMB + nbase) = *(uint32_t*)ph;
                }
            }
        }
    } else {
        float* Y = (z == 3) ? kg : (z == 4) ? vg : qg;
#pragma unroll
        for (int mi = 0; mi < 2; mi++) {
            int mbase = m0 + wm * 32 + mi * 16;
#pragma unroll
            for (int ni = 0; ni < 8; ni++) {
                int nbase = n0 + wn * 64 + ni * 8 + cp;
                float b0 = bias[nbase], b1 = bias[nbase + 1];
#pragma unroll
                for (int hr = 0; hr < 2; hr++) {
                    int row = mbase + r + hr * 8;
                    if (z == 5 && row >= BATCH * GLB) continue;
                    float2 o;
                    o.x = (acc[mi][ni][hr * 2 + 0] + b0) * scale;
                    o.y = (acc[mi][ni][hr * 2 + 1] + b1) * scale;
                    *(float2*)(Y + (size_t)row * EMB + nbase) = o;
                }
            }
        }
    }
}

// ------- Local attention: flash-v2, Q-tile 128, 64-key stages ------------
// P single fp16 in PV (p-lo dropped: probs in [0,1], quantization 2^-11 rel).
#define LL_QH 0
#define LL_QL 16384
#define LL_K  32768           // + s*8192 (64 rows)
#define LL_V  49152           // + s*8192
#define LL_MS 65536           // int[2][64]
#define LL_TOTAL 66048

__global__ __launch_bounds__(256, 2) void local_attn_mma(
    const __half* __restrict__ q1, const __half* __restrict__ q2,
    const __half* __restrict__ k1, const __half* __restrict__ v1,
    const int* __restrict__ mask, float* __restrict__ out)
{
    extern __shared__ char lsm[];
    uint32_t sbase = smem_to_u32(lsm);
    int* msk = (int*)(lsm + LL_MS);

    int b = blockIdx.z, h = blockIdx.y, i0 = blockIdx.x * QTL;
    int t = threadIdx.x, wm = t >> 5, lane = t & 31;
    int r = lane >> 2, cq = lane & 3;

#pragma unroll
    for (int i = 0; i < 4; i++) {
        int idx = t + i * 256;
        int row = idx >> 3, u = idx & 7;
        size_t g = ((size_t)(b * S_LEN + i0 + row)) * EMB + h * HDIM + u * 8;
        uint32_t sw = SW128((uint32_t)(row * 128 + u * 16));
        *(uint4*)(lsm + LL_QH + sw) = *(const uint4*)(q1 + g);
        *(uint4*)(lsm + LL_QL + sw) = *(const uint4*)(q2 + g);
    }

    int lo = i0 - WIN; if (lo < 0) lo = 0;
    int hi = i0 + QTL - 1 + WIN; if (hi > S_LEN - 1) hi = S_LEN - 1;
    int wstart = lo & ~63;
    int nst = (hi - wstart) / 64 + 1;

#define LOAD_KV64(kstart_, s_) do {                                          \
        _Pragma("unroll")                                                    \
        for (int i_ = 0; i_ < 2; i_++) {                                     \
            int idx_ = t + i_ * 256;                                         \
            int r_ = idx_ >> 3, u_ = idx_ & 7;                               \
            int p_ = (kstart_) + r_;                                         \
            int ok_ = p_ < S_LEN;                                            \
            int pc_ = ok_ ? p_ : (S_LEN - 1);                                \
            size_t g_ = ((size_t)(b * S_LEN + pc_)) * EMB + h * HDIM + u_ * 8; \
            uint32_t sw_ = SW128((uint32_t)(r_ * 128 + u_ * 16));            \
            CPZ16(sbase + LL_K + (s_) * 8192 + sw_, k1 + g_, ok_);           \
            CPZ16(sbase + LL_V + (s_) * 8192 + sw_, v1 + g_, ok_);           \
        }                                                                    \
        if (t < 64) {                                                        \
            int p2_ = (kstart_) + t;                                         \
            int ok2_ = p2_ < S_LEN;                                          \
            const int* ms_ = mask + b * S_LEN + (ok2_ ? p2_ : (S_LEN - 1));  \
            CPZ4(sbase + LL_MS + (s_) * 256 + t * 4, ms_, ok2_);             \
        }                                                                    \
    } while (0)

    LOAD_KV64(0, 0);
    CP_COMMIT();

    uint32_t aoff = (uint32_t)((wm * 16 + (lane & 15)) * 128 + ((lane >> 4) << 4));
    uint32_t koff0 = (uint32_t)(((lane & 15)) * 128 + ((lane >> 4) << 4));
    uint32_t koff1 = (uint32_t)((16 + (lane & 15)) * 128 + ((lane >> 4) << 4));
    int vtile = lane >> 3, vrow = lane & 7;
    uint32_t vb = (uint32_t)(((vtile & 1) * 8 + vrow) * 128 + ((vtile >> 1) << 4));

    __syncthreads();
    uint32_t qfh[4][4], qfl[4][4];
#pragma unroll
    for (int ks = 0; ks < 4; ks++) {
        uint32_t kb = (uint32_t)(ks * 32);
        ldsm_x4(qfh[ks], sbase + LL_QH + SW128(aoff + kb));
        ldsm_x4(qfl[ks], sbase + LL_QL + SW128(aoff + kb));
    }

    float oacc[8][4];
#pragma unroll
    for (int dg = 0; dg < 8; dg++)
#pragma unroll
        for (int c = 0; c < 4; c++) oacc[dg][c] = 0.f;
    float m0 = -1e30f, m1 = -1e30f, l0 = 0.f, l1 = 0.f;

    int iq0 = i0 + wm * 16 + r;
    int iq_lo = i0 + wm * 16, iq_hi = iq_lo + 15;

    for (int st = -1; st < nst; st++) {
        bool gl = (st < 0);
        int s = (st + 1) & 1;

        __syncthreads();
        if (st + 1 < nst) LOAD_KV64(wstart + (st + 1) * 64, s ^ 1);
        CP_COMMIT();
        CP_WAIT1();
        __syncthreads();

        int nsub = gl ? 1 : 2;
        int kbase = gl ? 0 : wstart + st * 64;

        for (int sub = 0; sub < nsub; sub++) {
            int kstart = kbase + sub * 32;
            uint32_t uK = sbase + LL_K + s * 8192 + (uint32_t)(sub * 4096);
            uint32_t uV = sbase + LL_V + s * 8192 + (uint32_t)(sub * 4096);
            const int* mskS = msk + s * 64 + sub * 32;

            // QK: m16 x n32, K=64, 2-term
            float f[4][4];
#pragma unroll
            for (int nt = 0; nt < 4; nt++)
#pragma unroll
                for (int c = 0; c < 4; c++) f[nt][c] = 0.f;
#pragma unroll
            for (int ks = 0; ks < 4; ks++) {
                uint32_t kb = (uint32_t)(ks * 32);
                uint32_t bw0[4], bw1[4];
                ldsm_x4(bw0, uK + SW128(koff0 + kb));
                ldsm_x4(bw1, uK + SW128(koff1 + kb));
                mma16816(f[0], qfh[ks], bw0[0], bw0[2]);
                mma16816(f[0], qfl[ks], bw0[0], bw0[2]);
                mma16816(f[1], qfh[ks], bw0[1], bw0[3]);
                mma16816(f[1], qfl[ks], bw0[1], bw0[3]);
                mma16816(f[2], qfh[ks], bw1[0], bw1[2]);
                mma16816(f[2], qfl[ks], bw1[0], bw1[2]);
                mma16816(f[3], qfh[ks], bw1[1], bw1[3]);
                mma16816(f[3], qfl[ks], bw1[1], bw1[3]);
            }

            if (!gl) {
                bool all_valid = (kstart >= iq_hi - WIN) &&
                                 (kstart + 31 <= iq_lo + WIN) &&
                                 (kstart + 31 < S_LEN);
                if (all_valid) {
#pragma unroll
                    for (int nt = 0; nt < 4; nt++)
#pragma unroll
                        for (int cc = 0; cc < 2; cc++) {
                            int j = nt * 8 + cq * 2 + cc;
                            float pen = mskS[j] ? -10000.f : 0.f;
                            f[nt][cc]     += pen;
                            f[nt][2 + cc] += pen;
                        }
                } else {
#pragma unroll
                    for (int nt = 0; nt < 4; nt++)
#pragma unroll
                        for (int cc = 0; cc < 2; cc++) {
                            int j = nt * 8 + cq * 2 + cc;
                            int p = kstart + j;
                            float pen = mskS[j] ? -10000.f : 0.f;
                            bool okp = (p < S_LEN);
                            bool v0 = okp && (p >= iq0 - WIN) && (p <= iq0 + WIN);
                            bool v1v = okp && (p >= iq0 + 8 - WIN) && (p <= iq0 + 8 + WIN);
                            f[nt][cc]     = v0  ? f[nt][cc] + pen     : -1e30f;
                            f[nt][2 + cc] = v1v ? f[nt][2 + cc] + pen : -1e30f;
                        }
                }
            }

            // row-wise online softmax
            float mx0 = fmaxf(fmaxf(f[0][0], f[0][1]), fmaxf(f[1][0], f[1][1]));
            mx0 = fmaxf(mx0, fmaxf(fmaxf(f[2][0], f[2][1]), fmaxf(f[3][0], f[3][1])));
            float mx1 = fmaxf(fmaxf(f[0][2], f[0][3]), fmaxf(f[1][2], f[1][3]));
            mx1 = fmaxf(mx1, fmaxf(fmaxf(f[2][2], f[2][3]), fmaxf(f[3][2], f[3][3])));
            mx0 = fmaxf(mx0, __shfl_xor_sync(0xffffffffu, mx0, 1));
            mx0 = fmaxf(mx0, __shfl_xor_sync(0xffffffffu, mx0, 2));
            mx1 = fmaxf(mx1, __shfl_xor_sync(0xffffffffu, mx1, 1));
            mx1 = fmaxf(mx1, __shfl_xor_sync(0xffffffffu, mx1, 2));
            float mn0 = fmaxf(m0, mx0), mn1 = fmaxf(m1, mx1);
            float rsc0 = __expf(m0 - mn0), rsc1 = __expf(m1 - mn1);
            float s0 = 0.f, s1 = 0.f;
#pragma unroll
            for (int nt = 0; nt < 4; nt++) {
#pragma unroll
                for (int cc = 0; cc < 2; cc++) {
                    float e0 = __expf(f[nt][cc] - mn0);
                    float e1 = __expf(f[nt][2 + cc] - mn1);
                    f[nt][cc] = e0; f[nt][2 + cc] = e1;
                    s0 += e0; s1 += e1;
                }
            }
            s0 += __shfl_xor_sync(0xffffffffu, s0, 1);
            s0 += __shfl_xor_sync(0xffffffffu, s0, 2);
            s1 += __shfl_xor_sync(0xffffffffu, s1, 1);
            s1 += __shfl_xor_sync(0xffffffffu, s1, 2);
            l0 = l0 * rsc0 + s0; m0 = mn0;
            l1 = l1 * rsc1 + s1; m1 = mn1;

            // pack P (single fp16) into A-fragments
            uint32_t aPh[2][4];
#pragma unroll
            for (int ks = 0; ks < 2; ks++) {
                int t0 = 2 * ks, t1 = 2 * ks + 1;
                aPh[ks][0] = packh2(f[t0][0], f[t0][1]);
                aPh[ks][1] = packh2(f[t0][2], f[t0][3]);
                aPh[ks][2] = packh2(f[t1][0], f[t1][1]);
                aPh[ks][3] = packh2(f[t1][2], f[t1][3]);
            }

#pragma unroll
            for (int dg = 0; dg < 8; dg++) {
                oacc[dg][0] *= rsc0; oacc[dg][1] *= rsc0;
                oacc[dg][2] *= rsc1; oacc[dg][3] *= rsc1;
            }

            // PV: m16 x d64, k=32 (2 ksteps), single-term P
#pragma unroll
            for (int ks = 0; ks < 2; ks++) {
#pragma unroll
                for (int dgp = 0; dgp < 4; dgp++) {
                    uint32_t bv[4];
                    ldsm_x4t(bv, uV + SW128(vb + (uint32_t)(dgp * 32) +
                                            (uint32_t)(ks * 2048)));
                    mma16816(oacc[dgp * 2],     aPh[ks], bv[0], bv[1]);
                    mma16816(oacc[dgp * 2 + 1], aPh[ks], bv[2], bv[3]);
                }
            }
        }
    }
#undef LOAD_KV64

    float inv0 = 1.f / l0, inv1 = 1.f / l1;
    int row0 = i0 + wm * 16 + r;
#pragma unroll
    for (int dg = 0; dg < 8; dg++) {
        int c = dg * 8 + cq * 2;
        size_t o0 = ((size_t)(b * S_LEN + row0)) * EMB + h * HDIM + c;
        size_t o1 = ((size_t)(b * S_LEN + row0 + 8)) * EMB + h * HDIM + c;
        float2 v0; v0.x = oacc[dg][0] * inv0; v0.y = oacc[dg][1] * inv0;
        float2 v1; v1.x = oacc[dg][2] * inv1; v1.y = oacc[dg][3] * inv1;
        *(float2*)(out + o0) = v0;
        *(float2*)(out + o1) = v1;
    }
}

// ---------------- Global rows: split-K partial flash ----------------
__global__ __launch_bounds__(256, 2) void global_part_kernel(
    const float* __restrict__ qg, const float* __restrict__ kg,
    const float* __restrict__ vg,
    float* __restrict__ po, float* __restrict__ pm, float* __restrict__ pl)
{
    __shared__ float ks[32][68];
    __shared__ float vs[32][68];
    __shared__ float sc[32][36];

    int seg = blockIdx.x, h = blockIdx.y, b = blockIdx.z;
    int t = threadIdx.x;
    int qi = t >> 3, sub = t & 7;

    u64 q2[32];
    {
        const ulonglong2* qrow = (const ulonglong2*)
            (qg + ((size_t)(b * GLB + qi)) * EMB + h * HDIM);
#pragma unroll
        for (int e = 0; e < 16; e++) {
            ulonglong2 t2 = qrow[e];
            q2[e * 2] = t2.x; q2[e * 2 + 1] = t2.y;
        }
    }
    u64 acc2[4] = {0ULL, 0ULL, 0ULL, 0ULL};
    float m_run = -1e30f, l_run = 0.f;

    for (int c = 0; c < SEGLEN / 32; c++) {
        int kstart = seg * SEGLEN + c * 32;
        __syncthreads();
        for (int u = t; u < 32 * 16; u += 256) {
            int r = u >> 4, cc = (u & 15) << 2;
            size_t off = ((size_t)(b * S_LEN + kstart + r)) * EMB + h * HDIM + cc;
            *(float4*)&ks[r][cc] = *(const float4*)(kg + off);
            *(float4*)&vs[r][cc] = *(const float4*)(vg + off);
        }
        __syncthreads();

        float sv[4];
#pragma unroll
        for (int u2 = 0; u2 < 4; u2++) {
            int j = sub * 4 + u2;
            const ulonglong2* kr = (const ulonglong2*)&ks[j][0];
            u64 s0 = 0ULL, s1 = 0ULL, s2 = 0ULL, s3 = 0ULL;
#pragma unroll
            for (int e = 0; e < 16; e += 2) {
                ulonglong2 ka = kr[e];
                ulonglong2 kb = kr[e + 1];
                s0 = ffma2(q2[e * 2],     ka.x, s0);
                s1 = ffma2(q2[e * 2 + 1], ka.y, s1);
                s2 = ffma2(q2[e * 2 + 2], kb.x, s2);
                s3 = ffma2(q2[e * 2 + 3], kb.y, s3);
            }
            float2 r2 = up2(fadd2(fadd2(s0, s1), fadd2(s2, s3)));
            sv[u2] = r2.x + r2.y;
        }
        float cm = fmaxf(fmaxf(sv[0], sv[1]), fmaxf(sv[2], sv[3]));
        cm = fmaxf(cm, __shfl_xor_sync(0xffffffffu, cm, 1));
        cm = fmaxf(cm, __shfl_xor_sync(0xffffffffu, cm, 2));
        cm = fmaxf(cm, __shfl_xor_sync(0xffffffffu, cm, 4));
        float m_new = fmaxf(m_run, cm);
        float rsc = __expf(m_run - m_new);
        float psum = 0.f;
#pragma unroll
        for (int u2 = 0; u2 < 4; u2++) {
            float e = __expf(sv[u2] - m_new);
            sc[qi][sub * 4 + u2] = e;
            psum += e;
        }
        psum += __shfl_xor_sync(0xffffffffu, psum, 1);
        psum += __shfl_xor_sync(0xffffffffu, psum, 2);
        psum += __shfl_xor_sync(0xffffffffu, psum, 4);
        l_run = l_run * rsc + psum;
        m_run = m_new;
        __syncwarp();

        u64 rb = dup2(rsc);
#pragma unroll
        for (int d = 0; d < 4; d++) acc2[d] = fmul2(acc2[d], rb);
#pragma unroll 4
        for (int j = 0; j < 32; j++) {
            u64 eb = dup2(sc[qi][j]);
            ulonglong2 v0 = *(const ulonglong2*)&vs[j][sub * 4];
            ulonglong2 v1 = *(const ulonglong2*)&vs[j][sub * 4 + 32];
            acc2[0] = ffma2(eb, v0.x, acc2[0]);
            acc2[1] = ffma2(eb, v0.y, acc2[1]);
            acc2[2] = ffma2(eb, v1.x, acc2[2]);
            acc2[3] = ffma2(eb, v1.y, acc2[3]);
        }
    }

    size_t pidx = (((size_t)seg * BATCH + b) * NH + h) * GLB + qi;
    float2 a0 = up2(acc2[0]), a1 = up2(acc2[1]);
    float2 a2 = up2(acc2[2]), a3 = up2(acc2[3]);
    float* prow = po + pidx * HDIM;
    *(float4*)(prow + sub * 4)      = make_float4(a0.x, a0.y, a1.x, a1.y);
    *(float4*)(prow + 32 + sub * 4) = make_float4(a2.x, a2.y, a3.x, a3.y);
    if (sub == 0) { pm[pidx] = m_run; pl[pidx] = l_run; }
}

__global__ __launch_bounds__(64) void global_merge_kernel(
    const float* __restrict__ po, const float* __restrict__ pm,
    const float* __restrict__ pl, float* __restrict__ out)
{
    int g = blockIdx.x, h = blockIdx.y, b = blockIdx.z;
    int d = threadIdx.x;

    float mv[NSEG];
    float mx = -1e30f;
#pragma unroll
    for (int s = 0; s < NSEG; s++) {
        mv[s] = pm[(((size_t)s * BATCH + b) * NH + h) * GLB + g];
        mx = fmaxf(mx, mv[s]);
    }
    float num = 0.f, den = 0.f;
#pragma unroll
    for (int s = 0; s < NSEG; s++) {
        size_t pidx = (((size_t)s * BATCH + b) * NH + h) * GLB + g;
        float w = __expf(mv[s] - mx);
        num += w * po[pidx * HDIM + d];
        den += w * pl[pidx];
    }
    out[((size_t)(b * S_LEN + g)) * EMB + h * HDIM + d] = num / den;
}

// ---------------- launch ----------------
extern "C" void kernel_launch(void* const* d_in, const int* in_sizes, int n_in,
                              void* d_out, int out_size)
{
    (void)n_in; (void)out_size;
    int base = (in_sizes[2] == EMB * EMB) ? 2 : 3;

    const float* x    = (const float*)d_in[0];
    const int*   mask = (const int*)d_in[1];
    const float* wq   = (const float*)d_in[base + 0];
    const float* bq   = (const float*)d_in[base + 1];
    const float* wk   = (const float*)d_in[base + 2];
    const float* bk   = (const float*)d_in[base + 3];
    const float* wv   = (const float*)d_in[base + 4];
    const float* bv   = (const float*)d_in[base + 5];
    const float* wqg  = (const float*)d_in[base + 6];
    const float* bqg  = (const float*)d_in[base + 7];
    const float* wkg  = (const float*)d_in[base + 8];
    const float* bkg  = (const float*)d_in[base + 9];
    const float* wvg  = (const float*)d_in[base + 10];
    const float* bvg  = (const float*)d_in[base + 11];
    float* out = (float*)d_out;

    float *kg, *vg, *qg, *po, *pm, *pl;
    __half *xh, *xl, *wt, *q1, *q2, *k1, *v1;
    cudaGetSymbolAddress((void**)&kg, g_kg);
    cudaGetSymbolAddress((void**)&vg, g_vg);
    cudaGetSymbolAddress((void**)&qg, g_qg);
    cudaGetSymbolAddress((void**)&xh, g_xh);
    cudaGetSymbolAddress((void**)&xl, g_xl);
    cudaGetSymbolAddress((void**)&wt, g_wt);
    cudaGetSymbolAddress((void**)&q1, g_q1);
    cudaGetSymbolAddress((void**)&q2, g_q2);
    cudaGetSymbolAddress((void**)&k1, g_k1);
    cudaGetSymbolAddress((void**)&v1, g_v1);
    cudaGetSymbolAddress((void**)&po, g_po);
    cudaGetSymbolAddress((void**)&pm, g_pm);
    cudaGetSymbolAddress((void**)&pl, g_pl);

    cudaFuncSetAttribute(mma_gemm6_kernel,
                         cudaFuncAttributeMaxDynamicSharedMemorySize, GSM2);
    cudaFuncSetAttribute(local_attn_mma,
                         cudaFuncAttributeMaxDynamicSharedMemorySize, LL_TOTAL);

    convx_kernel<<<(BATCH * S_LEN * EMB) / (256 * 4), 256>>>(x, xh, xl);
    convw_kernel<<<dim3(EMB / 32, EMB / 32, 6), 256>>>(
        wq, wk, wv, wkg, wvg, wqg, wt);
    mma_gemm6_kernel<<<dim3(EMB / 128, BATCH * S_LEN / 128, 6), 256, GSM2>>>(
        xh, xl, wt, bq, bk, bv, bkg, bvg, bqg,
        q1, q2, k1, v1, kg, vg, qg);
    local_attn_mma<<<dim3(S_LEN / QTL, NH, BATCH), 256, LL_TOTAL>>>(
        q1, q2, k1, v1, mask, out);
    global_part_kernel<<<dim3(NSEG, NH, BATCH), 256>>>(qg, kg, vg, po, pm, pl);
    global_merge_kernel<<<dim3(GLB, NH, BATCH), 64>>>(po, pm, pl, out);
}

// round 17
// speedup vs baseline: 1.3314x; 1.0889x over previous
#include <cuda_runtime.h>
#include <cuda_fp16.h>
#include <cstdint>

#define S_LEN 4096
#define BATCH 2
#define EMB   768
#define NH    12
#define HDIM  64
#define WIN   256
#define GLB   32
#define QTL   128
#define NSEG  16
#define SEGLEN (S_LEN / NSEG)
#define NLOC  (S_LEN / QTL)     // 32 local tiles per (b,h)

typedef unsigned long long u64;

// ---------- packed f32x2 helpers ----------
__device__ __forceinline__ u64 pk2(float x, float y) {
    u64 r; asm("mov.b64 %0, {%1,%2};" : "=l"(r) : "f"(x), "f"(y)); return r;
}
__device__ __forceinline__ u64 dup2(float x) { return pk2(x, x); }
__device__ __forceinline__ float2 up2(u64 v) {
    float2 f; asm("mov.b64 {%0,%1}, %2;" : "=f"(f.x), "=f"(f.y) : "l"(v)); return f;
}
__device__ __forceinline__ u64 ffma2(u64 a, u64 b, u64 c) {
    u64 d; asm("fma.rn.f32x2 %0, %1, %2, %3;" : "=l"(d) : "l"(a), "l"(b), "l"(c)); return d;
}
__device__ __forceinline__ u64 fadd2(u64 a, u64 b) {
    u64 d; asm("add.rn.f32x2 %0, %1, %2;" : "=l"(d) : "l"(a), "l"(b)); return d;
}
__device__ __forceinline__ u64 fmul2(u64 a, u64 b) {
    u64 d; asm("mul.rn.f32x2 %0, %1, %2;" : "=l"(d) : "l"(a), "l"(b)); return d;
}

__device__ __forceinline__ uint32_t smem_to_u32(const void* p) {
    uint32_t a;
    asm("{ .reg .u64 t; cvta.to.shared.u64 t, %1; cvt.u32.u64 %0, t; }" : "=r"(a) : "l"(p));
    return a;
}
#define SW128(o) ((o) ^ (((o) >> 3) & 0x70))

#define CP16(dst, src) \
    asm volatile("cp.async.cg.shared.global [%0], [%1], 16;" \
                 :: "r"(dst), "l"(src) : "memory")
#define CPZ16(dst, src, pred) do { \
    int _sz = (pred) ? 16 : 0; \
    asm volatile("cp.async.cg.shared.global [%0], [%1], 16, %2;" \
                 :: "r"(dst), "l"(src), "r"(_sz) : "memory"); } while (0)
#define CPZ4(dst, src, pred) do { \
    int _sz = (pred) ? 4 : 0; \
    asm volatile("cp.async.ca.shared.global [%0], [%1], 4, %2;" \
                 :: "r"(dst), "l"(src), "r"(_sz) : "memory"); } while (0)
#define CP_COMMIT() asm volatile("cp.async.commit_group;" ::: "memory")
#define CP_WAIT1()  asm volatile("cp.async.wait_group 1;" ::: "memory")

__device__ __forceinline__ void ldsm_x4(uint32_t* r, uint32_t addr) {
    asm volatile("ldmatrix.sync.aligned.m8n8.x4.shared.b16 {%0,%1,%2,%3}, [%4];"
                 : "=r"(r[0]), "=r"(r[1]), "=r"(r[2]), "=r"(r[3]) : "r"(addr));
}
__device__ __forceinline__ void ldsm_x4t(uint32_t* r, uint32_t addr) {
    asm volatile("ldmatrix.sync.aligned.m8n8.x4.trans.shared.b16 {%0,%1,%2,%3}, [%4];"
                 : "=r"(r[0]), "=r"(r[1]), "=r"(r[2]), "=r"(r[3]) : "r"(addr));
}
// fp16 mma, fp32 accum
__device__ __forceinline__ void mma16816(float* c, const uint32_t* a,
                                         uint32_t b0, uint32_t b1) {
    asm volatile(
        "mma.sync.aligned.m16n8k16.row.col.f32.f16.f16.f32 "
        "{%0,%1,%2,%3}, {%4,%5,%6,%7}, {%8,%9}, {%0,%1,%2,%3};"
        : "+f"(c[0]), "+f"(c[1]), "+f"(c[2]), "+f"(c[3])
        : "r"(a[0]), "r"(a[1]), "r"(a[2]), "r"(a[3]), "r"(b0), "r"(b1));
}
__device__ __forceinline__ uint32_t packh2(float a, float b) {
    __half2 h; h.x = __float2half(a); h.y = __float2half(b);
    return *(uint32_t*)&h;
}

// -------- scratch --------
__device__ float g_kg[BATCH * S_LEN * EMB];
__device__ float g_vg[BATCH * S_LEN * EMB];
__device__ float g_qg[BATCH * GLB * EMB];
__device__ __half g_xh[BATCH * S_LEN * EMB];
__device__ __half g_xl[BATCH * S_LEN * EMB];
__device__ __half g_wt[6 * EMB * EMB];
__device__ __half g_q1[BATCH * S_LEN * EMB];
__device__ __half g_q2[BATCH * S_LEN * EMB];
__device__ __half g_k1[BATCH * S_LEN * EMB];
__device__ __half g_v1[BATCH * S_LEN * EMB];
__device__ float g_po[NSEG * BATCH * NH * GLB * HDIM];
__device__ float g_pm[NSEG * BATCH * NH * GLB];
__device__ float g_pl[NSEG * BATCH * NH * GLB];

// ---------------- fused prep: x -> fp16 hi/lo  AND  W -> W^T fp16 ----------
#define NXBLK (BATCH * S_LEN * EMB / (256 * 4))   // 6144
#define NWB   (EMB / 32)                          // 24

__global__ __launch_bounds__(256) void prep_kernel(
    const float* __restrict__ x, __half* __restrict__ xh,
    __half* __restrict__ xl,
    const float* __restrict__ w0, const float* __restrict__ w1,
    const float* __restrict__ w2, const float* __restrict__ w3,
    const float* __restrict__ w4, const float* __restrict__ w5,
    __half* __restrict__ wt)
{
    __shared__ float tile[32][33];
    int bx = blockIdx.x;
    if (bx < NXBLK) {
        int i = (bx * 256 + threadIdx.x) * 4;
        float4 a = *(const float4*)(x + i);
        __half h[4], l[4];
        float av[4] = {a.x, a.y, a.z, a.w};
#pragma unroll
        for (int j = 0; j < 4; j++) {
            h[j] = __float2half(av[j]);
            l[j] = __float2half(av[j] - __half2float(h[j]));
        }
        *(uint2*)(xh + i) = *(const uint2*)h;
        *(uint2*)(xl + i) = *(const uint2*)l;
    } else {
        int bz = bx - NXBLK;
        int z = bz / (NWB * NWB);
        int rem = bz % (NWB * NWB);
        int by = rem / NWB, bxx = rem % NWB;
        const float* W = (z == 0) ? w0 : (z == 1) ? w1 : (z == 2) ? w2 :
                         (z == 3) ? w3 : (z == 4) ? w4 : w5;
        int kb = by * 32, nb = bxx * 32;
        int tx = threadIdx.x & 31, ty = threadIdx.x >> 5;
        for (int i = ty; i < 32; i += 8)
            tile[i][tx] = W[(size_t)(kb + i) * EMB + nb + tx];
        __syncthreads();
        for (int j = ty; j < 32; j += 8) {
            size_t o = (size_t)z * EMB * EMB + (size_t)(nb + j) * EMB + kb + tx;
            wt[o] = __float2half(tile[tx][j]);
        }
    }
}

// ------- mma.sync GEMM: 128x128 CTA, 256 thr, warp 32x64, k-chunk 64 -------
// z=0 (q) and z=5 (qg): 2-term (xh+xl). z=1..4 (k,v,kg,vg): 1-term (xh only).
#define GST  49152
#define GSM2 (2 * GST)

__global__ __launch_bounds__(256, 2) void mma_gemm6_kernel(
    const __half* __restrict__ xh, const __half* __restrict__ xl,
    const __half* __restrict__ wt,
    const float* __restrict__ bq, const float* __restrict__ bk,
    const float* __restrict__ bv, const float* __restrict__ bkg,
    const float* __restrict__ bvg, const float* __restrict__ bqg,
    __half* q1, __half* q2, __half* k1, __half* v1,
    float* kg, float* vg, float* qg)
{
    extern __shared__ char dsm[];
    int z = blockIdx.z;
    if (z == 5 && blockIdx.y > 0) return;
    int t = threadIdx.x, wid = t >> 5, lane = t & 31;
    int m0 = blockIdx.y * 128, n0 = blockIdx.x * 128;
    int wm = wid & 3, wn = wid >> 2;
    bool twot = (z == 0 || z == 5);

    const float* bias;
    switch (z) {
        case 0:  bias = bq;  break;
        case 1:  bias = bk;  break;
        case 2:  bias = bv;  break;
        case 3:  bias = bkg; break;
        case 4:  bias = bvg; break;
        default: bias = bqg; break;
    }
    float scale = (z == 0 || z == 5) ? 0.125f : 1.0f;
    const __half* Bw = wt + (size_t)z * EMB * EMB;

    uint32_t sb = smem_to_u32(dsm);

    float acc[2][8][4];
#pragma unroll
    for (int mi = 0; mi < 2; mi++)
#pragma unroll
        for (int ni = 0; ni < 8; ni++)
#pragma unroll
            for (int c = 0; c < 4; c++) acc[mi][ni][c] = 0.f;

    uint32_t a_off[2], b_off[4];
#pragma unroll
    for (int mi = 0; mi < 2; mi++) {
        int row = wm * 32 + mi * 16 + (lane & 15);
        a_off[mi] = (uint32_t)(row * 128) + ((lane >> 4) << 4);
    }
#pragma unroll
    for (int bi = 0; bi < 4; bi++) {
        int row = wn * 64 + bi * 16 + (lane & 15);
        b_off[bi] = (uint32_t)(row * 128) + ((lane >> 4) << 4);
    }

#define LOAD_STAGE(chunk, s) do {                                            \
        int k0 = (chunk) * 64;                                               \
        uint32_t base = sb + (s) * GST;                                      \
        _Pragma("unroll")                                                    \
        for (int i = 0; i < 4; i++) {                                        \
            int idx = t + i * 256;                                           \
            int r = idx >> 3, u = idx & 7;                                   \
            uint32_t sw = SW128((uint32_t)(r * 128 + u * 16));               \
            size_t arow;                                                     \
            if (z == 5) { int q2r = r & 63;                                  \
                arow = (size_t)((q2r >> 5) * S_LEN + (q2r & 31)); }          \
            else arow = (size_t)(m0 + r);                                    \
            CP16(base + sw,         xh + arow * EMB + k0 + u * 8);           \
            if (twot)                                                        \
                CP16(base + 16384 + sw, xl + arow * EMB + k0 + u * 8);       \
            CP16(base + 32768 + sw, Bw + (size_t)(n0 + r) * EMB + k0 + u * 8); \
        }                                                                    \
    } while (0)

    LOAD_STAGE(0, 0);
    CP_COMMIT();

    for (int c = 0; c < 12; c++) {
        if (c < 11) LOAD_STAGE(c + 1, (c + 1) & 1);
        CP_COMMIT();
        CP_WAIT1();
        __syncthreads();
        uint32_t base = sb + (c & 1) * GST;
        uint32_t uAh = base, uAl = base + 16384;
        uint32_t uB  = base + 32768;
#pragma unroll
        for (int ks = 0; ks < 4; ks++) {
            uint32_t kb = (uint32_t)(ks * 32);
            uint32_t ah[2][4], al[2][4];
#pragma unroll
            for (int mi = 0; mi < 2; mi++) {
                uint32_t sw = SW128(a_off[mi] + kb);
                ldsm_x4(ah[mi], uAh + sw);
                if (twot) ldsm_x4(al[mi], uAl + sw);
            }
#pragma unroll
            for (int bi = 0; bi < 4; bi++) {
                uint32_t bw[4];
                ldsm_x4(bw, uB + SW128(b_off[bi] + kb));
#pragma unroll
                for (int sel = 0; sel < 2; sel++) {
                    int ni = bi * 2 + sel;
#pragma unroll
                    for (int mi = 0; mi < 2; mi++) {
                        mma16816(acc[mi][ni], ah[mi], bw[sel], bw[sel + 2]);
                        if (twot)
                            mma16816(acc[mi][ni], al[mi], bw[sel], bw[sel + 2]);
                    }
                }
            }
        }
        __syncthreads();
    }
#undef LOAD_STAGE

    int r = lane >> 2, cp = (lane & 3) * 2;
    if (z == 0) {
#pragma unroll
        for (int mi = 0; mi < 2; mi++) {
            int mbase = m0 + wm * 32 + mi * 16;
#pragma unroll
            for (int ni = 0; ni < 8; ni++) {
                int nbase = n0 + wn * 64 + ni * 8 + cp;
                float b0 = bias[nbase], b1 = bias[nbase + 1];
#pragma unroll
                for (int hr = 0; hr < 2; hr++) {
                    int row = mbase + r + hr * 8;
                    float v0 = (acc[mi][ni][hr * 2 + 0] + b0) * scale;
                    float v1 = (acc[mi][ni][hr * 2 + 1] + b1) * scale;
                    __half h0 = __float2half(v0);
                    __half h1 = __float2half(v1);
                    __half l0 = __float2half(v0 - __half2float(h0));
                    __half l1 = __float2half(v1 - __half2float(h1));
                    __half ph[2] = {h0, h1}, pl[2] = {l0, l1};
                    *(uint32_t*)(q1 + (size_t)row * EMB + nbase) = *(uint32_t*)ph;
                    *(uint32_t*)(q2 + (size_t)row * EMB + nbase) = *(uint32_t*)pl;
                }
            }
        }
    } else if (z == 1 || z == 2) {
        __half* Y = (z == 1) ? k1 : v1;
#pragma unroll
        for (int mi = 0; mi < 2; mi++) {
            int mbase = m0 + wm * 32 + mi * 16;
#pragma unroll
            for (int ni = 0; ni < 8; ni++) {
                int nbase = n0 + wn * 64 + ni * 8 + cp;
                float b0 = bias[nbase], b1 = bias[nbase + 1];
#pragma unroll
                for (int hr = 0; hr < 2; hr++) {
                    int row = mbase + r + hr * 8;
                    __half ph[2];
                    ph[0] = __float2half(acc[mi][ni][hr * 2 + 0] + b0);
                    ph[1] = __float2half(acc[mi][ni][hr * 2 + 1] + b1);
                    *(uint32_t*)(Y + (size_t)row * EMB + nbase) = *(uint32_t*)ph;
                }
            }
        }
    } else {
        float* Y = (z == 3) ? kg : (z == 4) ? vg : qg;
#pragma unroll
        for (int mi = 0; mi < 2; mi++) {
            int mbase = m0 + wm * 32 + mi * 16;
#pragma unroll
            for (int ni = 0; ni < 8; ni++) {
                int nbase = n0 + wn * 64 + ni * 8 + cp;
                float b0 = bias[nbase], b1 = bias[nbase + 1];
#pragma unroll
                for (int hr = 0; hr < 2; hr++) {
                    int row = mbase + r + hr * 8;
                    if (z == 5 && row >= BATCH * GLB) continue;
                    float2 o;
                    o.x = (acc[mi][ni][hr * 2 + 0] + b0) * scale;
                    o.y = (acc[mi][ni][hr * 2 + 1] + b1) * scale;
                    *(float2*)(Y + (size_t)row * EMB + nbase) = o;
                }
            }
        }
    }
}

// ------- Local attention path (flash-v2, Q-tile 128, 64-key stages) -------
#define LL_QH 0
#define LL_QL 16384
#define LL_K  32768           // + s*8192 (64 rows)
#define LL_V  49152           // + s*8192
#define LL_MS 65536           // int[2][64]
#define LL_TOTAL 66048

__device__ void local_attn_path(
    char* lsm, int bx,
    const __half* __restrict__ q1, const __half* __restrict__ q2,
    const __half* __restrict__ k1, const __half* __restrict__ v1,
    const int* __restrict__ mask, float* __restrict__ out)
{
    uint32_t sbase = smem_to_u32(lsm);
    int* msk = (int*)(lsm + LL_MS);

    int b = blockIdx.z, h = blockIdx.y, i0 = bx * QTL;
    int t = threadIdx.x, wm = t >> 5, lane = t & 31;
    int r = lane >> 2, cq = lane & 3;

#pragma unroll
    for (int i = 0; i < 4; i++) {
        int idx = t + i * 256;
        int row = idx >> 3, u = idx & 7;
        size_t g = ((size_t)(b * S_LEN + i0 + row)) * EMB + h * HDIM + u * 8;
        uint32_t sw = SW128((uint32_t)(row * 128 + u * 16));
        *(uint4*)(lsm + LL_QH + sw) = *(const uint4*)(q1 + g);
        *(uint4*)(lsm + LL_QL + sw) = *(const uint4*)(q2 + g);
    }

    int lo = i0 - WIN; if (lo < 0) lo = 0;
    int hi = i0 + QTL - 1 + WIN; if (hi > S_LEN - 1) hi = S_LEN - 1;
    int wstart = lo & ~63;
    int nst = (hi - wstart) / 64 + 1;

#define LOAD_KV64(kstart_, s_) do {                                          \
        _Pragma("unroll")                                                    \
        for (int i_ = 0; i_ < 2; i_++) {                                     \
            int idx_ = t + i_ * 256;                                         \
            int r_ = idx_ >> 3, u_ = idx_ & 7;                               \
            int p_ = (kstart_) + r_;                                         \
            int ok_ = p_ < S_LEN;                                            \
            int pc_ = ok_ ? p_ : (S_LEN - 1);                                \
            size_t g_ = ((size_t)(b * S_LEN + pc_)) * EMB + h * HDIM + u_ * 8; \
            uint32_t sw_ = SW128((uint32_t)(r_ * 128 + u_ * 16));            \
            CPZ16(sbase + LL_K + (s_) * 8192 + sw_, k1 + g_, ok_);           \
            CPZ16(sbase + LL_V + (s_) * 8192 + sw_, v1 + g_, ok_);           \
        }                                                                    \
        if (t < 64) {                                                        \
            int p2_ = (kstart_) + t;                                         \
            int ok2_ = p2_ < S_LEN;                                          \
            const int* ms_ = mask + b * S_LEN + (ok2_ ? p2_ : (S_LEN - 1));  \
            CPZ4(sbase + LL_MS + (s_) * 256 + t * 4, ms_, ok2_);             \
        }                                                                    \
    } while (0)

    LOAD_KV64(0, 0);
    CP_COMMIT();

    uint32_t aoff = (uint32_t)((wm * 16 + (lane & 15)) * 128 + ((lane >> 4) << 4));
    uint32_t koff0 = (uint32_t)(((lane & 15)) * 128 + ((lane >> 4) << 4));
    uint32_t koff1 = (uint32_t)((16 + (lane & 15)) * 128 + ((lane >> 4) << 4));
    int vtile = lane >> 3, vrow = lane & 7;
    uint32_t vb = (uint32_t)(((vtile & 1) * 8 + vrow) * 128 + ((vtile >> 1) << 4));

    __syncthreads();
    uint32_t qfh[4][4], qfl[4][4];
#pragma unroll
    for (int ks = 0; ks < 4; ks++) {
        uint32_t kb = (uint32_t)(ks * 32);
        ldsm_x4(qfh[ks], sbase + LL_QH + SW128(aoff + kb));
        ldsm_x4(qfl[ks], sbase + LL_QL + SW128(aoff + kb));
    }

    float oacc[8][4];
#pragma unroll
    for (int dg = 0; dg < 8; dg++)
#pragma unroll
        for (int c = 0; c < 4; c++) oacc[dg][c] = 0.f;
    float m0 = -1e30f, m1 = -1e30f, l0 = 0.f, l1 = 0.f;

    int iq0 = i0 + wm * 16 + r;
    int iq_lo = i0 + wm * 16, iq_hi = iq_lo + 15;

    for (int st = -1; st < nst; st++) {
        bool gl = (st < 0);
        int s = (st + 1) & 1;

        __syncthreads();
        if (st + 1 < nst) LOAD_KV64(wstart + (st + 1) * 64, s ^ 1);
        CP_COMMIT();
        CP_WAIT1();
        __syncthreads();

        int nsub = gl ? 1 : 2;
        int kbase = gl ? 0 : wstart + st * 64;

        for (int sub = 0; sub < nsub; sub++) {
            int kstart = kbase + sub * 32;
            uint32_t uK = sbase + LL_K + s * 8192 + (uint32_t)(sub * 4096);
            uint32_t uV = sbase + LL_V + s * 8192 + (uint32_t)(sub * 4096);
            const int* mskS = msk + s * 64 + sub * 32;

            // QK: m16 x n32, K=64, 2-term
            float f[4][4];
#pragma unroll
            for (int nt = 0; nt < 4; nt++)
#pragma unroll
                for (int c = 0; c < 4; c++) f[nt][c] = 0.f;
#pragma unroll
            for (int ks = 0; ks < 4; ks++) {
                uint32_t kb = (uint32_t)(ks * 32);
                uint32_t bw0[4], bw1[4];
                ldsm_x4(bw0, uK + SW128(koff0 + kb));
                ldsm_x4(bw1, uK + SW128(koff1 + kb));
                mma16816(f[0], qfh[ks], bw0[0], bw0[2]);
                mma16816(f[0], qfl[ks], bw0[0], bw0[2]);
                mma16816(f[1], qfh[ks], bw0[1], bw0[3]);
                mma16816(f[1], qfl[ks], bw0[1], bw0[3]);
                mma16816(f[2], qfh[ks], bw1[0], bw1[2]);
                mma16816(f[2], qfl[ks], bw1[0], bw1[2]);
                mma16816(f[3], qfh[ks], bw1[1], bw1[3]);
                mma16816(f[3], qfl[ks], bw1[1], bw1[3]);
            }

            if (!gl) {
                bool all_valid = (kstart >= iq_hi - WIN) &&
                                 (kstart + 31 <= iq_lo + WIN) &&
                                 (kstart + 31 < S_LEN);
                if (all_valid) {
#pragma unroll
                    for (int nt = 0; nt < 4; nt++)
#pragma unroll
                        for (int cc = 0; cc < 2; cc++) {
                            int j = nt * 8 + cq * 2 + cc;
                            float pen = mskS[j] ? -10000.f : 0.f;
                            f[nt][cc]     += pen;
                            f[nt][2 + cc] += pen;
                        }
                } else {
#pragma unroll
                    for (int nt = 0; nt < 4; nt++)
#pragma unroll
                        for (int cc = 0; cc < 2; cc++) {
                            int j = nt * 8 + cq * 2 + cc;
                            int p = kstart + j;
                            float pen = mskS[j] ? -10000.f : 0.f;
                            bool okp = (p < S_LEN);
                            bool v0 = okp && (p >= iq0 - WIN) && (p <= iq0 + WIN);
                            bool v1v = okp && (p >= iq0 + 8 - WIN) && (p <= iq0 + 8 + WIN);
                            f[nt][cc]     = v0  ? f[nt][cc] + pen     : -1e30f;
                            f[nt][2 + cc] = v1v ? f[nt][2 + cc] + pen : -1e30f;
                        }
                }
            }

            // row-wise online softmax
            float mx0 = fmaxf(fmaxf(f[0][0], f[0][1]), fmaxf(f[1][0], f[1][1]));
            mx0 = fmaxf(mx0, fmaxf(fmaxf(f[2][0], f[2][1]), fmaxf(f[3][0], f[3][1])));
            float mx1 = fmaxf(fmaxf(f[0][2], f[0][3]), fmaxf(f[1][2], f[1][3]));
            mx1 = fmaxf(mx1, fmaxf(fmaxf(f[2][2], f[2][3]), fmaxf(f[3][2], f[3][3])));
            mx0 = fmaxf(mx0, __shfl_xor_sync(0xffffffffu, mx0, 1));
            mx0 = fmaxf(mx0, __shfl_xor_sync(0xffffffffu, mx0, 2));
            mx1 = fmaxf(mx1, __shfl_xor_sync(0xffffffffu, mx1, 1));
            mx1 = fmaxf(mx1, __shfl_xor_sync(0xffffffffu, mx1, 2));
            float mn0 = fmaxf(m0, mx0), mn1 = fmaxf(m1, mx1);
            float rsc0 = __expf(m0 - mn0), rsc1 = __expf(m1 - mn1);
            float s0 = 0.f, s1 = 0.f;
#pragma unroll
            for (int nt = 0; nt < 4; nt++) {
#pragma unroll
                for (int cc = 0; cc < 2; cc++) {
                    float e0 = __expf(f[nt][cc] - mn0);
                    float e1 = __expf(f[nt][2 + cc] - mn1);
                    f[nt][cc] = e0; f[nt][2 + cc] = e1;
                    s0 += e0; s1 += e1;
                }
            }
            s0 += __shfl_xor_sync(0xffffffffu, s0, 1);
            s0 += __shfl_xor_sync(0xffffffffu, s0, 2);
            s1 += __shfl_xor_sync(0xffffffffu, s1, 1);
            s1 += __shfl_xor_sync(0xffffffffu, s1, 2);
            l0 = l0 * rsc0 + s0; m0 = mn0;
            l1 = l1 * rsc1 + s1; m1 = mn1;

            // pack P (single fp16) into A-fragments
            uint32_t aPh[2][4];
#pragma unroll
            for (int ks = 0; ks < 2; ks++) {
                int t0 = 2 * ks, t1 = 2 * ks + 1;
                aPh[ks][0] = packh2(f[t0][0], f[t0][1]);
                aPh[ks][1] = packh2(f[t0][2], f[t0][3]);
                aPh[ks][2] = packh2(f[t1][0], f[t1][1]);
                aPh[ks][3] = packh2(f[t1][2], f[t1][3]);
            }

#pragma unroll
            for (int dg = 0; dg < 8; dg++) {
                oacc[dg][0] *= rsc0; oacc[dg][1] *= rsc0;
                oacc[dg][2] *= rsc1; oacc[dg][3] *= rsc1;
            }

            // PV: m16 x d64, k=32 (2 ksteps), single-term P
#pragma unroll
            for (int ks = 0; ks < 2; ks++) {
#pragma unroll
                for (int dgp = 0; dgp < 4; dgp++) {
                    uint32_t bv[4];
                    ldsm_x4t(bv, uV + SW128(vb + (uint32_t)(dgp * 32) +
                                            (uint32_t)(ks * 2048)));
                    mma16816(oacc[dgp * 2],     aPh[ks], bv[0], bv[1]);
                    mma16816(oacc[dgp * 2 + 1], aPh[ks], bv[2], bv[3]);
                }
            }
        }
    }
#undef LOAD_KV64

    float inv0 = 1.f / l0, inv1 = 1.f / l1;
    int row0 = i0 + wm * 16 + r;
#pragma unroll
    for (int dg = 0; dg < 8; dg++) {
        int c = dg * 8 + cq * 2;
        size_t o0 = ((size_t)(b * S_LEN + row0)) * EMB + h * HDIM + c;
        size_t o1 = ((size_t)(b * S_LEN + row0 + 8)) * EMB + h * HDIM + c;
        float2 v0; v0.x = oacc[dg][0] * inv0; v0.y = oacc[dg][1] * inv0;
        float2 v1; v1.x = oacc[dg][2] * inv1; v1.y = oacc[dg][3] * inv1;
        *(float2*)(out + o0) = v0;
        *(float2*)(out + o1) = v1;
    }
}

// ------- Global rows path: split-K partial flash (uses dynamic smem) -------
__device__ void global_part_path(
    char* lsm, int seg,
    const float* __restrict__ qg, const float* __restrict__ kg,
    const float* __restrict__ vg,
    float* __restrict__ po, float* __restrict__ pm, float* __restrict__ pl)
{
    float (*ks)[68] = (float(*)[68])(lsm);
    float (*vs)[68] = (float(*)[68])(lsm + 8704);
    float (*sc)[36] = (float(*)[36])(lsm + 17408);

    int h = blockIdx.y, b = blockIdx.z;
    int t = threadIdx.x;
    int qi = t >> 3, sub = t & 7;

    u64 q2[32];
    {
        const ulonglong2* qrow = (const ulonglong2*)
            (qg + ((size_t)(b * GLB + qi)) * EMB + h * HDIM);
#pragma unroll
        for (int e = 0; e < 16; e++) {
            ulonglong2 t2 = qrow[e];
            q2[e * 2] = t2.x; q2[e * 2 + 1] = t2.y;
        }
    }
    u64 acc2[4] = {0ULL, 0ULL, 0ULL, 0ULL};
    float m_run = -1e30f, l_run = 0.f;

    for (int c = 0; c < SEGLEN / 32; c++) {
        int kstart = seg * SEGLEN + c * 32;
        __syncthreads();
        for (int u = t; u < 32 * 16; u += 256) {
            int r = u >> 4, cc = (u & 15) << 2;
            size_t off = ((size_t)(b * S_LEN + kstart + r)) * EMB + h * HDIM + cc;
            *(float4*)&ks[r][cc] = *(const float4*)(kg + off);
            *(float4*)&vs[r][cc] = *(const float4*)(vg + off);
        }
        __syncthreads();

        float sv[4];
#pragma unroll
        for (int u2 = 0; u2 < 4; u2++) {
            int j = sub * 4 + u2;
            const ulonglong2* kr = (const ulonglong2*)&ks[j][0];
            u64 s0 = 0ULL, s1 = 0ULL, s2 = 0ULL, s3 = 0ULL;
#pragma unroll
            for (int e = 0; e < 16; e += 2) {
                ulonglong2 ka = kr[e];
                ulonglong2 kb = kr[e + 1];
                s0 = ffma2(q2[e * 2],     ka.x, s0);
                s1 = ffma2(q2[e * 2 + 1], ka.y, s1);
                s2 = ffma2(q2[e * 2 + 2], kb.x, s2);
                s3 = ffma2(q2[e * 2 + 3], kb.y, s3);
            }
            float2 r2 = up2(fadd2(fadd2(s0, s1), fadd2(s2, s3)));
            sv[u2] = r2.x + r2.y;
        }
        float cm = fmaxf(fmaxf(sv[0], sv[1]), fmaxf(sv[2], sv[3]));
        cm = fmaxf(cm, __shfl_xor_sync(0xffffffffu, cm, 1));
        cm = fmaxf(cm, __shfl_xor_sync(0xffffffffu, cm, 2));
        cm = fmaxf(cm, __shfl_xor_sync(0xffffffffu, cm, 4));
        float m_new = fmaxf(m_run, cm);
        float rsc = __expf(m_run - m_new);
        float psum = 0.f;
#pragma unroll
        for (int u2 = 0; u2 < 4; u2++) {
            float e = __expf(sv[u2] - m_new);
            sc[qi][sub * 4 + u2] = e;
            psum += e;
        }
        psum += __shfl_xor_sync(0xffffffffu, psum, 1);
        psum += __shfl_xor_sync(0xffffffffu, psum, 2);
        psum += __shfl_xor_sync(0xffffffffu, psum, 4);
        l_run = l_run * rsc + psum;
        m_run = m_new;
        __syncwarp();

        u64 rb = dup2(rsc);
#pragma unroll
        for (int d = 0; d < 4; d++) acc2[d] = fmul2(acc2[d], rb);
#pragma unroll 4
        for (int j = 0; j < 32; j++) {
            u64 eb = dup2(sc[qi][j]);
            ulonglong2 v0 = *(const ulonglong2*)&vs[j][sub * 4];
            ulonglong2 v1 = *(const ulonglong2*)&vs[j][sub * 4 + 32];
            acc2[0] = ffma2(eb, v0.x, acc2[0]);
            acc2[1] = ffma2(eb, v0.y, acc2[1]);
            acc2[2] = ffma2(eb, v1.x, acc2[2]);
            acc2[3] = ffma2(eb, v1.y, acc2[3]);
        }
    }

    size_t pidx = (((size_t)seg * BATCH + b) * NH + h) * GLB + qi;
    float2 a0 = up2(acc2[0]), a1 = up2(acc2[1]);
    float2 a2 = up2(acc2[2]), a3 = up2(acc2[3]);
    float* prow = po + pidx * HDIM;
    *(float4*)(prow + sub * 4)      = make_float4(a0.x, a0.y, a1.x, a1.y);
    *(float4*)(prow + 32 + sub * 4) = make_float4(a2.x, a2.y, a3.x, a3.y);
    if (sub == 0) { pm[pidx] = m_run; pl[pidx] = l_run; }
}

// ---------------- fused attention kernel ----------------
__global__ __launch_bounds__(256, 2) void fused_attn_kernel(
    const __half* __restrict__ q1, const __half* __restrict__ q2,
    const __half* __restrict__ k1, const __half* __restrict__ v1,
    const int* __restrict__ mask, float* __restrict__ out,
    const float* __restrict__ qg, const float* __restrict__ kg,
    const float* __restrict__ vg,
    float* __restrict__ po, float* __restrict__ pm, float* __restrict__ pl)
{
    extern __shared__ char lsm[];
    int bx = blockIdx.x;
    if (bx < NLOC) {
        local_attn_path(lsm, bx, q1, q2, k1, v1, mask, out);
    } else {
        global_part_path(lsm, bx - NLOC, qg, kg, vg, po, pm, pl);
    }
}

// ---------------- merge ----------------
__global__ __launch_bounds__(64) void global_merge_kernel(
    const float* __restrict__ po, const float* __restrict__ pm,
    const float* __restrict__ pl, float* __restrict__ out)
{
    int g = blockIdx.x, h = blockIdx.y, b = blockIdx.z;
    int d = threadIdx.x;

    float mv[NSEG];
    float mx = -1e30f;
#pragma unroll
    for (int s = 0; s < NSEG; s++) {
        mv[s] = pm[(((size_t)s * BATCH + b) * NH + h) * GLB + g];
        mx = fmaxf(mx, mv[s]);
    }
    float num = 0.f, den = 0.f;
#pragma unroll
    for (int s = 0; s < NSEG; s++) {
        size_t pidx = (((size_t)s * BATCH + b) * NH + h) * GLB + g;
        float w = __expf(mv[s] - mx);
        num += w * po[pidx * HDIM + d];
        den += w * pl[pidx];
    }
    out[((size_t)(b * S_LEN + g)) * EMB + h * HDIM + d] = num / den;
}

// ---------------- launch ----------------
extern "C" void kernel_launch(void* const* d_in, const int* in_sizes, int n_in,
                              void* d_out, int out_size)
{
    (void)n_in; (void)out_size;
    int base = (in_sizes[2] == EMB * EMB) ? 2 : 3;

    const float* x    = (const float*)d_in[0];
    const int*   mask = (const int*)d_in[1];
    const float* wq   = (const float*)d_in[base + 0];
    const float* bq   = (const float*)d_in[base + 1];
    const float* wk   = (const float*)d_in[base + 2];
    const float* bk   = (const float*)d_in[base + 3];
    const float* wv   = (const float*)d_in[base + 4];
    const float* bv   = (const float*)d_in[base + 5];
    const float* wqg  = (const float*)d_in[base + 6];
    const float* bqg  = (const float*)d_in[base + 7];
    const float* wkg  = (const float*)d_in[base + 8];
    const float* bkg  = (const float*)d_in[base + 9];
    const float* wvg  = (const float*)d_in[base + 10];
    const float* bvg  = (const float*)d_in[base + 11];
    float* out = (float*)d_out;

    float *kg, *vg, *qg, *po, *pm, *pl;
    __half *xh, *xl, *wt, *q1, *q2, *k1, *v1;
    cudaGetSymbolAddress((void**)&kg, g_kg);
    cudaGetSymbolAddress((void**)&vg, g_vg);
    cudaGetSymbolAddress((void**)&qg, g_qg);
    cudaGetSymbolAddress((void**)&xh, g_xh);
    cudaGetSymbolAddress((void**)&xl, g_xl);
    cudaGetSymbolAddress((void**)&wt, g_wt);
    cudaGetSymbolAddress((void**)&q1, g_q1);
    cudaGetSymbolAddress((void**)&q2, g_q2);
    cudaGetSymbolAddress((void**)&k1, g_k1);
    cudaGetSymbolAddress((void**)&v1, g_v1);
    cudaGetSymbolAddress((void**)&po, g_po);
    cudaGetSymbolAddress((void**)&pm, g_pm);
    cudaGetSymbolAddress((void**)&pl, g_pl);

    cudaFuncSetAttribute(mma_gemm6_kernel,
                         cudaFuncAttributeMaxDynamicSharedMemorySize, GSM2);
    cudaFuncSetAttribute(fused_attn_kernel,
                         cudaFuncAttributeMaxDynamicSharedMemorySize, LL_TOTAL);

    prep_kernel<<<NXBLK + NWB * NWB * 6, 256>>>(
        x, xh, xl, wq, wk, wv, wkg, wvg, wqg, wt);
    mma_gemm6_kernel<<<dim3(EMB / 128, BATCH * S_LEN / 128, 6), 256, GSM2>>>(
        xh, xl, wt, bq, bk, bv, bkg, bvg, bqg,
        q1, q2, k1, v1, kg, vg, qg);
    fused_attn_kernel<<<dim3(NLOC + NSEG, NH, BATCH), 256, LL_TOTAL>>>(
        q1, q2, k1, v1, mask, out, qg, kg, vg, po, pm, pl);
    global_merge_kernel<<<dim3(GLB, NH, BATCH), 64>>>(po, pm, pl, out);
}